// round 2
// baseline (speedup 1.0000x reference)
#include <cuda_runtime.h>
#include <cuda_bf16.h>
#include <math.h>

// ---------------- problem constants ----------------
#define B_ 16
#define L_ 96
#define N_ 512
#define D_ 512
#define H_ 8
#define E_ 64
#define DFF_ 2048
#define T_ 516            // N_ + NMARK
#define PRED_ 96
#define NMARK_ 4
#define LAYERS_ 2
#define BT_ (B_ * T_)     // 8256
#define SCALE_ 0.125f     // 1/sqrt(E)

// ---------------- scratch (device globals; no allocation allowed) ----------------
__device__ float g_mean[B_ * N_];
__device__ float g_std[B_ * N_];
__device__ float g_tok[B_ * T_ * L_];          // [B,T,L] tokens (x_norm^T ++ marks^T)
__device__ float g_nt[B_ * N_ * L_];           // normalized trend rows
__device__ float g_guide[B_ * N_ * N_];        // raw Gram matrix (pre-sigmoid)
__device__ float g_x[BT_ * D_];
__device__ float g_tmp[BT_ * D_];
__device__ float g_q[BT_ * D_];
__device__ float g_k[BT_ * D_];
__device__ float g_v[BT_ * D_];
__device__ float g_ctx[BT_ * D_];
__device__ float g_scores[(long long)B_ * H_ * T_ * T_];   // 136 MB
__device__ float g_ffn[(long long)BT_ * DFF_];             // 67 MB

// ---------------- helpers ----------------
__device__ __forceinline__ float geluf(float x) {
    return 0.5f * x * (1.0f + erff(x * 0.70710678118654752f));
}

__device__ __forceinline__ float block_sum(float v, float* sh) {
    int lane = threadIdx.x & 31, w = threadIdx.x >> 5;
#pragma unroll
    for (int o = 16; o; o >>= 1) v += __shfl_xor_sync(0xffffffffu, v, o);
    if (lane == 0) sh[w] = v;
    __syncthreads();
    if (threadIdx.x == 0) {
        float t = 0.f;
        int nw = blockDim.x >> 5;
        for (int i = 0; i < nw; i++) t += sh[i];
        sh[32] = t;
    }
    __syncthreads();
    float r = sh[32];
    __syncthreads();
    return r;
}

__device__ __forceinline__ float block_max(float v, float* sh) {
    int lane = threadIdx.x & 31, w = threadIdx.x >> 5;
#pragma unroll
    for (int o = 16; o; o >>= 1) v = fmaxf(v, __shfl_xor_sync(0xffffffffu, v, o));
    if (lane == 0) sh[w] = v;
    __syncthreads();
    if (threadIdx.x == 0) {
        float t = -1e30f;
        int nw = blockDim.x >> 5;
        for (int i = 0; i < nw; i++) t = fmaxf(t, sh[i]);
        sh[32] = t;
    }
    __syncthreads();
    float r = sh[32];
    __syncthreads();
    return r;
}

// ---------------- generic tiled GEMM ----------------
// C[M,Nn] = A[M,K] @ op(B) (+bias) (+gelu) (+residual)
// TRANSB: B stored [Nn,K] row-major (C = A @ B^T)
// EPI: 0 none, 1 +bias, 2 +bias+gelu, 3 +bias+residual
#define BM 64
#define BN 64
#define BK 16

template <int EPI, bool TRANSB>
__global__ void gemm_k(const float* __restrict__ A, const float* __restrict__ Bm,
                       const float* __restrict__ bias, const float* __restrict__ Res,
                       float* __restrict__ C,
                       int M, int Nn, int K, int lda, int ldb, int ldc,
                       int nbH,
                       long long sAb, long long sAh, long long sBb, long long sBh,
                       long long sCb, long long sCh) {
    int z = blockIdx.z;
    int zb = z / nbH, zh = z % nbH;
    A  += zb * sAb + zh * sAh;
    Bm += zb * sBb + zh * sBh;
    C  += zb * sCb + zh * sCh;

    __shared__ float As[BK][BM];
    __shared__ float Bs[BK][BN];

    int tid = threadIdx.x;            // 256
    int m0 = blockIdx.y * BM;
    int n0 = blockIdx.x * BN;
    int tx = tid & 15, ty = tid >> 4;

    float acc[4][4];
#pragma unroll
    for (int i = 0; i < 4; i++)
#pragma unroll
        for (int j = 0; j < 4; j++) acc[i][j] = 0.f;

    int a_m = tid >> 2;               // 0..63
    int a_k = (tid & 3) * 4;          // 0,4,8,12
    int b_k = tid >> 4;               // 0..15
    int b_n = (tid & 15) * 4;         // 0..60

    for (int k0 = 0; k0 < K; k0 += BK) {
        // load A tile -> As[k][m]
#pragma unroll
        for (int i = 0; i < 4; i++) {
            int gm = m0 + a_m, gk = k0 + a_k + i;
            As[a_k + i][a_m] = (gm < M && gk < K) ? A[(long long)gm * lda + gk] : 0.f;
        }
        if (!TRANSB) {
#pragma unroll
            for (int i = 0; i < 4; i++) {
                int gk = k0 + b_k, gn = n0 + b_n + i;
                Bs[b_k][b_n + i] = (gk < K && gn < Nn) ? Bm[(long long)gk * ldb + gn] : 0.f;
            }
        } else {
#pragma unroll
            for (int i = 0; i < 4; i++) {
                int gn = n0 + a_m, gk = k0 + a_k + i;
                Bs[a_k + i][a_m] = (gn < Nn && gk < K) ? Bm[(long long)gn * ldb + gk] : 0.f;
            }
        }
        __syncthreads();
#pragma unroll
        for (int k = 0; k < BK; k++) {
            float4 av = *reinterpret_cast<const float4*>(&As[k][ty * 4]);
            float4 bv = *reinterpret_cast<const float4*>(&Bs[k][tx * 4]);
            float aa[4] = {av.x, av.y, av.z, av.w};
            float bb[4] = {bv.x, bv.y, bv.z, bv.w};
#pragma unroll
            for (int i = 0; i < 4; i++)
#pragma unroll
                for (int j = 0; j < 4; j++) acc[i][j] += aa[i] * bb[j];
        }
        __syncthreads();
    }

#pragma unroll
    for (int i = 0; i < 4; i++) {
        int gm = m0 + ty * 4 + i;
        if (gm >= M) continue;
#pragma unroll
        for (int j = 0; j < 4; j++) {
            int gn = n0 + tx * 4 + j;
            if (gn >= Nn) continue;
            float v = acc[i][j];
            if (EPI >= 1) v += bias[gn];
            if (EPI == 2) v = geluf(v);
            if (EPI == 3) v += Res[(long long)gm * ldc + gn];
            C[(long long)gm * ldc + gn] = v;
        }
    }
}

// ---------------- RevIN + transpose into token buffer ----------------
__global__ void revin_k(const float* __restrict__ x, const float* __restrict__ gamma,
                        const float* __restrict__ beta, float* __restrict__ tok,
                        float* __restrict__ meanO, float* __restrict__ stdO) {
    int idx = blockIdx.x * blockDim.x + threadIdx.x;
    if (idx >= B_ * N_) return;
    int b = idx / N_, n = idx % N_;
    const float* xp = x + (long long)b * L_ * N_ + n;
    float s = 0.f, s2 = 0.f;
#pragma unroll 4
    for (int l = 0; l < L_; l++) {
        float v = xp[(long long)l * N_];
        s += v; s2 += v * v;
    }
    float mean = s / L_;
    float var = fmaxf(s2 / L_ - mean * mean, 0.f);
    float sd = sqrtf(var + 1e-5f);
    meanO[idx] = mean;
    stdO[idx] = sd;
    float g = gamma[n], be = beta[n];
    float inv = 1.f / sd;
    float* tp = tok + ((long long)b * T_ + n) * L_;
#pragma unroll 4
    for (int l = 0; l < L_; l++)
        tp[l] = (xp[(long long)l * N_] - mean) * inv * g + be;
}

__global__ void marks_k(const float* __restrict__ xm, float* __restrict__ tok) {
    int idx = blockIdx.x * blockDim.x + threadIdx.x;
    if (idx >= B_ * NMARK_ * L_) return;
    int l = idx % L_;
    int m = (idx / L_) % NMARK_;
    int b = idx / (L_ * NMARK_);
    tok[((long long)b * T_ + N_ + m) * L_ + l] = xm[((long long)b * L_ + l) * NMARK_ + m];
}

// ---------------- trend guidance: per (b,n) MLP-weighted moving averages ----------------
__global__ void trend_k(const float* __restrict__ tok,
                        const float* __restrict__ w1, const float* __restrict__ b1,
                        const float* __restrict__ w2, const float* __restrict__ b2,
                        float* __restrict__ nt) {
    int idx = blockIdx.x * blockDim.x + threadIdx.x;
    if (idx >= B_ * N_) return;
    int b = idx / N_, n = idx % N_;
    const float* xp = tok + ((long long)b * T_ + n) * L_;

    float cum[L_ + 1];
    cum[0] = 0.f;
    float s = 0.f, s2 = 0.f;
    for (int l = 0; l < L_; l++) {
        float v = xp[l];
        cum[l + 1] = cum[l] + v;
        s += v; s2 += v * v;
    }
    float mean = s / L_;
    float var = fmaxf(s2 / L_ - mean * mean, 0.f);
    float sd = sqrtf(var + 1e-6f);

    float logits[4] = {b2[0], b2[1], b2[2], b2[3]};
#pragma unroll
    for (int j = 0; j < 16; j++) {
        float h = mean * w1[j] + sd * w1[16 + j] + b1[j];
        h = fmaxf(h, 0.f);
#pragma unroll
        for (int w = 0; w < 4; w++) logits[w] += h * w2[j * 4 + w];
    }
    float mx = fmaxf(fmaxf(logits[0], logits[1]), fmaxf(logits[2], logits[3]));
    float wt[4], ws = 0.f;
#pragma unroll
    for (int w = 0; w < 4; w++) { wt[w] = expf(logits[w] - mx); ws += wt[w]; }
#pragma unroll
    for (int w = 0; w < 4; w++) wt[w] /= ws;

    const int W[4] = {4, 8, 12, 24};
    float x0 = xp[0];
    float t[L_];
    float nrm2 = 0.f;
    for (int l = 0; l < L_; l++) {
        float tv = 0.f;
#pragma unroll
        for (int wi = 0; wi < 4; wi++) {
            int w = W[wi];
            int lo = l - w + 1;
            float sum = (lo < 0) ? (cum[l + 1] + (float)(-lo) * x0)
                                 : (cum[l + 1] - cum[lo]);
            tv += wt[wi] * sum / (float)w;
        }
        t[l] = tv;
        nrm2 += tv * tv;
    }
    float inv = 1.f / fmaxf(sqrtf(nrm2), 1e-12f);
    float* np = nt + ((long long)b * N_ + n) * L_;
    for (int l = 0; l < L_; l++) np[l] = t[l] * inv;
}

// ---------------- softmax + sigmoid-guidance gate + renorm (in-place) ----------------
__global__ void softmax_gate_k(float* __restrict__ sc, const float* __restrict__ guide) {
    __shared__ float sh[33];
    long long row = blockIdx.x;                 // b*H*T + h*T + i
    int i = (int)(row % T_);
    int bh = (int)(row / T_);
    int b = bh / H_;
    float* sp = sc + row * T_;
    const float* gp = guide + (long long)b * N_ * N_ + (long long)i * N_;

    float pv[3];
    float mx = -1e30f;
#pragma unroll
    for (int it = 0; it < 3; it++) {
        int j = threadIdx.x + it * 256;
        if (j < T_) mx = fmaxf(mx, sp[j] * SCALE_);
    }
    mx = block_max(mx, sh);

    float psum = 0.f;
#pragma unroll
    for (int it = 0; it < 3; it++) {
        int j = threadIdx.x + it * 256;
        float p = 0.f;
        if (j < T_) { p = expf(sp[j] * SCALE_ - mx); psum += p; }
        pv[it] = p;
    }
    psum = block_sum(psum, sh);
    float invP = 1.f / psum;

    float s2 = 0.f;
#pragma unroll
    for (int it = 0; it < 3; it++) {
        int j = threadIdx.x + it * 256;
        if (j < T_) {
            float g = 0.5f;
            if (i < N_ && j < N_) g = 1.f / (1.f + expf(-gp[j]));
            float a = pv[it] * invP * g;
            pv[it] = a;
            s2 += a;
        }
    }
    s2 = block_sum(s2, sh);
    float r = 1.f / (s2 + 1e-6f);
#pragma unroll
    for (int it = 0; it < 3; it++) {
        int j = threadIdx.x + it * 256;
        if (j < T_) sp[j] = pv[it] * r;
    }
}

// ---------------- layernorm (D=512, 128 threads, optional residual, in/out of place) --------
template <bool RES>
__global__ void ln_k(const float* __restrict__ X, const float* __restrict__ Y,
                     const float* __restrict__ g, const float* __restrict__ be,
                     float* __restrict__ out) {
    __shared__ float sh[33];
    long long r = blockIdx.x;
    const float* x = X + r * D_;
    const float* y = RES ? (Y + r * D_) : nullptr;
    float v[4];
    float s = 0.f;
#pragma unroll
    for (int i = 0; i < 4; i++) {
        int c = threadIdx.x + i * 128;
        v[i] = x[c] + (RES ? y[c] : 0.f);
        s += v[i];
    }
    s = block_sum(s, sh);
    float mean = s / D_;
    float s2 = 0.f;
#pragma unroll
    for (int i = 0; i < 4; i++) { float d = v[i] - mean; s2 += d * d; }
    s2 = block_sum(s2, sh);
    float rstd = rsqrtf(s2 / D_ + 1e-5f);
    float* o = out + r * D_;
#pragma unroll
    for (int i = 0; i < 4; i++) {
        int c = threadIdx.x + i * 128;
        o[c] = (v[i] - mean) * rstd * g[c] + be[c];
    }
}

// ---------------- output: transpose + RevIN inverse ----------------
__global__ void out_k(const float* __restrict__ proj, const float* __restrict__ meanI,
                      const float* __restrict__ stdI, const float* __restrict__ gamma,
                      const float* __restrict__ beta, float* __restrict__ out) {
    int idx = blockIdx.x * blockDim.x + threadIdx.x;
    if (idx >= B_ * PRED_ * N_) return;
    int n = idx % N_;
    int p = (idx / N_) % PRED_;
    int b = idx / (N_ * PRED_);
    float v = proj[((long long)b * T_ + n) * PRED_ + p];
    v = (v - beta[n]) / (gamma[n] + 1e-5f) * stdI[b * N_ + n] + meanI[b * N_ + n];
    out[idx] = v;
}

// ---------------- host orchestration ----------------
static inline dim3 gemm_grid(int M, int Nn, int batch) {
    return dim3((Nn + BN - 1) / BN, (M + BM - 1) / BM, batch);
}

extern "C" void kernel_launch(void* const* d_in, const int* in_sizes, int n_in,
                              void* d_out, int out_size) {
    const float* x_enc  = (const float*)d_in[0];
    const float* x_mark = (const float*)d_in[1];
    const float* gamma  = (const float*)d_in[4];
    const float* beta   = (const float*)d_in[5];
    const float* tp_w1  = (const float*)d_in[6];
    const float* tp_b1  = (const float*)d_in[7];
    const float* tp_w2  = (const float*)d_in[8];
    const float* tp_b2  = (const float*)d_in[9];
    const float* emb_w  = (const float*)d_in[10];
    const float* emb_b  = (const float*)d_in[11];
    const float* wq = (const float*)d_in[12];
    const float* bq = (const float*)d_in[13];
    const float* wk = (const float*)d_in[14];
    const float* bk = (const float*)d_in[15];
    const float* wv = (const float*)d_in[16];
    const float* bv = (const float*)d_in[17];
    const float* wo = (const float*)d_in[18];
    const float* bo = (const float*)d_in[19];
    const float* w1 = (const float*)d_in[20];
    const float* b1 = (const float*)d_in[21];
    const float* w2 = (const float*)d_in[22];
    const float* b2 = (const float*)d_in[23];
    const float* ln1g = (const float*)d_in[24];
    const float* ln1b = (const float*)d_in[25];
    const float* ln2g = (const float*)d_in[26];
    const float* ln2b = (const float*)d_in[27];
    const float* normg = (const float*)d_in[28];
    const float* normb = (const float*)d_in[29];
    const float* proj_w = (const float*)d_in[30];
    const float* proj_b = (const float*)d_in[31];
    float* out = (float*)d_out;

    float *p_mean, *p_std, *p_tok, *p_nt, *p_guide, *p_x, *p_tmp, *p_q, *p_k, *p_v,
          *p_ctx, *p_scores, *p_ffn;
    cudaGetSymbolAddress((void**)&p_mean, g_mean);
    cudaGetSymbolAddress((void**)&p_std, g_std);
    cudaGetSymbolAddress((void**)&p_tok, g_tok);
    cudaGetSymbolAddress((void**)&p_nt, g_nt);
    cudaGetSymbolAddress((void**)&p_guide, g_guide);
    cudaGetSymbolAddress((void**)&p_x, g_x);
    cudaGetSymbolAddress((void**)&p_tmp, g_tmp);
    cudaGetSymbolAddress((void**)&p_q, g_q);
    cudaGetSymbolAddress((void**)&p_k, g_k);
    cudaGetSymbolAddress((void**)&p_v, g_v);
    cudaGetSymbolAddress((void**)&p_ctx, g_ctx);
    cudaGetSymbolAddress((void**)&p_scores, g_scores);
    cudaGetSymbolAddress((void**)&p_ffn, g_ffn);

    // 1) RevIN + transpose into token buffer
    revin_k<<<(B_ * N_ + 255) / 256, 256>>>(x_enc, gamma, beta, p_tok, p_mean, p_std);
    marks_k<<<(B_ * NMARK_ * L_ + 255) / 256, 256>>>(x_mark, p_tok);

    // 2) trend guidance rows
    trend_k<<<(B_ * N_ + 255) / 256, 256>>>(p_tok, tp_w1, tp_b1, tp_w2, tp_b2, p_nt);

    // 3) Gram matrix: guide[b] = nt[b] @ nt[b]^T  (raw; sigmoid applied in softmax)
    gemm_k<0, true><<<gemm_grid(N_, N_, B_), 256>>>(
        p_nt, p_nt, nullptr, nullptr, p_guide,
        N_, N_, L_, L_, L_, N_, 1,
        (long long)N_ * L_, 0, (long long)N_ * L_, 0, (long long)N_ * N_, 0);

    // 4) inverted embedding: x = tok @ emb_w + emb_b  [BT, D]
    gemm_k<1, false><<<gemm_grid(BT_, D_, 1), 256>>>(
        p_tok, emb_w, emb_b, nullptr, p_x,
        BT_, D_, L_, L_, D_, D_, 1, 0, 0, 0, 0, 0, 0);

    // 5) encoder layers
    for (int i = 0; i < LAYERS_; i++) {
        const float* wq_i = wq + (long long)i * D_ * D_;
        const float* wk_i = wk + (long long)i * D_ * D_;
        const float* wv_i = wv + (long long)i * D_ * D_;
        const float* wo_i = wo + (long long)i * D_ * D_;
        const float* w1_i = w1 + (long long)i * D_ * DFF_;
        const float* w2_i = w2 + (long long)i * DFF_ * D_;

        gemm_k<1, false><<<gemm_grid(BT_, D_, 1), 256>>>(
            p_x, wq_i, bq + i * D_, nullptr, p_q,
            BT_, D_, D_, D_, D_, D_, 1, 0, 0, 0, 0, 0, 0);
        gemm_k<1, false><<<gemm_grid(BT_, D_, 1), 256>>>(
            p_x, wk_i, bk + i * D_, nullptr, p_k,
            BT_, D_, D_, D_, D_, D_, 1, 0, 0, 0, 0, 0, 0);
        gemm_k<1, false><<<gemm_grid(BT_, D_, 1), 256>>>(
            p_x, wv_i, bv + i * D_, nullptr, p_v,
            BT_, D_, D_, D_, D_, D_, 1, 0, 0, 0, 0, 0, 0);

        // scores[b,h] = q[b,:,h,:] @ k[b,:,h,:]^T   (raw; scale in softmax)
        gemm_k<0, true><<<gemm_grid(T_, T_, B_ * H_), 256>>>(
            p_q, p_k, nullptr, nullptr, p_scores,
            T_, T_, E_, D_, D_, T_, H_,
            (long long)T_ * D_, E_, (long long)T_ * D_, E_,
            (long long)H_ * T_ * T_, (long long)T_ * T_);

        softmax_gate_k<<<B_ * H_ * T_, 256>>>(p_scores, p_guide);

        // ctx[b,:,h,:] = attn[b,h] @ v[b,:,h,:]
        gemm_k<0, false><<<gemm_grid(T_, E_, B_ * H_), 256>>>(
            p_scores, p_v, nullptr, nullptr, p_ctx,
            T_, E_, T_, T_, D_, D_, H_,
            (long long)H_ * T_ * T_, (long long)T_ * T_,
            (long long)T_ * D_, E_, (long long)T_ * D_, E_);

        // x_attn = x + ctx @ wo + bo
        gemm_k<3, false><<<gemm_grid(BT_, D_, 1), 256>>>(
            p_ctx, wo_i, bo + i * D_, p_x, p_tmp,
            BT_, D_, D_, D_, D_, D_, 1, 0, 0, 0, 0, 0, 0);

        // LN1 (in-place on p_tmp)
        ln_k<false><<<BT_, 128>>>(p_tmp, nullptr, ln1g + i * D_, ln1b + i * D_, p_tmp);

        // FFN
        gemm_k<2, false><<<gemm_grid(BT_, DFF_, 1), 256>>>(
            p_tmp, w1_i, b1 + i * DFF_, nullptr, p_ffn,
            BT_, DFF_, D_, D_, DFF_, DFF_, 1, 0, 0, 0, 0, 0, 0);
        gemm_k<1, false><<<gemm_grid(BT_, D_, 1), 256>>>(
            p_ffn, w2_i, b2 + i * D_, nullptr, p_ctx,
            BT_, D_, DFF_, DFF_, D_, D_, 1, 0, 0, 0, 0, 0, 0);

        // LN2 with residual: x = LN(x_attn_post_ln1 + ffn_out)
        ln_k<true><<<BT_, 128>>>(p_tmp, p_ctx, ln2g + i * D_, ln2b + i * D_, p_x);
    }

    // 6) final LN
    ln_k<false><<<BT_, 128>>>(p_x, nullptr, normg, normb, p_tmp);

    // 7) projection: [BT, 96]
    gemm_k<1, false><<<gemm_grid(BT_, PRED_, 1), 256>>>(
        p_tmp, proj_w, proj_b, nullptr, p_q,
        BT_, PRED_, D_, D_, PRED_, PRED_, 1, 0, 0, 0, 0, 0, 0);

    // 8) transpose + RevIN inverse
    out_k<<<(B_ * PRED_ * N_ + 255) / 256, 256>>>(p_q, p_mean, p_std, gamma, beta, out);
}

// round 6
// speedup vs baseline: 2.8362x; 2.8362x over previous
#include <cuda_runtime.h>
#include <cuda_bf16.h>
#include <cstdint>
#include <math.h>

// ---------------- problem constants ----------------
#define B_ 16
#define L_ 96
#define N_ 512
#define D_ 512
#define H_ 8
#define E_ 64
#define DFF_ 2048
#define T_ 516            // N_ + NMARK
#define PRED_ 96
#define NMARK_ 4
#define LAYERS_ 2
#define BT_ (B_ * T_)     // 8256
#define SCALE_ 0.125f     // 1/sqrt(E)

// ---------------- scratch (device globals; no allocation allowed) ----------------
__device__ float g_mean[B_ * N_];
__device__ float g_std[B_ * N_];
__device__ float g_tok[B_ * T_ * L_];
__device__ float g_nt[B_ * N_ * L_];
__device__ float g_guide[B_ * N_ * N_];
__device__ float g_x[BT_ * D_];
__device__ float g_tmp[BT_ * D_];
__device__ float g_q[BT_ * D_];
__device__ float g_k[BT_ * D_];
__device__ float g_v[BT_ * D_];
__device__ float g_ctx[BT_ * D_];
__device__ float g_scores[(long long)B_ * H_ * T_ * T_];   // 136 MB
__device__ float g_ffn[(long long)BT_ * DFF_];             // 67 MB
// transposed operands (B must be [N,K] K-major)
__device__ float g_wqt[LAYERS_ * D_ * D_];
__device__ float g_wkt[LAYERS_ * D_ * D_];
__device__ float g_wvt[LAYERS_ * D_ * D_];
__device__ float g_wot[LAYERS_ * D_ * D_];
__device__ float g_w1t[(long long)LAYERS_ * D_ * DFF_];
__device__ float g_w2t[(long long)LAYERS_ * DFF_ * D_];
__device__ float g_embt[D_ * L_];
__device__ float g_projt[PRED_ * D_];
__device__ float g_vt[(long long)B_ * H_ * E_ * T_];

// ---------------- mma helpers ----------------
__device__ __forceinline__ uint32_t f2tf(float v) {
    uint32_t t;
    asm("cvt.rna.tf32.f32 %0, %1;" : "=r"(t) : "f"(v));
    return t;
}
__device__ __forceinline__ void mma8(float* c, const uint32_t* a, uint32_t b0, uint32_t b1) {
    asm volatile(
        "mma.sync.aligned.m16n8k8.row.col.f32.tf32.tf32.f32 "
        "{%0,%1,%2,%3}, {%4,%5,%6,%7}, {%8,%9}, {%0,%1,%2,%3};"
        : "+f"(c[0]), "+f"(c[1]), "+f"(c[2]), "+f"(c[3])
        : "r"(a[0]), "r"(a[1]), "r"(a[2]), "r"(a[3]), "r"(b0), "r"(b1));
}
__device__ __forceinline__ float geluf(float x) {
    return 0.5f * x * (1.0f + erff(x * 0.70710678118654752f));
}

// ---------------- tf32 tensor-core GEMM: C[M,N] = A[M,K] @ B[N,K]^T (+epi) ----------------
// EPI: 0 none, 1 +bias, 2 +bias+gelu, 3 +bias+residual
// Tile 128 x BNt x 16, 256 threads (8 warps: 2 in M x 4 in N), warp tile 64 x (BNt/4).
#define SSTRIDE 20

template <int EPI, int BNt>
__global__ void __launch_bounds__(256)
mmak(const float* __restrict__ A, const float* __restrict__ Bm,
     const float* __restrict__ bias, const float* __restrict__ Res,
     float* __restrict__ C,
     int M, int Nn, int K, int lda, int ldb, int ldc, int nbH,
     long long sAb, long long sAh, long long sBb, long long sBh,
     long long sCb, long long sCh) {
    constexpr int WN = BNt / 4;           // warp n-tile
    constexpr int NI = WN / 8;            // n-fragments per warp
    constexpr int BQ = BNt * 16 / 4 / 256;// B float4 loads per thread (2 or 1)

    __shared__ uint32_t As[2][128 * SSTRIDE];
    __shared__ uint32_t Bs[2][BNt * SSTRIDE];

    int tid = threadIdx.x;
    int z = blockIdx.z, zb = z / nbH, zh = z % nbH;
    A  += zb * sAb + zh * sAh;
    Bm += zb * sBb + zh * sBh;
    C  += zb * sCb + zh * sCh;
    int m0 = blockIdx.y * 128, n0 = blockIdx.x * BNt;

    int lane = tid & 31, wid = tid >> 5;
    int wm = (wid & 1) * 64;
    int wn = (wid >> 1) * WN;
    int grp = lane >> 2, tig = lane & 3;

    float acc[4][NI][4];
#pragma unroll
    for (int mi = 0; mi < 4; mi++)
#pragma unroll
        for (int ni = 0; ni < NI; ni++)
#pragma unroll
            for (int r = 0; r < 4; r++) acc[mi][ni][r] = 0.f;

    const int NC = (K + 15) / 16;
    float4 ra[2], rb[BQ];

    // ---- tile loaders (gmem -> regs) ----
    auto loadA = [&](int c) {
        int k0 = c * 16;
#pragma unroll
        for (int u = 0; u < 2; u++) {
            int e = tid + u * 256;               // float4 idx in 128x16 tile
            int row = e >> 2, c4 = (e & 3) * 4;
            int gm = m0 + row, gk = k0 + c4;
            float4 v = make_float4(0.f, 0.f, 0.f, 0.f);
            if (gm < M) {
                const float* p = A + (long long)gm * lda + gk;
                if (gk + 4 <= K) v = *(const float4*)p;
                else {
                    if (gk + 0 < K) v.x = p[0];
                    if (gk + 1 < K) v.y = p[1];
                    if (gk + 2 < K) v.z = p[2];
                }
            }
            ra[u] = v;
        }
    };
    auto loadB = [&](int c) {
        int k0 = c * 16;
#pragma unroll
        for (int u = 0; u < BQ; u++) {
            int e = tid + u * 256;
            int row = e >> 2, c4 = (e & 3) * 4;
            int gn = n0 + row, gk = k0 + c4;
            float4 v = make_float4(0.f, 0.f, 0.f, 0.f);
            if (gn < Nn) {
                const float* p = Bm + (long long)gn * ldb + gk;
                if (gk + 4 <= K) v = *(const float4*)p;
                else {
                    if (gk + 0 < K) v.x = p[0];
                    if (gk + 1 < K) v.y = p[1];
                    if (gk + 2 < K) v.z = p[2];
                }
            }
            rb[u] = v;
        }
    };
    auto storeT = [&](int buf) {
#pragma unroll
        for (int u = 0; u < 2; u++) {
            int e = tid + u * 256;
            int row = e >> 2, c4 = (e & 3) * 4;
            uint32_t* d = &As[buf][row * SSTRIDE + c4];
            d[0] = f2tf(ra[u].x); d[1] = f2tf(ra[u].y);
            d[2] = f2tf(ra[u].z); d[3] = f2tf(ra[u].w);
        }
#pragma unroll
        for (int u = 0; u < BQ; u++) {
            int e = tid + u * 256;
            int row = e >> 2, c4 = (e & 3) * 4;
            uint32_t* d = &Bs[buf][row * SSTRIDE + c4];
            d[0] = f2tf(rb[u].x); d[1] = f2tf(rb[u].y);
            d[2] = f2tf(rb[u].z); d[3] = f2tf(rb[u].w);
        }
    };

    loadA(0); loadB(0);
    storeT(0);
    __syncthreads();

    for (int c = 0; c < NC; c++) {
        int buf = c & 1;
        if (c + 1 < NC) { loadA(c + 1); loadB(c + 1); }
        // compute from smem[buf]
#pragma unroll
        for (int kk = 0; kk < 2; kk++) {
            int k0 = kk * 8;
            uint32_t af[4][4];
#pragma unroll
            for (int mi = 0; mi < 4; mi++) {
                int r = wm + mi * 16 + grp;
                const uint32_t* as = As[buf];
                af[mi][0] = as[r * SSTRIDE + k0 + tig];
                af[mi][1] = as[(r + 8) * SSTRIDE + k0 + tig];
                af[mi][2] = as[r * SSTRIDE + k0 + tig + 4];
                af[mi][3] = as[(r + 8) * SSTRIDE + k0 + tig + 4];
            }
#pragma unroll
            for (int ni = 0; ni < NI; ni++) {
                int col = wn + ni * 8 + grp;
                uint32_t b0 = Bs[buf][col * SSTRIDE + k0 + tig];
                uint32_t b1 = Bs[buf][col * SSTRIDE + k0 + tig + 4];
#pragma unroll
                for (int mi = 0; mi < 4; mi++) mma8(acc[mi][ni], af[mi], b0, b1);
            }
        }
        if (c + 1 < NC) {
            storeT(buf ^ 1);
            __syncthreads();
        }
    }

    // ---- epilogue: fragment -> gmem (float2 stores; cols always even) ----
#pragma unroll
    for (int mi = 0; mi < 4; mi++) {
#pragma unroll
        for (int ni = 0; ni < NI; ni++) {
            int col = n0 + wn + ni * 8 + 2 * tig;
            if (col >= Nn) continue;
            float bv0 = 0.f, bv1 = 0.f;
            if (EPI >= 1) { bv0 = bias[col]; bv1 = bias[col + 1]; }
#pragma unroll
            for (int h = 0; h < 2; h++) {
                int gm = m0 + wm + mi * 16 + grp + h * 8;
                if (gm >= M) continue;
                float v0 = acc[mi][ni][h * 2 + 0] + bv0;
                float v1 = acc[mi][ni][h * 2 + 1] + bv1;
                if (EPI == 2) { v0 = geluf(v0); v1 = geluf(v1); }
                if (EPI == 3) {
                    const float* rp = Res + (long long)gm * ldc + col;
                    v0 += rp[0]; v1 += rp[1];
                }
                *(float2*)(C + (long long)gm * ldc + col) = make_float2(v0, v1);
            }
        }
    }
}

// ---------------- batched tiled transpose ----------------
__global__ void transpose_k(const float* __restrict__ S, float* __restrict__ Dst,
                            int R, int C, int lds, int ldd, int nb2,
                            long long sSb, long long sSh, long long sDb, long long sDh) {
    __shared__ float t[32][33];
    int z = blockIdx.z, zb = z / nb2, zh = z % nb2;
    S += zb * sSb + zh * sSh;
    Dst += zb * sDb + zh * sDh;
    int r0 = blockIdx.y * 32, c0 = blockIdx.x * 32;
    int c = c0 + threadIdx.x;
#pragma unroll
    for (int i = 0; i < 32; i += 8) {
        int r = r0 + threadIdx.y + i;
        if (r < R && c < C) t[threadIdx.y + i][threadIdx.x] = S[(long long)r * lds + c];
    }
    __syncthreads();
    int cc2 = r0 + threadIdx.x;
#pragma unroll
    for (int i = 0; i < 32; i += 8) {
        int rr2 = c0 + threadIdx.y + i;
        if (rr2 < C && cc2 < R) Dst[(long long)rr2 * ldd + cc2] = t[threadIdx.x][threadIdx.y + i];
    }
}

// ---------------- reductions ----------------
__device__ __forceinline__ float block_sum(float v, float* sh) {
    int lane = threadIdx.x & 31, w = threadIdx.x >> 5;
#pragma unroll
    for (int o = 16; o; o >>= 1) v += __shfl_xor_sync(0xffffffffu, v, o);
    if (lane == 0) sh[w] = v;
    __syncthreads();
    if (threadIdx.x == 0) {
        float t = 0.f; int nw = blockDim.x >> 5;
        for (int i = 0; i < nw; i++) t += sh[i];
        sh[32] = t;
    }
    __syncthreads();
    float r = sh[32];
    __syncthreads();
    return r;
}
__device__ __forceinline__ float block_max(float v, float* sh) {
    int lane = threadIdx.x & 31, w = threadIdx.x >> 5;
#pragma unroll
    for (int o = 16; o; o >>= 1) v = fmaxf(v, __shfl_xor_sync(0xffffffffu, v, o));
    if (lane == 0) sh[w] = v;
    __syncthreads();
    if (threadIdx.x == 0) {
        float t = -1e30f; int nw = blockDim.x >> 5;
        for (int i = 0; i < nw; i++) t = fmaxf(t, sh[i]);
        sh[32] = t;
    }
    __syncthreads();
    float r = sh[32];
    __syncthreads();
    return r;
}

// ---------------- small fused kernels ----------------
__global__ void revin_k(const float* __restrict__ x, const float* __restrict__ gamma,
                        const float* __restrict__ beta, float* __restrict__ tok,
                        float* __restrict__ meanO, float* __restrict__ stdO) {
    int idx = blockIdx.x * blockDim.x + threadIdx.x;
    if (idx >= B_ * N_) return;
    int b = idx / N_, n = idx % N_;
    const float* xp = x + (long long)b * L_ * N_ + n;
    float s = 0.f, s2 = 0.f;
#pragma unroll 4
    for (int l = 0; l < L_; l++) { float v = xp[(long long)l * N_]; s += v; s2 += v * v; }
    float mean = s / L_;
    float var = fmaxf(s2 / L_ - mean * mean, 0.f);
    float sd = sqrtf(var + 1e-5f);
    meanO[idx] = mean; stdO[idx] = sd;
    float g = gamma[n], be = beta[n], inv = 1.f / sd;
    float* tp = tok + ((long long)b * T_ + n) * L_;
#pragma unroll 4
    for (int l = 0; l < L_; l++) tp[l] = (xp[(long long)l * N_] - mean) * inv * g + be;
}

__global__ void marks_k(const float* __restrict__ xm, float* __restrict__ tok) {
    int idx = blockIdx.x * blockDim.x + threadIdx.x;
    if (idx >= B_ * NMARK_ * L_) return;
    int l = idx % L_, m = (idx / L_) % NMARK_, b = idx / (L_ * NMARK_);
    tok[((long long)b * T_ + N_ + m) * L_ + l] = xm[((long long)b * L_ + l) * NMARK_ + m];
}

__global__ void trend_k(const float* __restrict__ tok,
                        const float* __restrict__ w1, const float* __restrict__ b1,
                        const float* __restrict__ w2, const float* __restrict__ b2,
                        float* __restrict__ nt) {
    int idx = blockIdx.x * blockDim.x + threadIdx.x;
    if (idx >= B_ * N_) return;
    int b = idx / N_, n = idx % N_;
    const float* xp = tok + ((long long)b * T_ + n) * L_;
    float cum[L_ + 1];
    cum[0] = 0.f;
    float s = 0.f, s2 = 0.f;
    for (int l = 0; l < L_; l++) {
        float v = xp[l];
        cum[l + 1] = cum[l] + v;
        s += v; s2 += v * v;
    }
    float mean = s / L_;
    float var = fmaxf(s2 / L_ - mean * mean, 0.f);
    float sd = sqrtf(var + 1e-6f);
    float logits[4] = {b2[0], b2[1], b2[2], b2[3]};
#pragma unroll
    for (int j = 0; j < 16; j++) {
        float h = fmaxf(mean * w1[j] + sd * w1[16 + j] + b1[j], 0.f);
#pragma unroll
        for (int w = 0; w < 4; w++) logits[w] += h * w2[j * 4 + w];
    }
    float mx = fmaxf(fmaxf(logits[0], logits[1]), fmaxf(logits[2], logits[3]));
    float wt[4], ws = 0.f;
#pragma unroll
    for (int w = 0; w < 4; w++) { wt[w] = expf(logits[w] - mx); ws += wt[w]; }
#pragma unroll
    for (int w = 0; w < 4; w++) wt[w] /= ws;
    const int W[4] = {4, 8, 12, 24};
    float x0 = xp[0];
    float t[L_];
    float nrm2 = 0.f;
    for (int l = 0; l < L_; l++) {
        float tv = 0.f;
#pragma unroll
        for (int wi = 0; wi < 4; wi++) {
            int w = W[wi], lo = l - w + 1;
            float sum = (lo < 0) ? (cum[l + 1] + (float)(-lo) * x0) : (cum[l + 1] - cum[lo]);
            tv += wt[wi] * sum / (float)w;
        }
        t[l] = tv; nrm2 += tv * tv;
    }
    float inv = 1.f / fmaxf(sqrtf(nrm2), 1e-12f);
    float* np = nt + ((long long)b * N_ + n) * L_;
    for (int l = 0; l < L_; l++) np[l] = t[l] * inv;
}

__global__ void softmax_gate_k(float* __restrict__ sc, const float* __restrict__ guide) {
    __shared__ float sh[33];
    long long row = blockIdx.x;
    int i = (int)(row % T_);
    int bh = (int)(row / T_);
    int b = bh / H_;
    float* sp = sc + row * T_;
    const float* gp = guide + (long long)b * N_ * N_ + (long long)i * N_;
    float pv[3];
    float mx = -1e30f;
#pragma unroll
    for (int it = 0; it < 3; it++) {
        int j = threadIdx.x + it * 256;
        if (j < T_) mx = fmaxf(mx, sp[j] * SCALE_);
    }
    mx = block_max(mx, sh);
    float psum = 0.f;
#pragma unroll
    for (int it = 0; it < 3; it++) {
        int j = threadIdx.x + it * 256;
        float p = 0.f;
        if (j < T_) { p = expf(sp[j] * SCALE_ - mx); psum += p; }
        pv[it] = p;
    }
    psum = block_sum(psum, sh);
    float invP = 1.f / psum;
    float s2 = 0.f;
#pragma unroll
    for (int it = 0; it < 3; it++) {
        int j = threadIdx.x + it * 256;
        if (j < T_) {
            float g = 0.5f;
            if (i < N_ && j < N_) g = 1.f / (1.f + expf(-gp[j]));
            float a = pv[it] * invP * g;
            pv[it] = a; s2 += a;
        }
    }
    s2 = block_sum(s2, sh);
    float r = 1.f / (s2 + 1e-6f);
#pragma unroll
    for (int it = 0; it < 3; it++) {
        int j = threadIdx.x + it * 256;
        if (j < T_) sp[j] = pv[it] * r;
    }
}

template <bool RES>
__global__ void ln_k(const float* __restrict__ X, const float* __restrict__ Y,
                     const float* __restrict__ g, const float* __restrict__ be,
                     float* __restrict__ out) {
    __shared__ float sh[33];
    long long r = blockIdx.x;
    const float* x = X + r * D_;
    const float* y = RES ? (Y + r * D_) : nullptr;
    float v[4];
    float s = 0.f;
#pragma unroll
    for (int i = 0; i < 4; i++) {
        int c = threadIdx.x + i * 128;
        v[i] = x[c] + (RES ? y[c] : 0.f);
        s += v[i];
    }
    s = block_sum(s, sh);
    float mean = s / D_;
    float s2 = 0.f;
#pragma unroll
    for (int i = 0; i < 4; i++) { float d = v[i] - mean; s2 += d * d; }
    s2 = block_sum(s2, sh);
    float rstd = rsqrtf(s2 / D_ + 1e-5f);
    float* o = out + r * D_;
#pragma unroll
    for (int i = 0; i < 4; i++) {
        int c = threadIdx.x + i * 128;
        o[c] = (v[i] - mean) * rstd * g[c] + be[c];
    }
}

__global__ void out_k(const float* __restrict__ proj, const float* __restrict__ meanI,
                      const float* __restrict__ stdI, const float* __restrict__ gamma,
                      const float* __restrict__ beta, float* __restrict__ out) {
    int idx = blockIdx.x * blockDim.x + threadIdx.x;
    if (idx >= B_ * PRED_ * N_) return;
    int n = idx % N_, p = (idx / N_) % PRED_, b = idx / (N_ * PRED_);
    float v = proj[((long long)b * T_ + n) * PRED_ + p];
    v = (v - beta[n]) / (gamma[n] + 1e-5f) * stdI[b * N_ + n] + meanI[b * N_ + n];
    out[idx] = v;
}

// ---------------- host orchestration ----------------
static inline dim3 tgrid(int M, int Nn, int BN, int batch) {
    return dim3((Nn + BN - 1) / BN, (M + 127) / 128, batch);
}

extern "C" void kernel_launch(void* const* d_in, const int* in_sizes, int n_in,
                              void* d_out, int out_size) {
    const float* x_enc  = (const float*)d_in[0];
    const float* x_mark = (const float*)d_in[1];
    const float* gamma  = (const float*)d_in[4];
    const float* beta   = (const float*)d_in[5];
    const float* tp_w1  = (const float*)d_in[6];
    const float* tp_b1  = (const float*)d_in[7];
    const float* tp_w2  = (const float*)d_in[8];
    const float* tp_b2  = (const float*)d_in[9];
    const float* emb_w  = (const float*)d_in[10];
    const float* emb_b  = (const float*)d_in[11];
    const float* wq = (const float*)d_in[12];
    const float* bq = (const float*)d_in[13];
    const float* wk = (const float*)d_in[14];
    const float* bk = (const float*)d_in[15];
    const float* wv = (const float*)d_in[16];
    const float* bv = (const float*)d_in[17];
    const float* wo = (const float*)d_in[18];
    const float* bo = (const float*)d_in[19];
    const float* w1 = (const float*)d_in[20];
    const float* b1 = (const float*)d_in[21];
    const float* w2 = (const float*)d_in[22];
    const float* b2 = (const float*)d_in[23];
    const float* ln1g = (const float*)d_in[24];
    const float* ln1b = (const float*)d_in[25];
    const float* ln2g = (const float*)d_in[26];
    const float* ln2b = (const float*)d_in[27];
    const float* normg = (const float*)d_in[28];
    const float* normb = (const float*)d_in[29];
    const float* proj_w = (const float*)d_in[30];
    const float* proj_b = (const float*)d_in[31];
    float* out = (float*)d_out;

    float *p_mean, *p_std, *p_tok, *p_nt, *p_guide, *p_x, *p_tmp, *p_q, *p_k, *p_v,
          *p_ctx, *p_scores, *p_ffn, *p_wqt, *p_wkt, *p_wvt, *p_wot, *p_w1t, *p_w2t,
          *p_embt, *p_projt, *p_vt;
    cudaGetSymbolAddress((void**)&p_mean, g_mean);
    cudaGetSymbolAddress((void**)&p_std, g_std);
    cudaGetSymbolAddress((void**)&p_tok, g_tok);
    cudaGetSymbolAddress((void**)&p_nt, g_nt);
    cudaGetSymbolAddress((void**)&p_guide, g_guide);
    cudaGetSymbolAddress((void**)&p_x, g_x);
    cudaGetSymbolAddress((void**)&p_tmp, g_tmp);
    cudaGetSymbolAddress((void**)&p_q, g_q);
    cudaGetSymbolAddress((void**)&p_k, g_k);
    cudaGetSymbolAddress((void**)&p_v, g_v);
    cudaGetSymbolAddress((void**)&p_ctx, g_ctx);
    cudaGetSymbolAddress((void**)&p_scores, g_scores);
    cudaGetSymbolAddress((void**)&p_ffn, g_ffn);
    cudaGetSymbolAddress((void**)&p_wqt, g_wqt);
    cudaGetSymbolAddress((void**)&p_wkt, g_wkt);
    cudaGetSymbolAddress((void**)&p_wvt, g_wvt);
    cudaGetSymbolAddress((void**)&p_wot, g_wot);
    cudaGetSymbolAddress((void**)&p_w1t, g_w1t);
    cudaGetSymbolAddress((void**)&p_w2t, g_w2t);
    cudaGetSymbolAddress((void**)&p_embt, g_embt);
    cudaGetSymbolAddress((void**)&p_projt, g_projt);
    cudaGetSymbolAddress((void**)&p_vt, g_vt);

    dim3 tb(32, 8);
    // weight transposes -> [N,K] K-major operands
    transpose_k<<<dim3(16, 16, 2), tb>>>(wq, p_wqt, 512, 512, 512, 512, 1, 512 * 512, 0, 512 * 512, 0);
    transpose_k<<<dim3(16, 16, 2), tb>>>(wk, p_wkt, 512, 512, 512, 512, 1, 512 * 512, 0, 512 * 512, 0);
    transpose_k<<<dim3(16, 16, 2), tb>>>(wv, p_wvt, 512, 512, 512, 512, 1, 512 * 512, 0, 512 * 512, 0);
    transpose_k<<<dim3(16, 16, 2), tb>>>(wo, p_wot, 512, 512, 512, 512, 1, 512 * 512, 0, 512 * 512, 0);
    transpose_k<<<dim3(64, 16, 2), tb>>>(w1, p_w1t, 512, 2048, 2048, 512, 1,
                                         (long long)512 * 2048, 0, (long long)512 * 2048, 0);
    transpose_k<<<dim3(16, 64, 2), tb>>>(w2, p_w2t, 2048, 512, 512, 2048, 1,
                                         (long long)512 * 2048, 0, (long long)512 * 2048, 0);
    transpose_k<<<dim3(16, 3, 1), tb>>>(emb_w, p_embt, L_, D_, D_, L_, 1, 0, 0, 0, 0);
    transpose_k<<<dim3(3, 16, 1), tb>>>(proj_w, p_projt, D_, PRED_, PRED_, D_, 1, 0, 0, 0, 0);

    // 1) RevIN + transpose, marks, trend rows
    revin_k<<<(B_ * N_ + 255) / 256, 256>>>(x_enc, gamma, beta, p_tok, p_mean, p_std);
    marks_k<<<(B_ * NMARK_ * L_ + 255) / 256, 256>>>(x_mark, p_tok);
    trend_k<<<(B_ * N_ + 255) / 256, 256>>>(p_tok, tp_w1, tp_b1, tp_w2, tp_b2, p_nt);

    // 2) Gram: guide[b] = nt[b] @ nt[b]^T
    mmak<0, 128><<<tgrid(N_, N_, 128, B_), 256>>>(
        p_nt, p_nt, nullptr, nullptr, p_guide, N_, N_, L_, L_, L_, N_, 1,
        (long long)N_ * L_, 0, (long long)N_ * L_, 0, (long long)N_ * N_, 0);

    // 3) embedding: x = tok @ emb_w + emb_b
    mmak<1, 128><<<tgrid(BT_, D_, 128, 1), 256>>>(
        p_tok, p_embt, emb_b, nullptr, p_x, BT_, D_, L_, L_, L_, D_, 1, 0, 0, 0, 0, 0, 0);

    for (int i = 0; i < LAYERS_; i++) {
        const float* wqt_i = p_wqt + (long long)i * D_ * D_;
        const float* wkt_i = p_wkt + (long long)i * D_ * D_;
        const float* wvt_i = p_wvt + (long long)i * D_ * D_;
        const float* wot_i = p_wot + (long long)i * D_ * D_;
        const float* w1t_i = p_w1t + (long long)i * D_ * DFF_;
        const float* w2t_i = p_w2t + (long long)i * DFF_ * D_;

        mmak<1, 128><<<tgrid(BT_, D_, 128, 1), 256>>>(
            p_x, wqt_i, bq + i * D_, nullptr, p_q, BT_, D_, D_, D_, D_, D_, 1, 0, 0, 0, 0, 0, 0);
        mmak<1, 128><<<tgrid(BT_, D_, 128, 1), 256>>>(
            p_x, wkt_i, bk + i * D_, nullptr, p_k, BT_, D_, D_, D_, D_, D_, 1, 0, 0, 0, 0, 0, 0);
        mmak<1, 128><<<tgrid(BT_, D_, 128, 1), 256>>>(
            p_x, wvt_i, bv + i * D_, nullptr, p_v, BT_, D_, D_, D_, D_, D_, 1, 0, 0, 0, 0, 0, 0);

        // V^T per (b,h): [E, T]
        transpose_k<<<dim3(2, 17, B_ * H_), tb>>>(
            p_v, p_vt, T_, E_, D_, T_, H_,
            (long long)T_ * D_, E_, (long long)H_ * E_ * T_, (long long)E_ * T_);

        // scores[b,h] = q @ k^T (raw; scale+gate in softmax)
        mmak<0, 128><<<tgrid(T_, T_, 128, B_ * H_), 256>>>(
            p_q, p_k, nullptr, nullptr, p_scores, T_, T_, E_, D_, D_, T_, H_,
            (long long)T_ * D_, E_, (long long)T_ * D_, E_,
            (long long)H_ * T_ * T_, (long long)T_ * T_);

        softmax_gate_k<<<B_ * H_ * T_, 256>>>(p_scores, p_guide);

        // ctx[b,:,h,:] = attn[b,h] @ V  (B operand = V^T)
        mmak<0, 64><<<tgrid(T_, E_, 64, B_ * H_), 256>>>(
            p_scores, p_vt, nullptr, nullptr, p_ctx, T_, E_, T_, T_, T_, D_, H_,
            (long long)H_ * T_ * T_, (long long)T_ * T_,
            (long long)H_ * E_ * T_, (long long)E_ * T_,
            (long long)T_ * D_, E_);

        // x_attn = x + ctx @ wo + bo
        mmak<3, 128><<<tgrid(BT_, D_, 128, 1), 256>>>(
            p_ctx, wot_i, bo + i * D_, p_x, p_tmp, BT_, D_, D_, D_, D_, D_, 1, 0, 0, 0, 0, 0, 0);

        ln_k<false><<<BT_, 128>>>(p_tmp, nullptr, ln1g + i * D_, ln1b + i * D_, p_tmp);

        mmak<2, 128><<<tgrid(BT_, DFF_, 128, 1), 256>>>(
            p_tmp, w1t_i, b1 + i * DFF_, nullptr, p_ffn, BT_, DFF_, D_, D_, D_, DFF_, 1, 0, 0, 0, 0, 0, 0);
        mmak<1, 128><<<tgrid(BT_, D_, 128, 1), 256>>>(
            p_ffn, w2t_i, b2 + i * D_, nullptr, p_ctx, BT_, D_, DFF_, DFF_, DFF_, D_, 1, 0, 0, 0, 0, 0, 0);

        ln_k<true><<<BT_, 128>>>(p_tmp, p_ctx, ln2g + i * D_, ln2b + i * D_, p_x);
    }

    ln_k<false><<<BT_, 128>>>(p_x, nullptr, normg, normb, p_tmp);

    mmak<1, 128><<<tgrid(BT_, PRED_, 128, 1), 256>>>(
        p_tmp, p_projt, proj_b, nullptr, p_q, BT_, PRED_, D_, D_, D_, PRED_, 1, 0, 0, 0, 0, 0, 0);

    out_k<<<(B_ * PRED_ * N_ + 255) / 256, 256>>>(p_q, p_mean, p_std, gamma, beta, out);
}

// round 7
// speedup vs baseline: 2.8489x; 1.0045x over previous
#include <cuda_runtime.h>
#include <cuda_bf16.h>
#include <cstdint>
#include <math.h>

// ---------------- problem constants ----------------
#define B_ 16
#define L_ 96
#define N_ 512
#define D_ 512
#define H_ 8
#define E_ 64
#define DFF_ 2048
#define T_ 516            // N_ + NMARK
#define PRED_ 96
#define NMARK_ 4
#define LAYERS_ 2
#define BT_ (B_ * T_)     // 8256
#define SCALE_ 0.125f     // 1/sqrt(E)

// ---------------- scratch (device globals; no allocation allowed) ----------------
__device__ float g_mean[B_ * N_];
__device__ float g_std[B_ * N_];
__device__ float g_tok[B_ * T_ * L_];
__device__ float g_nt[B_ * N_ * L_];
__device__ float g_guide[B_ * N_ * N_];
__device__ float g_x[BT_ * D_];
__device__ float g_tmp[BT_ * D_];
__device__ float g_q[BT_ * D_];
__device__ float g_k[BT_ * D_];
__device__ float g_v[BT_ * D_];
__device__ float g_ctx[BT_ * D_];
__device__ float g_scores[(long long)B_ * H_ * T_ * T_];   // 136 MB
__device__ float g_ffn[(long long)BT_ * DFF_];             // 67 MB
// transposed operands (B must be [N,K] K-major)
__device__ float g_wqt[LAYERS_ * D_ * D_];
__device__ float g_wkt[LAYERS_ * D_ * D_];
__device__ float g_wvt[LAYERS_ * D_ * D_];
__device__ float g_wot[LAYERS_ * D_ * D_];
__device__ float g_w1t[(long long)LAYERS_ * D_ * DFF_];
__device__ float g_w2t[(long long)LAYERS_ * DFF_ * D_];
__device__ float g_embt[D_ * L_];
__device__ float g_projt[PRED_ * D_];
__device__ float g_vt[(long long)B_ * H_ * E_ * T_];

// ---------------- mma / async-copy helpers ----------------
__device__ __forceinline__ uint32_t f2tf(float v) {
    uint32_t t;
    asm("cvt.rna.tf32.f32 %0, %1;" : "=r"(t) : "f"(v));
    return t;
}
__device__ __forceinline__ void mma8(float* c, const uint32_t* a, uint32_t b0, uint32_t b1) {
    asm volatile(
        "mma.sync.aligned.m16n8k8.row.col.f32.tf32.tf32.f32 "
        "{%0,%1,%2,%3}, {%4,%5,%6,%7}, {%8,%9}, {%0,%1,%2,%3};"
        : "+f"(c[0]), "+f"(c[1]), "+f"(c[2]), "+f"(c[3])
        : "r"(a[0]), "r"(a[1]), "r"(a[2]), "r"(a[3]), "r"(b0), "r"(b1));
}
__device__ __forceinline__ float geluf(float x) {
    return 0.5f * x * (1.0f + erff(x * 0.70710678118654752f));
}
__device__ __forceinline__ uint32_t smem_u32(const void* p) {
    uint32_t a;
    asm("{ .reg .u64 t; cvta.to.shared.u64 t, %1; cvt.u32.u64 %0, t; }" : "=r"(a) : "l"(p));
    return a;
}
__device__ __forceinline__ void cp16_full(uint32_t dst, const void* src) {
    asm volatile("cp.async.cg.shared.global [%0], [%1], 16;" :: "r"(dst), "l"(src) : "memory");
}
__device__ __forceinline__ void cp16_pred(uint32_t dst, const void* src, int nbytes) {
    asm volatile("cp.async.cg.shared.global [%0], [%1], 16, %2;" :: "r"(dst), "l"(src), "r"(nbytes) : "memory");
}
#define CP_COMMIT() asm volatile("cp.async.commit_group;" ::: "memory")
template <int Nw>
__device__ __forceinline__ void cp_wait() {
    asm volatile("cp.async.wait_group %0;" :: "n"(Nw) : "memory");
}

// ---------------- tf32 tensor-core GEMM: C[M,N] = A[M,K] @ B[N,K]^T (+epi) ----------------
// EPI: 0 none, 1 +bias, 2 +bias+gelu, 3 +bias+residual
// Tile 128 x BNt x 16, 256 threads (8 warps: 2 in M x 4 in N), 3-stage cp.async pipeline.
#define SSTRIDE 20

template <int EPI, int BNt>
__global__ void __launch_bounds__(256)
mmak(const float* __restrict__ A, const float* __restrict__ Bm,
     const float* __restrict__ bias, const float* __restrict__ Res,
     float* __restrict__ C,
     int M, int Nn, int K, int lda, int ldb, int ldc, int nbH,
     long long sAb, long long sAh, long long sBb, long long sBh,
     long long sCb, long long sCh) {
    constexpr int WN = BNt / 4;            // warp n-tile
    constexpr int NI = WN / 8;             // n-fragments per warp
    constexpr int BQ = (BNt * 4) / 256;    // B float4 loads per thread (2 or 1)
    constexpr int AE = 128 * SSTRIDE;      // A stage elements
    constexpr int BE = BNt * SSTRIDE;      // B stage elements
    constexpr int STG = AE + BE;           // stage elements

    extern __shared__ char smem_raw[];
    float* smf = (float*)smem_raw;
    const uint32_t sbase = smem_u32(smem_raw);

    int tid = threadIdx.x;
    int z = blockIdx.z, zb = z / nbH, zh = z % nbH;
    A  += zb * sAb + zh * sAh;
    Bm += zb * sBb + zh * sBh;
    C  += zb * sCb + zh * sCh;
    int m0 = blockIdx.y * 128, n0 = blockIdx.x * BNt;

    int lane = tid & 31, wid = tid >> 5;
    int wm = (wid & 1) * 64;
    int wn = (wid >> 1) * WN;
    int grp = lane >> 2, tig = lane & 3;

    float acc[4][NI][4];
#pragma unroll
    for (int mi = 0; mi < 4; mi++)
#pragma unroll
        for (int ni = 0; ni < NI; ni++)
#pragma unroll
            for (int r = 0; r < 4; r++) acc[mi][ni][r] = 0.f;

    const int NC = (K + 15) >> 4;
    const bool full = (m0 + 128 <= M) && (n0 + BNt <= Nn) && ((K & 15) == 0);

    // precomputed per-thread load coords
    const int a_row0 = tid >> 2, a_c4 = (tid & 3) << 2;   // + u*64 rows for A

    auto issue = [&](int c, int st) {
        int k0 = c * 16;
        uint32_t abase = sbase + (uint32_t)(st * STG) * 4u;
        uint32_t bbase = abase + (uint32_t)AE * 4u;
        if (full) {
#pragma unroll
            for (int u = 0; u < 2; u++) {
                int row = a_row0 + u * 64;
                cp16_full(abase + (uint32_t)(row * SSTRIDE + a_c4) * 4u,
                          A + (long long)(m0 + row) * lda + k0 + a_c4);
            }
#pragma unroll
            for (int u = 0; u < BQ; u++) {
                int row = a_row0 + u * 64;
                cp16_full(bbase + (uint32_t)(row * SSTRIDE + a_c4) * 4u,
                          Bm + (long long)(n0 + row) * ldb + k0 + a_c4);
            }
        } else {
#pragma unroll
            for (int u = 0; u < 2; u++) {
                int row = a_row0 + u * 64;
                int gm = m0 + row, gk = k0 + a_c4;
                int nb = 0;
                if (gm < M) { int rem = K - gk; nb = rem >= 4 ? 16 : (rem > 0 ? rem * 4 : 0); }
                const float* src = (nb > 0) ? (A + (long long)gm * lda + gk) : A;
                cp16_pred(abase + (uint32_t)(row * SSTRIDE + a_c4) * 4u, src, nb);
            }
#pragma unroll
            for (int u = 0; u < BQ; u++) {
                int row = a_row0 + u * 64;
                int gn = n0 + row, gk = k0 + a_c4;
                int nb = 0;
                if (gn < Nn) { int rem = K - gk; nb = rem >= 4 ? 16 : (rem > 0 ? rem * 4 : 0); }
                const float* src = (nb > 0) ? (Bm + (long long)gn * ldb + gk) : Bm;
                cp16_pred(bbase + (uint32_t)(row * SSTRIDE + a_c4) * 4u, src, nb);
            }
        }
    };

    // prologue: up to 2 chunks in flight
    int pre = NC < 2 ? NC : 2;
    for (int s = 0; s < pre; s++) { issue(s, s); CP_COMMIT(); }

    for (int c = 0; c < NC; c++) {
        if (c + 1 < NC) cp_wait<1>(); else cp_wait<0>();
        __syncthreads();                              // chunk c visible; stage (c-1)%3 free
        if (c + 2 < NC) { issue(c + 2, (c + 2) % 3); CP_COMMIT(); }

        const float* as = smf + (c % 3) * STG;
        const float* bs = as + AE;
#pragma unroll
        for (int kk = 0; kk < 2; kk++) {
            int k0 = kk * 8;
            uint32_t af[4][4];
#pragma unroll
            for (int mi = 0; mi < 4; mi++) {
                int r = wm + mi * 16 + grp;
                af[mi][0] = f2tf(as[r * SSTRIDE + k0 + tig]);
                af[mi][1] = f2tf(as[(r + 8) * SSTRIDE + k0 + tig]);
                af[mi][2] = f2tf(as[r * SSTRIDE + k0 + tig + 4]);
                af[mi][3] = f2tf(as[(r + 8) * SSTRIDE + k0 + tig + 4]);
            }
#pragma unroll
            for (int ni = 0; ni < NI; ni++) {
                int col = wn + ni * 8 + grp;
                uint32_t b0 = f2tf(bs[col * SSTRIDE + k0 + tig]);
                uint32_t b1 = f2tf(bs[col * SSTRIDE + k0 + tig + 4]);
#pragma unroll
                for (int mi = 0; mi < 4; mi++) mma8(acc[mi][ni], af[mi], b0, b1);
            }
        }
    }

    // ---- epilogue: fragment -> gmem (float2 stores; cols always even) ----
#pragma unroll
    for (int mi = 0; mi < 4; mi++) {
#pragma unroll
        for (int ni = 0; ni < NI; ni++) {
            int col = n0 + wn + ni * 8 + 2 * tig;
            if (col >= Nn) continue;
            float bv0 = 0.f, bv1 = 0.f;
            if (EPI >= 1) { bv0 = bias[col]; bv1 = bias[col + 1]; }
#pragma unroll
            for (int h = 0; h < 2; h++) {
                int gm = m0 + wm + mi * 16 + grp + h * 8;
                if (gm >= M) continue;
                float v0 = acc[mi][ni][h * 2 + 0] + bv0;
                float v1 = acc[mi][ni][h * 2 + 1] + bv1;
                if (EPI == 2) { v0 = geluf(v0); v1 = geluf(v1); }
                if (EPI == 3) {
                    const float* rp = Res + (long long)gm * ldc + col;
                    v0 += rp[0]; v1 += rp[1];
                }
                *(float2*)(C + (long long)gm * ldc + col) = make_float2(v0, v1);
            }
        }
    }
}

// ---------------- batched tiled transpose ----------------
__global__ void transpose_k(const float* __restrict__ S, float* __restrict__ Dst,
                            int R, int C, int lds, int ldd, int nb2,
                            long long sSb, long long sSh, long long sDb, long long sDh) {
    __shared__ float t[32][33];
    int z = blockIdx.z, zb = z / nb2, zh = z % nb2;
    S += zb * sSb + zh * sSh;
    Dst += zb * sDb + zh * sDh;
    int r0 = blockIdx.y * 32, c0 = blockIdx.x * 32;
    int c = c0 + threadIdx.x;
#pragma unroll
    for (int i = 0; i < 32; i += 8) {
        int r = r0 + threadIdx.y + i;
        if (r < R && c < C) t[threadIdx.y + i][threadIdx.x] = S[(long long)r * lds + c];
    }
    __syncthreads();
    int cc2 = r0 + threadIdx.x;
#pragma unroll
    for (int i = 0; i < 32; i += 8) {
        int rr2 = c0 + threadIdx.y + i;
        if (rr2 < C && cc2 < R) Dst[(long long)rr2 * ldd + cc2] = t[threadIdx.x][threadIdx.y + i];
    }
}

// ---------------- reductions ----------------
__device__ __forceinline__ float block_sum(float v, float* sh) {
    int lane = threadIdx.x & 31, w = threadIdx.x >> 5;
#pragma unroll
    for (int o = 16; o; o >>= 1) v += __shfl_xor_sync(0xffffffffu, v, o);
    if (lane == 0) sh[w] = v;
    __syncthreads();
    if (threadIdx.x == 0) {
        float t = 0.f; int nw = blockDim.x >> 5;
        for (int i = 0; i < nw; i++) t += sh[i];
        sh[32] = t;
    }
    __syncthreads();
    float r = sh[32];
    __syncthreads();
    return r;
}
__device__ __forceinline__ float block_max(float v, float* sh) {
    int lane = threadIdx.x & 31, w = threadIdx.x >> 5;
#pragma unroll
    for (int o = 16; o; o >>= 1) v = fmaxf(v, __shfl_xor_sync(0xffffffffu, v, o));
    if (lane == 0) sh[w] = v;
    __syncthreads();
    if (threadIdx.x == 0) {
        float t = -1e30f; int nw = blockDim.x >> 5;
        for (int i = 0; i < nw; i++) t = fmaxf(t, sh[i]);
        sh[32] = t;
    }
    __syncthreads();
    float r = sh[32];
    __syncthreads();
    return r;
}

// ---------------- small fused kernels ----------------
__global__ void revin_k(const float* __restrict__ x, const float* __restrict__ gamma,
                        const float* __restrict__ beta, float* __restrict__ tok,
                        float* __restrict__ meanO, float* __restrict__ stdO) {
    int idx = blockIdx.x * blockDim.x + threadIdx.x;
    if (idx >= B_ * N_) return;
    int b = idx / N_, n = idx % N_;
    const float* xp = x + (long long)b * L_ * N_ + n;
    float s = 0.f, s2 = 0.f;
#pragma unroll 4
    for (int l = 0; l < L_; l++) { float v = xp[(long long)l * N_]; s += v; s2 += v * v; }
    float mean = s / L_;
    float var = fmaxf(s2 / L_ - mean * mean, 0.f);
    float sd = sqrtf(var + 1e-5f);
    meanO[idx] = mean; stdO[idx] = sd;
    float g = gamma[n], be = beta[n], inv = 1.f / sd;
    float* tp = tok + ((long long)b * T_ + n) * L_;
#pragma unroll 4
    for (int l = 0; l < L_; l++) tp[l] = (xp[(long long)l * N_] - mean) * inv * g + be;
}

__global__ void marks_k(const float* __restrict__ xm, float* __restrict__ tok) {
    int idx = blockIdx.x * blockDim.x + threadIdx.x;
    if (idx >= B_ * NMARK_ * L_) return;
    int l = idx % L_, m = (idx / L_) % NMARK_, b = idx / (L_ * NMARK_);
    tok[((long long)b * T_ + N_ + m) * L_ + l] = xm[((long long)b * L_ + l) * NMARK_ + m];
}

__global__ void trend_k(const float* __restrict__ tok,
                        const float* __restrict__ w1, const float* __restrict__ b1,
                        const float* __restrict__ w2, const float* __restrict__ b2,
                        float* __restrict__ nt) {
    int idx = blockIdx.x * blockDim.x + threadIdx.x;
    if (idx >= B_ * N_) return;
    int b = idx / N_, n = idx % N_;
    const float* xp = tok + ((long long)b * T_ + n) * L_;
    float cum[L_ + 1];
    cum[0] = 0.f;
    float s = 0.f, s2 = 0.f;
    for (int l = 0; l < L_; l++) {
        float v = xp[l];
        cum[l + 1] = cum[l] + v;
        s += v; s2 += v * v;
    }
    float mean = s / L_;
    float var = fmaxf(s2 / L_ - mean * mean, 0.f);
    float sd = sqrtf(var + 1e-6f);
    float logits[4] = {b2[0], b2[1], b2[2], b2[3]};
#pragma unroll
    for (int j = 0; j < 16; j++) {
        float h = fmaxf(mean * w1[j] + sd * w1[16 + j] + b1[j], 0.f);
#pragma unroll
        for (int w = 0; w < 4; w++) logits[w] += h * w2[j * 4 + w];
    }
    float mx = fmaxf(fmaxf(logits[0], logits[1]), fmaxf(logits[2], logits[3]));
    float wt[4], ws = 0.f;
#pragma unroll
    for (int w = 0; w < 4; w++) { wt[w] = expf(logits[w] - mx); ws += wt[w]; }
#pragma unroll
    for (int w = 0; w < 4; w++) wt[w] /= ws;
    const int W[4] = {4, 8, 12, 24};
    float x0 = xp[0];
    float t[L_];
    float nrm2 = 0.f;
    for (int l = 0; l < L_; l++) {
        float tv = 0.f;
#pragma unroll
        for (int wi = 0; wi < 4; wi++) {
            int w = W[wi], lo = l - w + 1;
            float sum = (lo < 0) ? (cum[l + 1] + (float)(-lo) * x0) : (cum[l + 1] - cum[lo]);
            tv += wt[wi] * sum / (float)w;
        }
        t[l] = tv; nrm2 += tv * tv;
    }
    float inv = 1.f / fmaxf(sqrtf(nrm2), 1e-12f);
    float* np = nt + ((long long)b * N_ + n) * L_;
    for (int l = 0; l < L_; l++) np[l] = t[l] * inv;
}

__global__ void softmax_gate_k(float* __restrict__ sc, const float* __restrict__ guide) {
    __shared__ float sh[33];
    long long row = blockIdx.x;
    int i = (int)(row % T_);
    int bh = (int)(row / T_);
    int b = bh / H_;
    float* sp = sc + row * T_;
    const float* gp = guide + (long long)b * N_ * N_ + (long long)i * N_;
    float pv[3];
    float mx = -1e30f;
#pragma unroll
    for (int it = 0; it < 3; it++) {
        int j = threadIdx.x + it * 256;
        if (j < T_) mx = fmaxf(mx, sp[j] * SCALE_);
    }
    mx = block_max(mx, sh);
    float psum = 0.f;
#pragma unroll
    for (int it = 0; it < 3; it++) {
        int j = threadIdx.x + it * 256;
        float p = 0.f;
        if (j < T_) { p = expf(sp[j] * SCALE_ - mx); psum += p; }
        pv[it] = p;
    }
    psum = block_sum(psum, sh);
    float invP = 1.f / psum;
    float s2 = 0.f;
#pragma unroll
    for (int it = 0; it < 3; it++) {
        int j = threadIdx.x + it * 256;
        if (j < T_) {
            float g = 0.5f;
            if (i < N_ && j < N_) g = 1.f / (1.f + expf(-gp[j]));
            float a = pv[it] * invP * g;
            pv[it] = a; s2 += a;
        }
    }
    s2 = block_sum(s2, sh);
    float r = 1.f / (s2 + 1e-6f);
#pragma unroll
    for (int it = 0; it < 3; it++) {
        int j = threadIdx.x + it * 256;
        if (j < T_) sp[j] = pv[it] * r;
    }
}

template <bool RES>
__global__ void ln_k(const float* __restrict__ X, const float* __restrict__ Y,
                     const float* __restrict__ g, const float* __restrict__ be,
                     float* __restrict__ out) {
    __shared__ float sh[33];
    long long r = blockIdx.x;
    const float* x = X + r * D_;
    const float* y = RES ? (Y + r * D_) : nullptr;
    float v[4];
    float s = 0.f;
#pragma unroll
    for (int i = 0; i < 4; i++) {
        int c = threadIdx.x + i * 128;
        v[i] = x[c] + (RES ? y[c] : 0.f);
        s += v[i];
    }
    s = block_sum(s, sh);
    float mean = s / D_;
    float s2 = 0.f;
#pragma unroll
    for (int i = 0; i < 4; i++) { float d = v[i] - mean; s2 += d * d; }
    s2 = block_sum(s2, sh);
    float rstd = rsqrtf(s2 / D_ + 1e-5f);
    float* o = out + r * D_;
#pragma unroll
    for (int i = 0; i < 4; i++) {
        int c = threadIdx.x + i * 128;
        o[c] = (v[i] - mean) * rstd * g[c] + be[c];
    }
}

__global__ void out_k(const float* __restrict__ proj, const float* __restrict__ meanI,
                      const float* __restrict__ stdI, const float* __restrict__ gamma,
                      const float* __restrict__ beta, float* __restrict__ out) {
    int idx = blockIdx.x * blockDim.x + threadIdx.x;
    if (idx >= B_ * PRED_ * N_) return;
    int n = idx % N_, p = (idx / N_) % PRED_, b = idx / (N_ * PRED_);
    float v = proj[((long long)b * T_ + n) * PRED_ + p];
    v = (v - beta[n]) / (gamma[n] + 1e-5f) * stdI[b * N_ + n] + meanI[b * N_ + n];
    out[idx] = v;
}

// ---------------- host orchestration ----------------
static inline dim3 tgrid(int M, int Nn, int BN, int batch) {
    return dim3((Nn + BN - 1) / BN, (M + 127) / 128, batch);
}
#define SMEMB(BNt) (3 * (128 * SSTRIDE + (BNt) * SSTRIDE) * 4)

extern "C" void kernel_launch(void* const* d_in, const int* in_sizes, int n_in,
                              void* d_out, int out_size) {
    const float* x_enc  = (const float*)d_in[0];
    const float* x_mark = (const float*)d_in[1];
    const float* gamma  = (const float*)d_in[4];
    const float* beta   = (const float*)d_in[5];
    const float* tp_w1  = (const float*)d_in[6];
    const float* tp_b1  = (const float*)d_in[7];
    const float* tp_w2  = (const float*)d_in[8];
    const float* tp_b2  = (const float*)d_in[9];
    const float* emb_w  = (const float*)d_in[10];
    const float* emb_b  = (const float*)d_in[11];
    const float* wq = (const float*)d_in[12];
    const float* bq = (const float*)d_in[13];
    const float* wk = (const float*)d_in[14];
    const float* bk = (const float*)d_in[15];
    const float* wv = (const float*)d_in[16];
    const float* bv = (const float*)d_in[17];
    const float* wo = (const float*)d_in[18];
    const float* bo = (const float*)d_in[19];
    const float* w1 = (const float*)d_in[20];
    const float* b1 = (const float*)d_in[21];
    const float* w2 = (const float*)d_in[22];
    const float* b2 = (const float*)d_in[23];
    const float* ln1g = (const float*)d_in[24];
    const float* ln1b = (const float*)d_in[25];
    const float* ln2g = (const float*)d_in[26];
    const float* ln2b = (const float*)d_in[27];
    const float* normg = (const float*)d_in[28];
    const float* normb = (const float*)d_in[29];
    const float* proj_w = (const float*)d_in[30];
    const float* proj_b = (const float*)d_in[31];
    float* out = (float*)d_out;

    float *p_mean, *p_std, *p_tok, *p_nt, *p_guide, *p_x, *p_tmp, *p_q, *p_k, *p_v,
          *p_ctx, *p_scores, *p_ffn, *p_wqt, *p_wkt, *p_wvt, *p_wot, *p_w1t, *p_w2t,
          *p_embt, *p_projt, *p_vt;
    cudaGetSymbolAddress((void**)&p_mean, g_mean);
    cudaGetSymbolAddress((void**)&p_std, g_std);
    cudaGetSymbolAddress((void**)&p_tok, g_tok);
    cudaGetSymbolAddress((void**)&p_nt, g_nt);
    cudaGetSymbolAddress((void**)&p_guide, g_guide);
    cudaGetSymbolAddress((void**)&p_x, g_x);
    cudaGetSymbolAddress((void**)&p_tmp, g_tmp);
    cudaGetSymbolAddress((void**)&p_q, g_q);
    cudaGetSymbolAddress((void**)&p_k, g_k);
    cudaGetSymbolAddress((void**)&p_v, g_v);
    cudaGetSymbolAddress((void**)&p_ctx, g_ctx);
    cudaGetSymbolAddress((void**)&p_scores, g_scores);
    cudaGetSymbolAddress((void**)&p_ffn, g_ffn);
    cudaGetSymbolAddress((void**)&p_wqt, g_wqt);
    cudaGetSymbolAddress((void**)&p_wkt, g_wkt);
    cudaGetSymbolAddress((void**)&p_wvt, g_wvt);
    cudaGetSymbolAddress((void**)&p_wot, g_wot);
    cudaGetSymbolAddress((void**)&p_w1t, g_w1t);
    cudaGetSymbolAddress((void**)&p_w2t, g_w2t);
    cudaGetSymbolAddress((void**)&p_embt, g_embt);
    cudaGetSymbolAddress((void**)&p_projt, g_projt);
    cudaGetSymbolAddress((void**)&p_vt, g_vt);

    static int attr_done = 0;
    cudaFuncSetAttribute(mmak<0, 128>, cudaFuncAttributeMaxDynamicSharedMemorySize, SMEMB(128));
    cudaFuncSetAttribute(mmak<1, 128>, cudaFuncAttributeMaxDynamicSharedMemorySize, SMEMB(128));
    cudaFuncSetAttribute(mmak<2, 128>, cudaFuncAttributeMaxDynamicSharedMemorySize, SMEMB(128));
    cudaFuncSetAttribute(mmak<3, 128>, cudaFuncAttributeMaxDynamicSharedMemorySize, SMEMB(128));
    cudaFuncSetAttribute(mmak<0, 64>,  cudaFuncAttributeMaxDynamicSharedMemorySize, SMEMB(64));
    (void)attr_done;

    dim3 tb(32, 8);
    // weight transposes -> [N,K] K-major operands
    transpose_k<<<dim3(16, 16, 2), tb>>>(wq, p_wqt, 512, 512, 512, 512, 1, 512 * 512, 0, 512 * 512, 0);
    transpose_k<<<dim3(16, 16, 2), tb>>>(wk, p_wkt, 512, 512, 512, 512, 1, 512 * 512, 0, 512 * 512, 0);
    transpose_k<<<dim3(16, 16, 2), tb>>>(wv, p_wvt, 512, 512, 512, 512, 1, 512 * 512, 0, 512 * 512, 0);
    transpose_k<<<dim3(16, 16, 2), tb>>>(wo, p_wot, 512, 512, 512, 512, 1, 512 * 512, 0, 512 * 512, 0);
    transpose_k<<<dim3(64, 16, 2), tb>>>(w1, p_w1t, 512, 2048, 2048, 512, 1,
                                         (long long)512 * 2048, 0, (long long)512 * 2048, 0);
    transpose_k<<<dim3(16, 64, 2), tb>>>(w2, p_w2t, 2048, 512, 512, 2048, 1,
                                         (long long)512 * 2048, 0, (long long)512 * 2048, 0);
    transpose_k<<<dim3(16, 3, 1), tb>>>(emb_w, p_embt, L_, D_, D_, L_, 1, 0, 0, 0, 0);
    transpose_k<<<dim3(3, 16, 1), tb>>>(proj_w, p_projt, D_, PRED_, PRED_, D_, 1, 0, 0, 0, 0);

    // 1) RevIN + transpose, marks, trend rows
    revin_k<<<(B_ * N_ + 255) / 256, 256>>>(x_enc, gamma, beta, p_tok, p_mean, p_std);
    marks_k<<<(B_ * NMARK_ * L_ + 255) / 256, 256>>>(x_mark, p_tok);
    trend_k<<<(B_ * N_ + 255) / 256, 256>>>(p_tok, tp_w1, tp_b1, tp_w2, tp_b2, p_nt);

    // 2) Gram: guide[b] = nt[b] @ nt[b]^T
    mmak<0, 128><<<tgrid(N_, N_, 128, B_), 256, SMEMB(128)>>>(
        p_nt, p_nt, nullptr, nullptr, p_guide, N_, N_, L_, L_, L_, N_, 1,
        (long long)N_ * L_, 0, (long long)N_ * L_, 0, (long long)N_ * N_, 0);

    // 3) embedding: x = tok @ emb_w + emb_b
    mmak<1, 128><<<tgrid(BT_, D_, 128, 1), 256, SMEMB(128)>>>(
        p_tok, p_embt, emb_b, nullptr, p_x, BT_, D_, L_, L_, L_, D_, 1, 0, 0, 0, 0, 0, 0);

    for (int i = 0; i < LAYERS_; i++) {
        const float* wqt_i = p_wqt + (long long)i * D_ * D_;
        const float* wkt_i = p_wkt + (long long)i * D_ * D_;
        const float* wvt_i = p_wvt + (long long)i * D_ * D_;
        const float* wot_i = p_wot + (long long)i * D_ * D_;
        const float* w1t_i = p_w1t + (long long)i * D_ * DFF_;
        const float* w2t_i = p_w2t + (long long)i * DFF_ * D_;

        mmak<1, 128><<<tgrid(BT_, D_, 128, 1), 256, SMEMB(128)>>>(
            p_x, wqt_i, bq + i * D_, nullptr, p_q, BT_, D_, D_, D_, D_, D_, 1, 0, 0, 0, 0, 0, 0);
        mmak<1, 128><<<tgrid(BT_, D_, 128, 1), 256, SMEMB(128)>>>(
            p_x, wkt_i, bk + i * D_, nullptr, p_k, BT_, D_, D_, D_, D_, D_, 1, 0, 0, 0, 0, 0, 0);
        mmak<1, 128><<<tgrid(BT_, D_, 128, 1), 256, SMEMB(128)>>>(
            p_x, wvt_i, bv + i * D_, nullptr, p_v, BT_, D_, D_, D_, D_, D_, 1, 0, 0, 0, 0, 0, 0);

        // V^T per (b,h): [E, T]
        transpose_k<<<dim3(2, 17, B_ * H_), tb>>>(
            p_v, p_vt, T_, E_, D_, T_, H_,
            (long long)T_ * D_, E_, (long long)H_ * E_ * T_, (long long)E_ * T_);

        // scores[b,h] = q @ k^T (raw; scale+gate in softmax)
        mmak<0, 128><<<tgrid(T_, T_, 128, B_ * H_), 256, SMEMB(128)>>>(
            p_q, p_k, nullptr, nullptr, p_scores, T_, T_, E_, D_, D_, T_, H_,
            (long long)T_ * D_, E_, (long long)T_ * D_, E_,
            (long long)H_ * T_ * T_, (long long)T_ * T_);

        softmax_gate_k<<<B_ * H_ * T_, 256>>>(p_scores, p_guide);

        // ctx[b,:,h,:] = attn[b,h] @ V  (B operand = V^T)
        mmak<0, 64><<<tgrid(T_, E_, 64, B_ * H_), 256, SMEMB(64)>>>(
            p_scores, p_vt, nullptr, nullptr, p_ctx, T_, E_, T_, T_, T_, D_, H_,
            (long long)H_ * T_ * T_, (long long)T_ * T_,
            (long long)H_ * E_ * T_, (long long)E_ * T_,
            (long long)T_ * D_, E_);

        // x_attn = x + ctx @ wo + bo
        mmak<3, 128><<<tgrid(BT_, D_, 128, 1), 256, SMEMB(128)>>>(
            p_ctx, wot_i, bo + i * D_, p_x, p_tmp, BT_, D_, D_, D_, D_, D_, 1, 0, 0, 0, 0, 0, 0);

        ln_k<false><<<BT_, 128>>>(p_tmp, nullptr, ln1g + i * D_, ln1b + i * D_, p_tmp);

        mmak<2, 128><<<tgrid(BT_, DFF_, 128, 1), 256, SMEMB(128)>>>(
            p_tmp, w1t_i, b1 + i * DFF_, nullptr, p_ffn, BT_, DFF_, D_, D_, D_, DFF_, 1, 0, 0, 0, 0, 0, 0);
        mmak<1, 128><<<tgrid(BT_, D_, 128, 1), 256, SMEMB(128)>>>(
            p_ffn, w2t_i, b2 + i * D_, nullptr, p_ctx, BT_, D_, DFF_, DFF_, DFF_, D_, 1, 0, 0, 0, 0, 0, 0);

        ln_k<true><<<BT_, 128>>>(p_tmp, p_ctx, ln2g + i * D_, ln2b + i * D_, p_x);
    }

    ln_k<false><<<BT_, 128>>>(p_x, nullptr, normg, normb, p_tmp);

    mmak<1, 128><<<tgrid(BT_, PRED_, 128, 1), 256, SMEMB(128)>>>(
        p_tmp, p_projt, proj_b, nullptr, p_q, BT_, PRED_, D_, D_, D_, PRED_, 1, 0, 0, 0, 0, 0, 0);

    out_k<<<(B_ * PRED_ * N_ + 255) / 256, 256>>>(p_q, p_mean, p_std, gamma, beta, out);
}

// round 8
// speedup vs baseline: 3.0508x; 1.0709x over previous
#include <cuda_runtime.h>
#include <cuda_bf16.h>
#include <cstdint>
#include <math.h>

// ---------------- problem constants ----------------
#define B_ 16
#define L_ 96
#define N_ 512
#define D_ 512
#define H_ 8
#define E_ 64
#define DFF_ 2048
#define T_ 516            // N_ + NMARK
#define PRED_ 96
#define NMARK_ 4
#define LAYERS_ 2
#define BT_ (B_ * T_)     // 8256
#define SCALE_ 0.125f     // 1/sqrt(E)

// ---------------- scratch (device globals; no allocation allowed) ----------------
__device__ float g_mean[B_ * N_];
__device__ float g_std[B_ * N_];
__device__ float g_tok[B_ * T_ * L_];
__device__ float g_nt[B_ * N_ * L_];
__device__ float g_guide[B_ * N_ * N_];
__device__ float g_x[BT_ * D_];
__device__ float g_tmp[BT_ * D_];
__device__ float g_q[BT_ * D_];
__device__ float g_k[BT_ * D_];
__device__ float g_v[BT_ * D_];
__device__ float g_ctx[BT_ * D_];
__device__ float g_scores[(long long)B_ * H_ * T_ * T_];   // 136 MB
__device__ float g_ffn[(long long)BT_ * DFF_];             // 67 MB
// transposed operands (B must be [N,K] K-major)
__device__ float g_wqt[LAYERS_ * D_ * D_];
__device__ float g_wkt[LAYERS_ * D_ * D_];
__device__ float g_wvt[LAYERS_ * D_ * D_];
__device__ float g_wot[LAYERS_ * D_ * D_];
__device__ float g_w1t[(long long)LAYERS_ * D_ * DFF_];
__device__ float g_w2t[(long long)LAYERS_ * DFF_ * D_];
__device__ float g_embt[D_ * L_];
__device__ float g_projt[PRED_ * D_];
__device__ float g_vt[(long long)B_ * H_ * E_ * T_];

// ---------------- mma / async-copy helpers ----------------
__device__ __forceinline__ uint32_t f2tf(float v) {
    uint32_t t;
    asm("cvt.rna.tf32.f32 %0, %1;" : "=r"(t) : "f"(v));
    return t;
}
__device__ __forceinline__ float rnd_tf(float v) {        // round fp32 -> tf32-representable fp32
    return __uint_as_float(f2tf(v));
}
__device__ __forceinline__ void mma8(float* c, const uint32_t* a, uint32_t b0, uint32_t b1) {
    asm volatile(
        "mma.sync.aligned.m16n8k8.row.col.f32.tf32.tf32.f32 "
        "{%0,%1,%2,%3}, {%4,%5,%6,%7}, {%8,%9}, {%0,%1,%2,%3};"
        : "+f"(c[0]), "+f"(c[1]), "+f"(c[2]), "+f"(c[3])
        : "r"(a[0]), "r"(a[1]), "r"(a[2]), "r"(a[3]), "r"(b0), "r"(b1));
}
__device__ __forceinline__ float geluf(float x) {
    return 0.5f * x * (1.0f + erff(x * 0.70710678118654752f));
}
__device__ __forceinline__ uint32_t smem_u32(const void* p) {
    uint32_t a;
    asm("{ .reg .u64 t; cvta.to.shared.u64 t, %1; cvt.u32.u64 %0, t; }" : "=r"(a) : "l"(p));
    return a;
}
__device__ __forceinline__ void cp16_full(uint32_t dst, const void* src) {
    asm volatile("cp.async.cg.shared.global [%0], [%1], 16;" :: "r"(dst), "l"(src) : "memory");
}
__device__ __forceinline__ void cp16_pred(uint32_t dst, const void* src, int nbytes) {
    asm volatile("cp.async.cg.shared.global [%0], [%1], 16, %2;" :: "r"(dst), "l"(src), "r"(nbytes) : "memory");
}
#define CP_COMMIT() asm volatile("cp.async.commit_group;" ::: "memory")
template <int Nw>
__device__ __forceinline__ void cp_wait() {
    asm volatile("cp.async.wait_group %0;" :: "n"(Nw) : "memory");
}

// ---------------- tf32 tensor-core GEMM: C[M,N] = A[M,K] @ B[N,K]^T (+epi) ----------------
// EPI: 0 none, 1 +bias, 2 +bias+gelu, 3 +bias+residual
// All operands MUST be pre-rounded to tf32 by their producers (mainloop feeds raw bits to mma).
// ROUND: round the output to tf32 (set when C feeds another GEMM).
#define SSTRIDE 20

template <int EPI, int BNt, bool ROUND>
__global__ void __launch_bounds__(256)
mmak(const float* __restrict__ A, const float* __restrict__ Bm,
     const float* __restrict__ bias, const float* __restrict__ Res,
     float* __restrict__ C,
     int M, int Nn, int K, int lda, int ldb, int ldc, int nbH,
     long long sAb, long long sAh, long long sBb, long long sBh,
     long long sCb, long long sCh) {
    constexpr int WN = BNt / 4;            // warp n-tile
    constexpr int NI = WN / 8;             // n-fragments per warp
    constexpr int BQ = (BNt * 4) / 256;    // B float4 loads per thread (2 or 1)
    constexpr int AE = 128 * SSTRIDE;      // A stage elements
    constexpr int BE = BNt * SSTRIDE;      // B stage elements
    constexpr int STG = AE + BE;           // stage elements

    extern __shared__ char smem_raw[];
    const uint32_t* smu = (const uint32_t*)smem_raw;
    const uint32_t sbase = smem_u32(smem_raw);

    int tid = threadIdx.x;
    int z = blockIdx.z, zb = z / nbH, zh = z % nbH;
    A  += zb * sAb + zh * sAh;
    Bm += zb * sBb + zh * sBh;
    C  += zb * sCb + zh * sCh;
    int m0 = blockIdx.y * 128, n0 = blockIdx.x * BNt;

    int lane = tid & 31, wid = tid >> 5;
    int wm = (wid & 1) * 64;
    int wn = (wid >> 1) * WN;
    int grp = lane >> 2, tig = lane & 3;

    float acc[4][NI][4];
#pragma unroll
    for (int mi = 0; mi < 4; mi++)
#pragma unroll
        for (int ni = 0; ni < NI; ni++)
#pragma unroll
            for (int r = 0; r < 4; r++) acc[mi][ni][r] = 0.f;

    const int NC = (K + 15) >> 4;
    const bool full = (m0 + 128 <= M) && (n0 + BNt <= Nn) && ((K & 15) == 0);

    const int a_row0 = tid >> 2, a_c4 = (tid & 3) << 2;

    auto issue = [&](int c, int st) {
        int k0 = c * 16;
        uint32_t abase = sbase + (uint32_t)(st * STG) * 4u;
        uint32_t bbase = abase + (uint32_t)AE * 4u;
        if (full) {
#pragma unroll
            for (int u = 0; u < 2; u++) {
                int row = a_row0 + u * 64;
                cp16_full(abase + (uint32_t)(row * SSTRIDE + a_c4) * 4u,
                          A + (long long)(m0 + row) * lda + k0 + a_c4);
            }
#pragma unroll
            for (int u = 0; u < BQ; u++) {
                int row = a_row0 + u * 64;
                cp16_full(bbase + (uint32_t)(row * SSTRIDE + a_c4) * 4u,
                          Bm + (long long)(n0 + row) * ldb + k0 + a_c4);
            }
        } else {
#pragma unroll
            for (int u = 0; u < 2; u++) {
                int row = a_row0 + u * 64;
                int gm = m0 + row, gk = k0 + a_c4;
                int nb = 0;
                if (gm < M) { int rem = K - gk; nb = rem >= 4 ? 16 : (rem > 0 ? rem * 4 : 0); }
                const float* src = (nb > 0) ? (A + (long long)gm * lda + gk) : A;
                cp16_pred(abase + (uint32_t)(row * SSTRIDE + a_c4) * 4u, src, nb);
            }
#pragma unroll
            for (int u = 0; u < BQ; u++) {
                int row = a_row0 + u * 64;
                int gn = n0 + row, gk = k0 + a_c4;
                int nb = 0;
                if (gn < Nn) { int rem = K - gk; nb = rem >= 4 ? 16 : (rem > 0 ? rem * 4 : 0); }
                const float* src = (nb > 0) ? (Bm + (long long)gn * ldb + gk) : Bm;
                cp16_pred(bbase + (uint32_t)(row * SSTRIDE + a_c4) * 4u, src, nb);
            }
        }
    };

    int pre = NC < 2 ? NC : 2;
    for (int s = 0; s < pre; s++) { issue(s, s); CP_COMMIT(); }

    for (int c = 0; c < NC; c++) {
        if (c + 1 < NC) cp_wait<1>(); else cp_wait<0>();
        __syncthreads();
        if (c + 2 < NC) { issue(c + 2, (c + 2) % 3); CP_COMMIT(); }

        const uint32_t* as = smu + (c % 3) * STG;
        const uint32_t* bs = as + AE;
#pragma unroll
        for (int kk = 0; kk < 2; kk++) {
            int k0 = kk * 8;
            uint32_t af[4][4];
#pragma unroll
            for (int mi = 0; mi < 4; mi++) {
                int r = wm + mi * 16 + grp;
                af[mi][0] = as[r * SSTRIDE + k0 + tig];
                af[mi][1] = as[(r + 8) * SSTRIDE + k0 + tig];
                af[mi][2] = as[r * SSTRIDE + k0 + tig + 4];
                af[mi][3] = as[(r + 8) * SSTRIDE + k0 + tig + 4];
            }
#pragma unroll
            for (int ni = 0; ni < NI; ni++) {
                int col = wn + ni * 8 + grp;
                uint32_t b0 = bs[col * SSTRIDE + k0 + tig];
                uint32_t b1 = bs[col * SSTRIDE + k0 + tig + 4];
#pragma unroll
                for (int mi = 0; mi < 4; mi++) mma8(acc[mi][ni], af[mi], b0, b1);
            }
        }
    }

    // ---- epilogue ----
#pragma unroll
    for (int mi = 0; mi < 4; mi++) {
#pragma unroll
        for (int ni = 0; ni < NI; ni++) {
            int col = n0 + wn + ni * 8 + 2 * tig;
            if (col >= Nn) continue;
            float bv0 = 0.f, bv1 = 0.f;
            if (EPI >= 1) { bv0 = bias[col]; bv1 = bias[col + 1]; }
#pragma unroll
            for (int h = 0; h < 2; h++) {
                int gm = m0 + wm + mi * 16 + grp + h * 8;
                if (gm >= M) continue;
                float v0 = acc[mi][ni][h * 2 + 0] + bv0;
                float v1 = acc[mi][ni][h * 2 + 1] + bv1;
                if (EPI == 2) { v0 = geluf(v0); v1 = geluf(v1); }
                if (EPI == 3) {
                    const float* rp = Res + (long long)gm * ldc + col;
                    v0 += rp[0]; v1 += rp[1];
                }
                if (ROUND) { v0 = rnd_tf(v0); v1 = rnd_tf(v1); }
                *(float2*)(C + (long long)gm * ldc + col) = make_float2(v0, v1);
            }
        }
    }
}

// ---------------- batched tiled transpose (rounds output to tf32) ----------------
__global__ void transpose_k(const float* __restrict__ S, float* __restrict__ Dst,
                            int R, int C, int lds, int ldd, int nb2,
                            long long sSb, long long sSh, long long sDb, long long sDh) {
    __shared__ float t[32][33];
    int z = blockIdx.z, zb = z / nb2, zh = z % nb2;
    S += zb * sSb + zh * sSh;
    Dst += zb * sDb + zh * sDh;
    int r0 = blockIdx.y * 32, c0 = blockIdx.x * 32;
    int c = c0 + threadIdx.x;
#pragma unroll
    for (int i = 0; i < 32; i += 8) {
        int r = r0 + threadIdx.y + i;
        if (r < R && c < C) t[threadIdx.y + i][threadIdx.x] = S[(long long)r * lds + c];
    }
    __syncthreads();
    int cc2 = r0 + threadIdx.x;
#pragma unroll
    for (int i = 0; i < 32; i += 8) {
        int rr2 = c0 + threadIdx.y + i;
        if (rr2 < C && cc2 < R) Dst[(long long)rr2 * ldd + cc2] = rnd_tf(t[threadIdx.x][threadIdx.y + i]);
    }
}

// ---------------- reductions ----------------
__device__ __forceinline__ float block_sum(float v, float* sh) {
    int lane = threadIdx.x & 31, w = threadIdx.x >> 5;
#pragma unroll
    for (int o = 16; o; o >>= 1) v += __shfl_xor_sync(0xffffffffu, v, o);
    if (lane == 0) sh[w] = v;
    __syncthreads();
    if (threadIdx.x == 0) {
        float t = 0.f; int nw = blockDim.x >> 5;
        for (int i = 0; i < nw; i++) t += sh[i];
        sh[32] = t;
    }
    __syncthreads();
    float r = sh[32];
    __syncthreads();
    return r;
}
__device__ __forceinline__ float block_max(float v, float* sh) {
    int lane = threadIdx.x & 31, w = threadIdx.x >> 5;
#pragma unroll
    for (int o = 16; o; o >>= 1) v = fmaxf(v, __shfl_xor_sync(0xffffffffu, v, o));
    if (lane == 0) sh[w] = v;
    __syncthreads();
    if (threadIdx.x == 0) {
        float t = -1e30f; int nw = blockDim.x >> 5;
        for (int i = 0; i < nw; i++) t = fmaxf(t, sh[i]);
        sh[32] = t;
    }
    __syncthreads();
    float r = sh[32];
    __syncthreads();
    return r;
}

// ---------------- small fused kernels ----------------
__global__ void revin_k(const float* __restrict__ x, const float* __restrict__ gamma,
                        const float* __restrict__ beta, float* __restrict__ tok,
                        float* __restrict__ meanO, float* __restrict__ stdO) {
    int idx = blockIdx.x * blockDim.x + threadIdx.x;
    if (idx >= B_ * N_) return;
    int b = idx / N_, n = idx % N_;
    const float* xp = x + (long long)b * L_ * N_ + n;
    float s = 0.f, s2 = 0.f;
#pragma unroll 4
    for (int l = 0; l < L_; l++) { float v = xp[(long long)l * N_]; s += v; s2 += v * v; }
    float mean = s / L_;
    float var = fmaxf(s2 / L_ - mean * mean, 0.f);
    float sd = sqrtf(var + 1e-5f);
    meanO[idx] = mean; stdO[idx] = sd;
    float g = gamma[n], be = beta[n], inv = 1.f / sd;
    float* tp = tok + ((long long)b * T_ + n) * L_;
#pragma unroll 4
    for (int l = 0; l < L_; l++) tp[l] = rnd_tf((xp[(long long)l * N_] - mean) * inv * g + be);
}

__global__ void marks_k(const float* __restrict__ xm, float* __restrict__ tok) {
    int idx = blockIdx.x * blockDim.x + threadIdx.x;
    if (idx >= B_ * NMARK_ * L_) return;
    int l = idx % L_, m = (idx / L_) % NMARK_, b = idx / (L_ * NMARK_);
    tok[((long long)b * T_ + N_ + m) * L_ + l] = rnd_tf(xm[((long long)b * L_ + l) * NMARK_ + m]);
}

__global__ void trend_k(const float* __restrict__ tok,
                        const float* __restrict__ w1, const float* __restrict__ b1,
                        const float* __restrict__ w2, const float* __restrict__ b2,
                        float* __restrict__ nt) {
    int idx = blockIdx.x * blockDim.x + threadIdx.x;
    if (idx >= B_ * N_) return;
    int b = idx / N_, n = idx % N_;
    const float* xp = tok + ((long long)b * T_ + n) * L_;
    float cum[L_ + 1];
    cum[0] = 0.f;
    float s = 0.f, s2 = 0.f;
    for (int l = 0; l < L_; l++) {
        float v = xp[l];
        cum[l + 1] = cum[l] + v;
        s += v; s2 += v * v;
    }
    float mean = s / L_;
    float var = fmaxf(s2 / L_ - mean * mean, 0.f);
    float sd = sqrtf(var + 1e-6f);
    float logits[4] = {b2[0], b2[1], b2[2], b2[3]};
#pragma unroll
    for (int j = 0; j < 16; j++) {
        float h = fmaxf(mean * w1[j] + sd * w1[16 + j] + b1[j], 0.f);
#pragma unroll
        for (int w = 0; w < 4; w++) logits[w] += h * w2[j * 4 + w];
    }
    float mx = fmaxf(fmaxf(logits[0], logits[1]), fmaxf(logits[2], logits[3]));
    float wt[4], ws = 0.f;
#pragma unroll
    for (int w = 0; w < 4; w++) { wt[w] = expf(logits[w] - mx); ws += wt[w]; }
#pragma unroll
    for (int w = 0; w < 4; w++) wt[w] /= ws;
    const int W[4] = {4, 8, 12, 24};
    float x0 = xp[0];
    float t[L_];
    float nrm2 = 0.f;
    for (int l = 0; l < L_; l++) {
        float tv = 0.f;
#pragma unroll
        for (int wi = 0; wi < 4; wi++) {
            int w = W[wi], lo = l - w + 1;
            float sum = (lo < 0) ? (cum[l + 1] + (float)(-lo) * x0) : (cum[l + 1] - cum[lo]);
            tv += wt[wi] * sum / (float)w;
        }
        t[l] = tv; nrm2 += tv * tv;
    }
    float inv = 1.f / fmaxf(sqrtf(nrm2), 1e-12f);
    float* np = nt + ((long long)b * N_ + n) * L_;
    for (int l = 0; l < L_; l++) np[l] = rnd_tf(t[l] * inv);
}

// sigmoid over the raw Gram matrix, in place (gate shared by all heads and both layers)
__global__ void sigmoid_k(float* __restrict__ g, int n) {
    int idx = blockIdx.x * blockDim.x + threadIdx.x;
    if (idx < n) g[idx] = 1.f / (1.f + expf(-g[idx]));
}

__global__ void softmax_gate_k(float* __restrict__ sc, const float* __restrict__ gate) {
    __shared__ float sh[33];
    long long row = blockIdx.x;
    int i = (int)(row % T_);
    int bh = (int)(row / T_);
    int b = bh / H_;
    float* sp = sc + row * T_;
    const float* gp = gate + (long long)b * N_ * N_ + (long long)i * N_;
    float pv[3];
    float mx = -1e30f;
#pragma unroll
    for (int it = 0; it < 3; it++) {
        int j = threadIdx.x + it * 256;
        if (j < T_) mx = fmaxf(mx, sp[j] * SCALE_);
    }
    mx = block_max(mx, sh);
    float psum = 0.f;
#pragma unroll
    for (int it = 0; it < 3; it++) {
        int j = threadIdx.x + it * 256;
        float p = 0.f;
        if (j < T_) { p = expf(sp[j] * SCALE_ - mx); psum += p; }
        pv[it] = p;
    }
    psum = block_sum(psum, sh);
    float invP = 1.f / psum;
    float s2 = 0.f;
#pragma unroll
    for (int it = 0; it < 3; it++) {
        int j = threadIdx.x + it * 256;
        if (j < T_) {
            float g = 0.5f;
            if (i < N_ && j < N_) g = gp[j];
            float a = pv[it] * invP * g;
            pv[it] = a; s2 += a;
        }
    }
    s2 = block_sum(s2, sh);
    float r = 1.f / (s2 + 1e-6f);
#pragma unroll
    for (int it = 0; it < 3; it++) {
        int j = threadIdx.x + it * 256;
        if (j < T_) sp[j] = rnd_tf(pv[it] * r);
    }
}

template <bool RES>
__global__ void ln_k(const float* __restrict__ X, const float* __restrict__ Y,
                     const float* __restrict__ g, const float* __restrict__ be,
                     float* __restrict__ out) {
    __shared__ float sh[33];
    long long r = blockIdx.x;
    const float* x = X + r * D_;
    const float* y = RES ? (Y + r * D_) : nullptr;
    float v[4];
    float s = 0.f;
#pragma unroll
    for (int i = 0; i < 4; i++) {
        int c = threadIdx.x + i * 128;
        v[i] = x[c] + (RES ? y[c] : 0.f);
        s += v[i];
    }
    s = block_sum(s, sh);
    float mean = s / D_;
    float s2 = 0.f;
#pragma unroll
    for (int i = 0; i < 4; i++) { float d = v[i] - mean; s2 += d * d; }
    s2 = block_sum(s2, sh);
    float rstd = rsqrtf(s2 / D_ + 1e-5f);
    float* o = out + r * D_;
#pragma unroll
    for (int i = 0; i < 4; i++) {
        int c = threadIdx.x + i * 128;
        o[c] = rnd_tf((v[i] - mean) * rstd * g[c] + be[c]);
    }
}

__global__ void out_k(const float* __restrict__ proj, const float* __restrict__ meanI,
                      const float* __restrict__ stdI, const float* __restrict__ gamma,
                      const float* __restrict__ beta, float* __restrict__ out) {
    int idx = blockIdx.x * blockDim.x + threadIdx.x;
    if (idx >= B_ * PRED_ * N_) return;
    int n = idx % N_, p = (idx / N_) % PRED_, b = idx / (N_ * PRED_);
    float v = proj[((long long)b * T_ + n) * PRED_ + p];
    v = (v - beta[n]) / (gamma[n] + 1e-5f) * stdI[b * N_ + n] + meanI[b * N_ + n];
    out[idx] = v;
}

// ---------------- host orchestration ----------------
static inline dim3 tgrid(int M, int Nn, int BN, int batch) {
    return dim3((Nn + BN - 1) / BN, (M + 127) / 128, batch);
}
#define SMEMB(BNt) (3 * (128 * SSTRIDE + (BNt) * SSTRIDE) * 4)

extern "C" void kernel_launch(void* const* d_in, const int* in_sizes, int n_in,
                              void* d_out, int out_size) {
    const float* x_enc  = (const float*)d_in[0];
    const float* x_mark = (const float*)d_in[1];
    const float* gamma  = (const float*)d_in[4];
    const float* beta   = (const float*)d_in[5];
    const float* tp_w1  = (const float*)d_in[6];
    const float* tp_b1  = (const float*)d_in[7];
    const float* tp_w2  = (const float*)d_in[8];
    const float* tp_b2  = (const float*)d_in[9];
    const float* emb_w  = (const float*)d_in[10];
    const float* emb_b  = (const float*)d_in[11];
    const float* wq = (const float*)d_in[12];
    const float* bq = (const float*)d_in[13];
    const float* wk = (const float*)d_in[14];
    const float* bk = (const float*)d_in[15];
    const float* wv = (const float*)d_in[16];
    const float* bv = (const float*)d_in[17];
    const float* wo = (const float*)d_in[18];
    const float* bo = (const float*)d_in[19];
    const float* w1 = (const float*)d_in[20];
    const float* b1 = (const float*)d_in[21];
    const float* w2 = (const float*)d_in[22];
    const float* b2 = (const float*)d_in[23];
    const float* ln1g = (const float*)d_in[24];
    const float* ln1b = (const float*)d_in[25];
    const float* ln2g = (const float*)d_in[26];
    const float* ln2b = (const float*)d_in[27];
    const float* normg = (const float*)d_in[28];
    const float* normb = (const float*)d_in[29];
    const float* proj_w = (const float*)d_in[30];
    const float* proj_b = (const float*)d_in[31];
    float* out = (float*)d_out;

    float *p_mean, *p_std, *p_tok, *p_nt, *p_guide, *p_x, *p_tmp, *p_q, *p_k, *p_v,
          *p_ctx, *p_scores, *p_ffn, *p_wqt, *p_wkt, *p_wvt, *p_wot, *p_w1t, *p_w2t,
          *p_embt, *p_projt, *p_vt;
    cudaGetSymbolAddress((void**)&p_mean, g_mean);
    cudaGetSymbolAddress((void**)&p_std, g_std);
    cudaGetSymbolAddress((void**)&p_tok, g_tok);
    cudaGetSymbolAddress((void**)&p_nt, g_nt);
    cudaGetSymbolAddress((void**)&p_guide, g_guide);
    cudaGetSymbolAddress((void**)&p_x, g_x);
    cudaGetSymbolAddress((void**)&p_tmp, g_tmp);
    cudaGetSymbolAddress((void**)&p_q, g_q);
    cudaGetSymbolAddress((void**)&p_k, g_k);
    cudaGetSymbolAddress((void**)&p_v, g_v);
    cudaGetSymbolAddress((void**)&p_ctx, g_ctx);
    cudaGetSymbolAddress((void**)&p_scores, g_scores);
    cudaGetSymbolAddress((void**)&p_ffn, g_ffn);
    cudaGetSymbolAddress((void**)&p_wqt, g_wqt);
    cudaGetSymbolAddress((void**)&p_wkt, g_wkt);
    cudaGetSymbolAddress((void**)&p_wvt, g_wvt);
    cudaGetSymbolAddress((void**)&p_wot, g_wot);
    cudaGetSymbolAddress((void**)&p_w1t, g_w1t);
    cudaGetSymbolAddress((void**)&p_w2t, g_w2t);
    cudaGetSymbolAddress((void**)&p_embt, g_embt);
    cudaGetSymbolAddress((void**)&p_projt, g_projt);
    cudaGetSymbolAddress((void**)&p_vt, g_vt);

    cudaFuncSetAttribute(mmak<0, 128, true>,  cudaFuncAttributeMaxDynamicSharedMemorySize, SMEMB(128));
    cudaFuncSetAttribute(mmak<1, 128, true>,  cudaFuncAttributeMaxDynamicSharedMemorySize, SMEMB(128));
    cudaFuncSetAttribute(mmak<1, 128, false>, cudaFuncAttributeMaxDynamicSharedMemorySize, SMEMB(128));
    cudaFuncSetAttribute(mmak<2, 128, true>,  cudaFuncAttributeMaxDynamicSharedMemorySize, SMEMB(128));
    cudaFuncSetAttribute(mmak<3, 128, true>,  cudaFuncAttributeMaxDynamicSharedMemorySize, SMEMB(128));
    cudaFuncSetAttribute(mmak<0, 64, true>,   cudaFuncAttributeMaxDynamicSharedMemorySize, SMEMB(64));

    dim3 tb(32, 8);

    // Launch order arranged so profile slot #5 (-s 5 -c 1) lands on an mmak (embedding GEMM).
    // 0) RevIN + transpose
    revin_k<<<(B_ * N_ + 255) / 256, 256>>>(x_enc, gamma, beta, p_tok, p_mean, p_std);
    // 1) marks
    marks_k<<<(B_ * NMARK_ * L_ + 255) / 256, 256>>>(x_mark, p_tok);
    // 2) trend rows
    trend_k<<<(B_ * N_ + 255) / 256, 256>>>(p_tok, tp_w1, tp_b1, tp_w2, tp_b2, p_nt);
    // 3) emb weight transpose
    transpose_k<<<dim3(16, 3, 1), tb>>>(emb_w, p_embt, L_, D_, D_, L_, 1, 0, 0, 0, 0);
    // 4) Gram: guide[b] = nt[b] @ nt[b]^T (raw logits)
    mmak<0, 128, true><<<tgrid(N_, N_, 128, B_), 256, SMEMB(128)>>>(
        p_nt, p_nt, nullptr, nullptr, p_guide, N_, N_, L_, L_, L_, N_, 1,
        (long long)N_ * L_, 0, (long long)N_ * L_, 0, (long long)N_ * N_, 0);
    // 5) embedding: x = tok @ emb_w + emb_b   <-- profiled launch
    mmak<1, 128, true><<<tgrid(BT_, D_, 128, 1), 256, SMEMB(128)>>>(
        p_tok, p_embt, emb_b, nullptr, p_x, BT_, D_, L_, L_, L_, D_, 1, 0, 0, 0, 0, 0, 0);
    // 6) sigmoid gate (shared across heads and layers)
    sigmoid_k<<<(B_ * N_ * N_ + 255) / 256, 256>>>(p_guide, B_ * N_ * N_);
    // 7-13) remaining weight transposes
    transpose_k<<<dim3(16, 16, 2), tb>>>(wq, p_wqt, 512, 512, 512, 512, 1, 512 * 512, 0, 512 * 512, 0);
    transpose_k<<<dim3(16, 16, 2), tb>>>(wk, p_wkt, 512, 512, 512, 512, 1, 512 * 512, 0, 512 * 512, 0);
    transpose_k<<<dim3(16, 16, 2), tb>>>(wv, p_wvt, 512, 512, 512, 512, 1, 512 * 512, 0, 512 * 512, 0);
    transpose_k<<<dim3(16, 16, 2), tb>>>(wo, p_wot, 512, 512, 512, 512, 1, 512 * 512, 0, 512 * 512, 0);
    transpose_k<<<dim3(64, 16, 2), tb>>>(w1, p_w1t, 512, 2048, 2048, 512, 1,
                                         (long long)512 * 2048, 0, (long long)512 * 2048, 0);
    transpose_k<<<dim3(16, 64, 2), tb>>>(w2, p_w2t, 2048, 512, 512, 2048, 1,
                                         (long long)512 * 2048, 0, (long long)512 * 2048, 0);
    transpose_k<<<dim3(3, 16, 1), tb>>>(proj_w, p_projt, D_, PRED_, PRED_, D_, 1, 0, 0, 0, 0);

    for (int i = 0; i < LAYERS_; i++) {
        const float* wqt_i = p_wqt + (long long)i * D_ * D_;
        const float* wkt_i = p_wkt + (long long)i * D_ * D_;
        const float* wvt_i = p_wvt + (long long)i * D_ * D_;
        const float* wot_i = p_wot + (long long)i * D_ * D_;
        const float* w1t_i = p_w1t + (long long)i * D_ * DFF_;
        const float* w2t_i = p_w2t + (long long)i * DFF_ * D_;

        mmak<1, 128, true><<<tgrid(BT_, D_, 128, 1), 256, SMEMB(128)>>>(
            p_x, wqt_i, bq + i * D_, nullptr, p_q, BT_, D_, D_, D_, D_, D_, 1, 0, 0, 0, 0, 0, 0);
        mmak<1, 128, true><<<tgrid(BT_, D_, 128, 1), 256, SMEMB(128)>>>(
            p_x, wkt_i, bk + i * D_, nullptr, p_k, BT_, D_, D_, D_, D_, D_, 1, 0, 0, 0, 0, 0, 0);
        mmak<1, 128, true><<<tgrid(BT_, D_, 128, 1), 256, SMEMB(128)>>>(
            p_x, wvt_i, bv + i * D_, nullptr, p_v, BT_, D_, D_, D_, D_, D_, 1, 0, 0, 0, 0, 0, 0);

        // V^T per (b,h): [E, T]
        transpose_k<<<dim3(2, 17, B_ * H_), tb>>>(
            p_v, p_vt, T_, E_, D_, T_, H_,
            (long long)T_ * D_, E_, (long long)H_ * E_ * T_, (long long)E_ * T_);

        // scores[b,h] = q @ k^T (raw; scale+gate in softmax)
        mmak<0, 128, true><<<tgrid(T_, T_, 128, B_ * H_), 256, SMEMB(128)>>>(
            p_q, p_k, nullptr, nullptr, p_scores, T_, T_, E_, D_, D_, T_, H_,
            (long long)T_ * D_, E_, (long long)T_ * D_, E_,
            (long long)H_ * T_ * T_, (long long)T_ * T_);

        softmax_gate_k<<<B_ * H_ * T_, 256>>>(p_scores, p_guide);

        // ctx[b,:,h,:] = attn[b,h] @ V  (B operand = V^T)
        mmak<0, 64, true><<<tgrid(T_, E_, 64, B_ * H_), 256, SMEMB(64)>>>(
            p_scores, p_vt, nullptr, nullptr, p_ctx, T_, E_, T_, T_, T_, D_, H_,
            (long long)H_ * T_ * T_, (long long)T_ * T_,
            (long long)H_ * E_ * T_, (long long)E_ * T_,
            (long long)T_ * D_, E_);

        // x_attn = x + ctx @ wo + bo
        mmak<3, 128, true><<<tgrid(BT_, D_, 128, 1), 256, SMEMB(128)>>>(
            p_ctx, wot_i, bo + i * D_, p_x, p_tmp, BT_, D_, D_, D_, D_, D_, 1, 0, 0, 0, 0, 0, 0);

        ln_k<false><<<BT_, 128>>>(p_tmp, nullptr, ln1g + i * D_, ln1b + i * D_, p_tmp);

        mmak<2, 128, true><<<tgrid(BT_, DFF_, 128, 1), 256, SMEMB(128)>>>(
            p_tmp, w1t_i, b1 + i * DFF_, nullptr, p_ffn, BT_, DFF_, D_, D_, D_, DFF_, 1, 0, 0, 0, 0, 0, 0);
        mmak<1, 128, true><<<tgrid(BT_, D_, 128, 1), 256, SMEMB(128)>>>(
            p_ffn, w2t_i, b2 + i * D_, nullptr, p_ctx, BT_, D_, DFF_, DFF_, DFF_, D_, 1, 0, 0, 0, 0, 0, 0);

        ln_k<true><<<BT_, 128>>>(p_tmp, p_ctx, ln2g + i * D_, ln2b + i * D_, p_x);
    }

    ln_k<false><<<BT_, 128>>>(p_x, nullptr, normg, normb, p_tmp);

    // proj output feeds out_k directly (not a GEMM input) -> no rounding
    mmak<1, 128, false><<<tgrid(BT_, PRED_, 128, 1), 256, SMEMB(128)>>>(
        p_tmp, p_projt, proj_b, nullptr, p_q, BT_, PRED_, D_, D_, D_, PRED_, 1, 0, 0, 0, 0, 0, 0);

    out_k<<<(B_ * PRED_ * N_ + 255) / 256, 256>>>(p_q, p_mean, p_std, gamma, beta, out);
}

// round 9
// speedup vs baseline: 3.3995x; 1.1143x over previous
#include <cuda_runtime.h>
#include <cuda_bf16.h>
#include <cstdint>
#include <math.h>

// ---------------- problem constants ----------------
#define B_ 16
#define L_ 96
#define N_ 512
#define D_ 512
#define H_ 8
#define E_ 64
#define DFF_ 2048
#define T_ 516            // N_ + NMARK
#define PRED_ 96
#define NMARK_ 4
#define LAYERS_ 2
#define BT_ (B_ * T_)     // 8256
#define SCALE_ 0.125f     // 1/sqrt(E)

// ---------------- scratch (device globals; no allocation allowed) ----------------
__device__ float g_mean[B_ * N_];
__device__ float g_std[B_ * N_];
__device__ float g_tok[B_ * T_ * L_];
__device__ float g_nt[B_ * N_ * L_];
__device__ float g_guide[B_ * N_ * N_];
__device__ float g_x[BT_ * D_];
__device__ float g_tmp[BT_ * D_];
__device__ float g_ctx[BT_ * D_];
__device__ float g_qkv[(long long)BT_ * 3 * D_];           // 50.7 MB
__device__ float g_ffn[(long long)BT_ * DFF_];             // 67 MB
// transposed operands (B must be [N,K] K-major)
__device__ float g_wqkvt[(long long)LAYERS_ * 3 * D_ * D_];
__device__ float g_bqkv[LAYERS_ * 3 * D_];
__device__ float g_wot[LAYERS_ * D_ * D_];
__device__ float g_w1t[(long long)LAYERS_ * D_ * DFF_];
__device__ float g_w2t[(long long)LAYERS_ * DFF_ * D_];
__device__ float g_embt[D_ * L_];
__device__ float g_projt[PRED_ * D_];

// ---------------- mma / async-copy helpers ----------------
__device__ __forceinline__ uint32_t f2tf(float v) {
    uint32_t t;
    asm("cvt.rna.tf32.f32 %0, %1;" : "=r"(t) : "f"(v));
    return t;
}
__device__ __forceinline__ float rnd_tf(float v) {
    return __uint_as_float(f2tf(v));
}
__device__ __forceinline__ void mma8(float* c, const uint32_t* a, uint32_t b0, uint32_t b1) {
    asm volatile(
        "mma.sync.aligned.m16n8k8.row.col.f32.tf32.tf32.f32 "
        "{%0,%1,%2,%3}, {%4,%5,%6,%7}, {%8,%9}, {%0,%1,%2,%3};"
        : "+f"(c[0]), "+f"(c[1]), "+f"(c[2]), "+f"(c[3])
        : "r"(a[0]), "r"(a[1]), "r"(a[2]), "r"(a[3]), "r"(b0), "r"(b1));
}
__device__ __forceinline__ float geluf(float x) {
    return 0.5f * x * (1.0f + erff(x * 0.70710678118654752f));
}
__device__ __forceinline__ uint32_t smem_u32(const void* p) {
    uint32_t a;
    asm("{ .reg .u64 t; cvta.to.shared.u64 t, %1; cvt.u32.u64 %0, t; }" : "=r"(a) : "l"(p));
    return a;
}
__device__ __forceinline__ void cp16_full(uint32_t dst, const void* src) {
    asm volatile("cp.async.cg.shared.global [%0], [%1], 16;" :: "r"(dst), "l"(src) : "memory");
}
__device__ __forceinline__ void cp16_pred(uint32_t dst, const void* src, int nbytes) {
    asm volatile("cp.async.cg.shared.global [%0], [%1], 16, %2;" :: "r"(dst), "l"(src), "r"(nbytes) : "memory");
}
#define CP_COMMIT() asm volatile("cp.async.commit_group;" ::: "memory")
template <int Nw>
__device__ __forceinline__ void cp_wait() {
    asm volatile("cp.async.wait_group %0;" :: "n"(Nw) : "memory");
}

// ---------------- tf32 tensor-core GEMM: C[M,N] = A[M,K] @ B[N,K]^T (+epi) ----------------
// EPI: 0 none, 1 +bias, 2 +bias+gelu, 3 +bias+residual.  Operands pre-rounded to tf32.
#define SSTRIDE 20

template <int EPI, int BNt, bool ROUND>
__global__ void __launch_bounds__(256)
mmak(const float* __restrict__ A, const float* __restrict__ Bm,
     const float* __restrict__ bias, const float* __restrict__ Res,
     float* __restrict__ C,
     int M, int Nn, int K, int lda, int ldb, int ldc, int nbH,
     long long sAb, long long sAh, long long sBb, long long sBh,
     long long sCb, long long sCh) {
    constexpr int WN = BNt / 4;
    constexpr int NI = WN / 8;
    constexpr int BQ = (BNt * 4) / 256;
    constexpr int AE = 128 * SSTRIDE;
    constexpr int BE = BNt * SSTRIDE;
    constexpr int STG = AE + BE;

    extern __shared__ char smem_raw[];
    const uint32_t* smu = (const uint32_t*)smem_raw;
    const uint32_t sbase = smem_u32(smem_raw);

    int tid = threadIdx.x;
    int z = blockIdx.z, zb = z / nbH, zh = z % nbH;
    A  += zb * sAb + zh * sAh;
    Bm += zb * sBb + zh * sBh;
    C  += zb * sCb + zh * sCh;
    int m0 = blockIdx.y * 128, n0 = blockIdx.x * BNt;

    int lane = tid & 31, wid = tid >> 5;
    int wm = (wid & 1) * 64;
    int wn = (wid >> 1) * WN;
    int grp = lane >> 2, tig = lane & 3;

    float acc[4][NI][4];
#pragma unroll
    for (int mi = 0; mi < 4; mi++)
#pragma unroll
        for (int ni = 0; ni < NI; ni++)
#pragma unroll
            for (int r = 0; r < 4; r++) acc[mi][ni][r] = 0.f;

    const int NC = (K + 15) >> 4;
    const bool full = (m0 + 128 <= M) && (n0 + BNt <= Nn) && ((K & 15) == 0);
    const int a_row0 = tid >> 2, a_c4 = (tid & 3) << 2;

    auto issue = [&](int c, int st) {
        int k0 = c * 16;
        uint32_t abase = sbase + (uint32_t)(st * STG) * 4u;
        uint32_t bbase = abase + (uint32_t)AE * 4u;
        if (full) {
#pragma unroll
            for (int u = 0; u < 2; u++) {
                int row = a_row0 + u * 64;
                cp16_full(abase + (uint32_t)(row * SSTRIDE + a_c4) * 4u,
                          A + (long long)(m0 + row) * lda + k0 + a_c4);
            }
#pragma unroll
            for (int u = 0; u < BQ; u++) {
                int row = a_row0 + u * 64;
                cp16_full(bbase + (uint32_t)(row * SSTRIDE + a_c4) * 4u,
                          Bm + (long long)(n0 + row) * ldb + k0 + a_c4);
            }
        } else {
#pragma unroll
            for (int u = 0; u < 2; u++) {
                int row = a_row0 + u * 64;
                int gm = m0 + row, gk = k0 + a_c4;
                int nb = 0;
                if (gm < M) { int rem = K - gk; nb = rem >= 4 ? 16 : (rem > 0 ? rem * 4 : 0); }
                const float* src = (nb > 0) ? (A + (long long)gm * lda + gk) : A;
                cp16_pred(abase + (uint32_t)(row * SSTRIDE + a_c4) * 4u, src, nb);
            }
#pragma unroll
            for (int u = 0; u < BQ; u++) {
                int row = a_row0 + u * 64;
                int gn = n0 + row, gk = k0 + a_c4;
                int nb = 0;
                if (gn < Nn) { int rem = K - gk; nb = rem >= 4 ? 16 : (rem > 0 ? rem * 4 : 0); }
                const float* src = (nb > 0) ? (Bm + (long long)gn * ldb + gk) : Bm;
                cp16_pred(bbase + (uint32_t)(row * SSTRIDE + a_c4) * 4u, src, nb);
            }
        }
    };

    int pre = NC < 2 ? NC : 2;
    for (int s = 0; s < pre; s++) { issue(s, s); CP_COMMIT(); }

    for (int c = 0; c < NC; c++) {
        if (c + 1 < NC) cp_wait<1>(); else cp_wait<0>();
        __syncthreads();
        if (c + 2 < NC) { issue(c + 2, (c + 2) % 3); CP_COMMIT(); }

        const uint32_t* as = smu + (c % 3) * STG;
        const uint32_t* bs = as + AE;
#pragma unroll
        for (int kk = 0; kk < 2; kk++) {
            int k0 = kk * 8;
            uint32_t af[4][4];
#pragma unroll
            for (int mi = 0; mi < 4; mi++) {
                int r = wm + mi * 16 + grp;
                af[mi][0] = as[r * SSTRIDE + k0 + tig];
                af[mi][1] = as[(r + 8) * SSTRIDE + k0 + tig];
                af[mi][2] = as[r * SSTRIDE + k0 + tig + 4];
                af[mi][3] = as[(r + 8) * SSTRIDE + k0 + tig + 4];
            }
#pragma unroll
            for (int ni = 0; ni < NI; ni++) {
                int col = wn + ni * 8 + grp;
                uint32_t b0 = bs[col * SSTRIDE + k0 + tig];
                uint32_t b1 = bs[col * SSTRIDE + k0 + tig + 4];
#pragma unroll
                for (int mi = 0; mi < 4; mi++) mma8(acc[mi][ni], af[mi], b0, b1);
            }
        }
    }

#pragma unroll
    for (int mi = 0; mi < 4; mi++) {
#pragma unroll
        for (int ni = 0; ni < NI; ni++) {
            int col = n0 + wn + ni * 8 + 2 * tig;
            if (col >= Nn) continue;
            float bv0 = 0.f, bv1 = 0.f;
            if (EPI >= 1) { bv0 = bias[col]; bv1 = bias[col + 1]; }
#pragma unroll
            for (int h = 0; h < 2; h++) {
                int gm = m0 + wm + mi * 16 + grp + h * 8;
                if (gm >= M) continue;
                float v0 = acc[mi][ni][h * 2 + 0] + bv0;
                float v1 = acc[mi][ni][h * 2 + 1] + bv1;
                if (EPI == 2) { v0 = geluf(v0); v1 = geluf(v1); }
                if (EPI == 3) {
                    const float* rp = Res + (long long)gm * ldc + col;
                    v0 += rp[0]; v1 += rp[1];
                }
                if (ROUND) { v0 = rnd_tf(v0); v1 = rnd_tf(v1); }
                *(float2*)(C + (long long)gm * ldc + col) = make_float2(v0, v1);
            }
        }
    }
}

// ---------------- fused gated flash attention ----------------
// Per block: (qtile, b*H+h). 8 warps x 16 rows. Online softmax with gate folded:
//   ctx_i = (sum_j e_j g_ij v_j) / (sum_j e_j g_ij + 1e-6 * sum_j e_j),  e_j = exp(s_ij - m_i)
#define QSTR 132
#define KSTR 68
#define FSMEM ((128 * QSTR + 2 * 128 * KSTR) * 4)

__global__ void __launch_bounds__(256)
flash_k(const float* __restrict__ qkv, const float* __restrict__ gate,
        float* __restrict__ ctx) {
    extern __shared__ char sm[];
    float* Sp = (float*)sm;                 // [128][QSTR]  Q staging, then P
    float* Sk = Sp + 128 * QSTR;            // [128][KSTR]
    float* Sv = Sk + 128 * KSTR;            // [128][KSTR]

    int qt = blockIdx.x;                    // 0..4
    int bh = blockIdx.y;
    int b = bh >> 3, h = bh & 7;
    int i0 = qt * 128;
    int tid = threadIdx.x, lane = tid & 31, w = tid >> 5;
    int grp = lane >> 2, tig = lane & 3;

    const float* qb = qkv + (long long)b * T_ * (3 * D_) + h * E_;
    const float* kb = qb + D_;
    const float* vb = qb + 2 * D_;

    // load Q tile (rows clamped) into Sp, extract fragments into registers
    for (int e = tid; e < 128 * 16; e += 256) {
        int r = e >> 4, c4 = (e & 15) << 2;
        int gi = i0 + r; if (gi >= T_) gi = T_ - 1;
        *(float4*)(Sp + r * QSTR + c4) = *(const float4*)(qb + (long long)gi * (3 * D_) + c4);
    }
    __syncthreads();
    uint32_t qf[8][4];
    {
        const uint32_t* s = (const uint32_t*)Sp;
        int r = w * 16 + grp;
#pragma unroll
        for (int ks = 0; ks < 8; ks++) {
            qf[ks][0] = s[r * QSTR + tig + 8 * ks];
            qf[ks][1] = s[(r + 8) * QSTR + tig + 8 * ks];
            qf[ks][2] = s[r * QSTR + tig + 4 + 8 * ks];
            qf[ks][3] = s[(r + 8) * QSTR + tig + 4 + 8 * ks];
        }
    }

    float of[8][4];
#pragma unroll
    for (int nf = 0; nf < 8; nf++)
#pragma unroll
        for (int r = 0; r < 4; r++) of[nf][r] = 0.f;
    float m0 = -1e30f, m1 = -1e30f;
    float s1a = 0.f, s1b = 0.f, s2a = 0.f, s2b = 0.f;

    const float* gb = gate + (long long)b * N_ * N_;
    const int row0 = i0 + w * 16 + grp, row1 = row0 + 8;

    for (int j0 = 0; j0 < T_; j0 += 128) {
        __syncthreads();     // previous chunk's Sk/Sv and Sp(Q) consumers done
        for (int e = tid; e < 128 * 16; e += 256) {
            int r = e >> 4, c4 = (e & 15) << 2;
            int gj = j0 + r; if (gj >= T_) gj = T_ - 1;
            *(float4*)(Sk + r * KSTR + c4) = *(const float4*)(kb + (long long)gj * (3 * D_) + c4);
            *(float4*)(Sv + r * KSTR + c4) = *(const float4*)(vb + (long long)gj * (3 * D_) + c4);
        }
        __syncthreads();

        // S = Q @ K^T  (warp: 16 rows x 128 cols)
        float sf[16][4];
#pragma unroll
        for (int nf = 0; nf < 16; nf++)
#pragma unroll
            for (int r = 0; r < 4; r++) sf[nf][r] = 0.f;
        const uint32_t* sku = (const uint32_t*)Sk;
#pragma unroll
        for (int ks = 0; ks < 8; ks++) {
#pragma unroll
            for (int nf = 0; nf < 16; nf++) {
                uint32_t b0 = sku[(nf * 8 + grp) * KSTR + tig + 8 * ks];
                uint32_t b1 = sku[(nf * 8 + grp) * KSTR + tig + 4 + 8 * ks];
                mma8(sf[nf], qf[ks], b0, b1);
            }
        }

        // scale + mask + chunk max
        float cm0 = -1e30f, cm1 = -1e30f;
#pragma unroll
        for (int nf = 0; nf < 16; nf++) {
            int j = j0 + nf * 8 + 2 * tig;
            float x0 = sf[nf][0] * SCALE_, x1 = sf[nf][1] * SCALE_;
            float x2 = sf[nf][2] * SCALE_, x3 = sf[nf][3] * SCALE_;
            if (j >= T_)     { x0 = -1e30f; x2 = -1e30f; }
            if (j + 1 >= T_) { x1 = -1e30f; x3 = -1e30f; }
            sf[nf][0] = x0; sf[nf][1] = x1; sf[nf][2] = x2; sf[nf][3] = x3;
            cm0 = fmaxf(cm0, fmaxf(x0, x1));
            cm1 = fmaxf(cm1, fmaxf(x2, x3));
        }
#pragma unroll
        for (int o = 1; o <= 2; o <<= 1) {
            cm0 = fmaxf(cm0, __shfl_xor_sync(0xffffffffu, cm0, o));
            cm1 = fmaxf(cm1, __shfl_xor_sync(0xffffffffu, cm1, o));
        }
        float nm0 = fmaxf(m0, cm0), nm1 = fmaxf(m1, cm1);
        float f0 = __expf(m0 - nm0), f1 = __expf(m1 - nm1);
        m0 = nm0; m1 = nm1;
        s1a *= f0; s2a *= f0; s1b *= f1; s2b *= f1;
#pragma unroll
        for (int nf = 0; nf < 8; nf++) {
            of[nf][0] *= f0; of[nf][1] *= f0;
            of[nf][2] *= f1; of[nf][3] *= f1;
        }

        // exp, gate, partial sums, write P (warp-private rows of Sp)
        float ls1a = 0.f, ls1b = 0.f, ls2a = 0.f, ls2b = 0.f;
        int r = w * 16 + grp;
#pragma unroll
        for (int nf = 0; nf < 16; nf++) {
            int j = j0 + nf * 8 + 2 * tig;
            float p0 = __expf(sf[nf][0] - m0), p1 = __expf(sf[nf][1] - m0);
            float p2 = __expf(sf[nf][2] - m1), p3 = __expf(sf[nf][3] - m1);
            float g0 = 0.5f, g1 = 0.5f, g2 = 0.5f, g3 = 0.5f;
            if (j < N_) {   // pairs are even-aligned; j < N_ implies j+1 < N_
                if (row0 < N_) { float2 gg = *(const float2*)(gb + (long long)row0 * N_ + j); g0 = gg.x; g1 = gg.y; }
                if (row1 < N_) { float2 gg = *(const float2*)(gb + (long long)row1 * N_ + j); g2 = gg.x; g3 = gg.y; }
            }
            ls1a += p0 + p1; ls1b += p2 + p3;
            float q0 = p0 * g0, q1 = p1 * g1, q2 = p2 * g2, q3 = p3 * g3;
            ls2a += q0 + q1; ls2b += q2 + q3;
            *(float2*)(Sp + r * QSTR + nf * 8 + 2 * tig) = make_float2(q0, q1);
            *(float2*)(Sp + (r + 8) * QSTR + nf * 8 + 2 * tig) = make_float2(q2, q3);
        }
#pragma unroll
        for (int o = 1; o <= 2; o <<= 1) {
            ls1a += __shfl_xor_sync(0xffffffffu, ls1a, o);
            ls1b += __shfl_xor_sync(0xffffffffu, ls1b, o);
            ls2a += __shfl_xor_sync(0xffffffffu, ls2a, o);
            ls2b += __shfl_xor_sync(0xffffffffu, ls2b, o);
        }
        s1a += ls1a; s1b += ls1b; s2a += ls2a; s2b += ls2b;

        // O += P @ V  (P rows warp-private -> only warp-level ordering needed)
        __syncwarp();
        const uint32_t* spu = (const uint32_t*)Sp;
        const uint32_t* svu = (const uint32_t*)Sv;
#pragma unroll
        for (int ks = 0; ks < 16; ks++) {
            uint32_t a[4];
            a[0] = spu[r * QSTR + tig + 8 * ks];
            a[1] = spu[(r + 8) * QSTR + tig + 8 * ks];
            a[2] = spu[r * QSTR + tig + 4 + 8 * ks];
            a[3] = spu[(r + 8) * QSTR + tig + 4 + 8 * ks];
#pragma unroll
            for (int nf = 0; nf < 8; nf++) {
                uint32_t b0 = svu[(tig + 8 * ks) * KSTR + nf * 8 + grp];
                uint32_t b1 = svu[(tig + 4 + 8 * ks) * KSTR + nf * 8 + grp];
                mma8(of[nf], a, b0, b1);
            }
        }
    }

    // epilogue
    float d0 = 1.f / (s2a + 1e-6f * s1a);
    float d1 = 1.f / (s2b + 1e-6f * s1b);
    float* cb = ctx + (long long)b * T_ * D_ + h * E_;
#pragma unroll
    for (int nf = 0; nf < 8; nf++) {
        int col = nf * 8 + 2 * tig;
        if (row0 < T_)
            *(float2*)(cb + (long long)row0 * D_ + col) =
                make_float2(rnd_tf(of[nf][0] * d0), rnd_tf(of[nf][1] * d0));
        if (row1 < T_)
            *(float2*)(cb + (long long)row1 * D_ + col) =
                make_float2(rnd_tf(of[nf][2] * d1), rnd_tf(of[nf][3] * d1));
    }
}

// ---------------- batched tiled transpose (rounds output to tf32) ----------------
__global__ void transpose_k(const float* __restrict__ S, float* __restrict__ Dst,
                            int R, int C, int lds, int ldd, int nb2,
                            long long sSb, long long sSh, long long sDb, long long sDh) {
    __shared__ float t[32][33];
    int z = blockIdx.z, zb = z / nb2, zh = z % nb2;
    S += zb * sSb + zh * sSh;
    Dst += zb * sDb + zh * sDh;
    int r0 = blockIdx.y * 32, c0 = blockIdx.x * 32;
    int c = c0 + threadIdx.x;
#pragma unroll
    for (int i = 0; i < 32; i += 8) {
        int r = r0 + threadIdx.y + i;
        if (r < R && c < C) t[threadIdx.y + i][threadIdx.x] = S[(long long)r * lds + c];
    }
    __syncthreads();
    int cc2 = r0 + threadIdx.x;
#pragma unroll
    for (int i = 0; i < 32; i += 8) {
        int rr2 = c0 + threadIdx.y + i;
        if (rr2 < C && cc2 < R) Dst[(long long)rr2 * ldd + cc2] = rnd_tf(t[threadIdx.x][threadIdx.y + i]);
    }
}

// ---------------- reductions ----------------
__device__ __forceinline__ float block_sum(float v, float* sh) {
    int lane = threadIdx.x & 31, w = threadIdx.x >> 5;
#pragma unroll
    for (int o = 16; o; o >>= 1) v += __shfl_xor_sync(0xffffffffu, v, o);
    if (lane == 0) sh[w] = v;
    __syncthreads();
    if (threadIdx.x == 0) {
        float t = 0.f; int nw = blockDim.x >> 5;
        for (int i = 0; i < nw; i++) t += sh[i];
        sh[32] = t;
    }
    __syncthreads();
    float r = sh[32];
    __syncthreads();
    return r;
}

// ---------------- small fused kernels ----------------
__global__ void revin_k(const float* __restrict__ x, const float* __restrict__ gamma,
                        const float* __restrict__ beta, float* __restrict__ tok,
                        float* __restrict__ meanO, float* __restrict__ stdO) {
    int idx = blockIdx.x * blockDim.x + threadIdx.x;
    if (idx >= B_ * N_) return;
    int b = idx / N_, n = idx % N_;
    const float* xp = x + (long long)b * L_ * N_ + n;
    float s = 0.f, s2 = 0.f;
#pragma unroll 4
    for (int l = 0; l < L_; l++) { float v = xp[(long long)l * N_]; s += v; s2 += v * v; }
    float mean = s / L_;
    float var = fmaxf(s2 / L_ - mean * mean, 0.f);
    float sd = sqrtf(var + 1e-5f);
    meanO[idx] = mean; stdO[idx] = sd;
    float g = gamma[n], be = beta[n], inv = 1.f / sd;
    float* tp = tok + ((long long)b * T_ + n) * L_;
#pragma unroll 4
    for (int l = 0; l < L_; l++) tp[l] = rnd_tf((xp[(long long)l * N_] - mean) * inv * g + be);
}

__global__ void marks_k(const float* __restrict__ xm, float* __restrict__ tok) {
    int idx = blockIdx.x * blockDim.x + threadIdx.x;
    if (idx >= B_ * NMARK_ * L_) return;
    int l = idx % L_, m = (idx / L_) % NMARK_, b = idx / (L_ * NMARK_);
    tok[((long long)b * T_ + N_ + m) * L_ + l] = rnd_tf(xm[((long long)b * L_ + l) * NMARK_ + m]);
}

__global__ void trend_k(const float* __restrict__ tok,
                        const float* __restrict__ w1, const float* __restrict__ b1,
                        const float* __restrict__ w2, const float* __restrict__ b2,
                        float* __restrict__ nt) {
    int idx = blockIdx.x * blockDim.x + threadIdx.x;
    if (idx >= B_ * N_) return;
    int b = idx / N_, n = idx % N_;
    const float* xp = tok + ((long long)b * T_ + n) * L_;
    float cum[L_ + 1];
    cum[0] = 0.f;
    float s = 0.f, s2 = 0.f;
    for (int l = 0; l < L_; l++) {
        float v = xp[l];
        cum[l + 1] = cum[l] + v;
        s += v; s2 += v * v;
    }
    float mean = s / L_;
    float var = fmaxf(s2 / L_ - mean * mean, 0.f);
    float sd = sqrtf(var + 1e-6f);
    float logits[4] = {b2[0], b2[1], b2[2], b2[3]};
#pragma unroll
    for (int j = 0; j < 16; j++) {
        float h = fmaxf(mean * w1[j] + sd * w1[16 + j] + b1[j], 0.f);
#pragma unroll
        for (int w = 0; w < 4; w++) logits[w] += h * w2[j * 4 + w];
    }
    float mx = fmaxf(fmaxf(logits[0], logits[1]), fmaxf(logits[2], logits[3]));
    float wt[4], ws = 0.f;
#pragma unroll
    for (int w = 0; w < 4; w++) { wt[w] = expf(logits[w] - mx); ws += wt[w]; }
#pragma unroll
    for (int w = 0; w < 4; w++) wt[w] /= ws;
    const int W[4] = {4, 8, 12, 24};
    float x0 = xp[0];
    float t[L_];
    float nrm2 = 0.f;
    for (int l = 0; l < L_; l++) {
        float tv = 0.f;
#pragma unroll
        for (int wi = 0; wi < 4; wi++) {
            int w = W[wi], lo = l - w + 1;
            float sum = (lo < 0) ? (cum[l + 1] + (float)(-lo) * x0) : (cum[l + 1] - cum[lo]);
            tv += wt[wi] * sum / (float)w;
        }
        t[l] = tv; nrm2 += tv * tv;
    }
    float inv = 1.f / fmaxf(sqrtf(nrm2), 1e-12f);
    float* np = nt + ((long long)b * N_ + n) * L_;
    for (int l = 0; l < L_; l++) np[l] = rnd_tf(t[l] * inv);
}

__global__ void sigmoid_k(float* __restrict__ g, int n) {
    int idx = blockIdx.x * blockDim.x + threadIdx.x;
    if (idx < n) g[idx] = 1.f / (1.f + expf(-g[idx]));
}

__global__ void biascat_k(const float* __restrict__ bq, const float* __restrict__ bk,
                          const float* __restrict__ bv, float* __restrict__ o) {
    int i = blockIdx.x * blockDim.x + threadIdx.x;
    if (i >= LAYERS_ * 3 * D_) return;
    int l = i / (3 * D_), j = i % (3 * D_);
    float v = (j < D_) ? bq[l * D_ + j] : (j < 2 * D_) ? bk[l * D_ + j - D_] : bv[l * D_ + j - 2 * D_];
    o[i] = v;
}

template <bool RES>
__global__ void ln_k(const float* __restrict__ X, const float* __restrict__ Y,
                     const float* __restrict__ g, const float* __restrict__ be,
                     float* __restrict__ out) {
    __shared__ float sh[33];
    long long r = blockIdx.x;
    const float* x = X + r * D_;
    const float* y = RES ? (Y + r * D_) : nullptr;
    float v[4];
    float s = 0.f;
#pragma unroll
    for (int i = 0; i < 4; i++) {
        int c = threadIdx.x + i * 128;
        v[i] = x[c] + (RES ? y[c] : 0.f);
        s += v[i];
    }
    s = block_sum(s, sh);
    float mean = s / D_;
    float s2 = 0.f;
#pragma unroll
    for (int i = 0; i < 4; i++) { float d = v[i] - mean; s2 += d * d; }
    s2 = block_sum(s2, sh);
    float rstd = rsqrtf(s2 / D_ + 1e-5f);
    float* o = out + r * D_;
#pragma unroll
    for (int i = 0; i < 4; i++) {
        int c = threadIdx.x + i * 128;
        o[c] = rnd_tf((v[i] - mean) * rstd * g[c] + be[c]);
    }
}

__global__ void out_k(const float* __restrict__ proj, const float* __restrict__ meanI,
                      const float* __restrict__ stdI, const float* __restrict__ gamma,
                      const float* __restrict__ beta, float* __restrict__ out) {
    int idx = blockIdx.x * blockDim.x + threadIdx.x;
    if (idx >= B_ * PRED_ * N_) return;
    int n = idx % N_, p = (idx / N_) % PRED_, b = idx / (N_ * PRED_);
    float v = proj[((long long)b * T_ + n) * PRED_ + p];
    v = (v - beta[n]) / (gamma[n] + 1e-5f) * stdI[b * N_ + n] + meanI[b * N_ + n];
    out[idx] = v;
}

// ---------------- host orchestration ----------------
static inline dim3 tgrid(int M, int Nn, int BN, int batch) {
    return dim3((Nn + BN - 1) / BN, (M + 127) / 128, batch);
}
#define SMEMB(BNt) (3 * (128 * SSTRIDE + (BNt) * SSTRIDE) * 4)

extern "C" void kernel_launch(void* const* d_in, const int* in_sizes, int n_in,
                              void* d_out, int out_size) {
    const float* x_enc  = (const float*)d_in[0];
    const float* x_mark = (const float*)d_in[1];
    const float* gamma  = (const float*)d_in[4];
    const float* beta   = (const float*)d_in[5];
    const float* tp_w1  = (const float*)d_in[6];
    const float* tp_b1  = (const float*)d_in[7];
    const float* tp_w2  = (const float*)d_in[8];
    const float* tp_b2  = (const float*)d_in[9];
    const float* emb_w  = (const float*)d_in[10];
    const float* emb_b  = (const float*)d_in[11];
    const float* wq = (const float*)d_in[12];
    const float* bq = (const float*)d_in[13];
    const float* wk = (const float*)d_in[14];
    const float* bk = (const float*)d_in[15];
    const float* wv = (const float*)d_in[16];
    const float* bv = (const float*)d_in[17];
    const float* wo = (const float*)d_in[18];
    const float* bo = (const float*)d_in[19];
    const float* w1 = (const float*)d_in[20];
    const float* b1 = (const float*)d_in[21];
    const float* w2 = (const float*)d_in[22];
    const float* b2 = (const float*)d_in[23];
    const float* ln1g = (const float*)d_in[24];
    const float* ln1b = (const float*)d_in[25];
    const float* ln2g = (const float*)d_in[26];
    const float* ln2b = (const float*)d_in[27];
    const float* normg = (const float*)d_in[28];
    const float* normb = (const float*)d_in[29];
    const float* proj_w = (const float*)d_in[30];
    const float* proj_b = (const float*)d_in[31];
    float* out = (float*)d_out;

    float *p_mean, *p_std, *p_tok, *p_nt, *p_guide, *p_x, *p_tmp, *p_ctx, *p_qkv,
          *p_ffn, *p_wqkvt, *p_bqkv, *p_wot, *p_w1t, *p_w2t, *p_embt, *p_projt;
    cudaGetSymbolAddress((void**)&p_mean, g_mean);
    cudaGetSymbolAddress((void**)&p_std, g_std);
    cudaGetSymbolAddress((void**)&p_tok, g_tok);
    cudaGetSymbolAddress((void**)&p_nt, g_nt);
    cudaGetSymbolAddress((void**)&p_guide, g_guide);
    cudaGetSymbolAddress((void**)&p_x, g_x);
    cudaGetSymbolAddress((void**)&p_tmp, g_tmp);
    cudaGetSymbolAddress((void**)&p_ctx, g_ctx);
    cudaGetSymbolAddress((void**)&p_qkv, g_qkv);
    cudaGetSymbolAddress((void**)&p_ffn, g_ffn);
    cudaGetSymbolAddress((void**)&p_wqkvt, g_wqkvt);
    cudaGetSymbolAddress((void**)&p_bqkv, g_bqkv);
    cudaGetSymbolAddress((void**)&p_wot, g_wot);
    cudaGetSymbolAddress((void**)&p_w1t, g_w1t);
    cudaGetSymbolAddress((void**)&p_w2t, g_w2t);
    cudaGetSymbolAddress((void**)&p_embt, g_embt);
    cudaGetSymbolAddress((void**)&p_projt, g_projt);

    cudaFuncSetAttribute(mmak<0, 128, true>,  cudaFuncAttributeMaxDynamicSharedMemorySize, SMEMB(128));
    cudaFuncSetAttribute(mmak<1, 128, true>,  cudaFuncAttributeMaxDynamicSharedMemorySize, SMEMB(128));
    cudaFuncSetAttribute(mmak<1, 128, false>, cudaFuncAttributeMaxDynamicSharedMemorySize, SMEMB(128));
    cudaFuncSetAttribute(mmak<2, 128, true>,  cudaFuncAttributeMaxDynamicSharedMemorySize, SMEMB(128));
    cudaFuncSetAttribute(mmak<3, 128, true>,  cudaFuncAttributeMaxDynamicSharedMemorySize, SMEMB(128));
    cudaFuncSetAttribute(flash_k, cudaFuncAttributeMaxDynamicSharedMemorySize, FSMEM);

    dim3 tb(32, 8);

    revin_k<<<(B_ * N_ + 255) / 256, 256>>>(x_enc, gamma, beta, p_tok, p_mean, p_std);
    marks_k<<<(B_ * NMARK_ * L_ + 255) / 256, 256>>>(x_mark, p_tok);
    trend_k<<<(B_ * N_ + 255) / 256, 256>>>(p_tok, tp_w1, tp_b1, tp_w2, tp_b2, p_nt);
    transpose_k<<<dim3(16, 3, 1), tb>>>(emb_w, p_embt, L_, D_, D_, L_, 1, 0, 0, 0, 0);

    // Gram: guide[b] = nt[b] @ nt[b]^T (raw logits), then sigmoid in place
    mmak<0, 128, true><<<tgrid(N_, N_, 128, B_), 256, SMEMB(128)>>>(
        p_nt, p_nt, nullptr, nullptr, p_guide, N_, N_, L_, L_, L_, N_, 1,
        (long long)N_ * L_, 0, (long long)N_ * L_, 0, (long long)N_ * N_, 0);
    // embedding: x = tok @ emb_w + emb_b
    mmak<1, 128, true><<<tgrid(BT_, D_, 128, 1), 256, SMEMB(128)>>>(
        p_tok, p_embt, emb_b, nullptr, p_x, BT_, D_, L_, L_, L_, D_, 1, 0, 0, 0, 0, 0, 0);
    sigmoid_k<<<(B_ * N_ * N_ + 255) / 256, 256>>>(p_guide, B_ * N_ * N_);

    // weight transposes -> K-major; QKV concatenated [1536, 512] per layer
    transpose_k<<<dim3(16, 16, 2), tb>>>(wq, p_wqkvt, 512, 512, 512, 512, 1,
                                         512 * 512, 0, (long long)3 * 512 * 512, 0);
    transpose_k<<<dim3(16, 16, 2), tb>>>(wk, p_wqkvt + 512 * 512, 512, 512, 512, 512, 1,
                                         512 * 512, 0, (long long)3 * 512 * 512, 0);
    transpose_k<<<dim3(16, 16, 2), tb>>>(wv, p_wqkvt + 2 * 512 * 512, 512, 512, 512, 512, 1,
                                         512 * 512, 0, (long long)3 * 512 * 512, 0);
    biascat_k<<<(LAYERS_ * 3 * D_ + 255) / 256, 256>>>(bq, bk, bv, p_bqkv);
    transpose_k<<<dim3(16, 16, 2), tb>>>(wo, p_wot, 512, 512, 512, 512, 1, 512 * 512, 0, 512 * 512, 0);
    transpose_k<<<dim3(64, 16, 2), tb>>>(w1, p_w1t, 512, 2048, 2048, 512, 1,
                                         (long long)512 * 2048, 0, (long long)512 * 2048, 0);
    transpose_k<<<dim3(16, 64, 2), tb>>>(w2, p_w2t, 2048, 512, 512, 2048, 1,
                                         (long long)512 * 2048, 0, (long long)512 * 2048, 0);
    transpose_k<<<dim3(3, 16, 1), tb>>>(proj_w, p_projt, D_, PRED_, PRED_, D_, 1, 0, 0, 0, 0);

    for (int i = 0; i < LAYERS_; i++) {
        const float* wqkvt_i = p_wqkvt + (long long)i * 3 * D_ * D_;
        const float* wot_i = p_wot + (long long)i * D_ * D_;
        const float* w1t_i = p_w1t + (long long)i * D_ * DFF_;
        const float* w2t_i = p_w2t + (long long)i * DFF_ * D_;

        // fused QKV: [BT, 1536]
        mmak<1, 128, true><<<tgrid(BT_, 3 * D_, 128, 1), 256, SMEMB(128)>>>(
            p_x, wqkvt_i, p_bqkv + i * 3 * D_, nullptr, p_qkv,
            BT_, 3 * D_, D_, D_, D_, 3 * D_, 1, 0, 0, 0, 0, 0, 0);

        // fused gated flash attention -> p_ctx
        flash_k<<<dim3(5, B_ * H_), 256, FSMEM>>>(p_qkv, p_guide, p_ctx);

        // x_attn = x + ctx @ wo + bo
        mmak<3, 128, true><<<tgrid(BT_, D_, 128, 1), 256, SMEMB(128)>>>(
            p_ctx, wot_i, bo + i * D_, p_x, p_tmp, BT_, D_, D_, D_, D_, D_, 1, 0, 0, 0, 0, 0, 0);

        ln_k<false><<<BT_, 128>>>(p_tmp, nullptr, ln1g + i * D_, ln1b + i * D_, p_tmp);

        mmak<2, 128, true><<<tgrid(BT_, DFF_, 128, 1), 256, SMEMB(128)>>>(
            p_tmp, w1t_i, b1 + i * DFF_, nullptr, p_ffn, BT_, DFF_, D_, D_, D_, DFF_, 1, 0, 0, 0, 0, 0, 0);
        mmak<1, 128, true><<<tgrid(BT_, D_, 128, 1), 256, SMEMB(128)>>>(
            p_ffn, w2t_i, b2 + i * D_, nullptr, p_ctx, BT_, D_, DFF_, DFF_, DFF_, D_, 1, 0, 0, 0, 0, 0, 0);

        ln_k<true><<<BT_, 128>>>(p_tmp, p_ctx, ln2g + i * D_, ln2b + i * D_, p_x);
    }

    ln_k<false><<<BT_, 128>>>(p_x, nullptr, normg, normb, p_tmp);

    // projection -> p_qkv scratch (not a GEMM input; no rounding)
    mmak<1, 128, false><<<tgrid(BT_, PRED_, 128, 1), 256, SMEMB(128)>>>(
        p_tmp, p_projt, proj_b, nullptr, p_qkv, BT_, PRED_, D_, D_, D_, PRED_, 1, 0, 0, 0, 0, 0, 0);

    out_k<<<(B_ * PRED_ * N_ + 255) / 256, 256>>>(p_qkv, p_mean, p_std, gamma, beta, out);
}

// round 11
// speedup vs baseline: 3.5425x; 1.0421x over previous
#include <cuda_runtime.h>
#include <cuda_bf16.h>
#include <cstdint>
#include <math.h>

// ---------------- problem constants ----------------
#define B_ 16
#define L_ 96
#define N_ 512
#define D_ 512
#define H_ 8
#define E_ 64
#define DFF_ 2048
#define T_ 516            // N_ + NMARK
#define PRED_ 96
#define NMARK_ 4
#define LAYERS_ 2
#define BT_ (B_ * T_)     // 8256
#define SCALE_ 0.125f     // 1/sqrt(E)

// ---------------- scratch (device globals; no allocation allowed) ----------------
__device__ float g_mean[B_ * N_];
__device__ float g_std[B_ * N_];
__device__ float g_tok[B_ * T_ * L_];
__device__ float g_nt[B_ * N_ * L_];
__device__ float g_guide[B_ * N_ * N_];
__device__ float g_x[BT_ * D_];
__device__ float g_tmp[BT_ * D_];
__device__ float g_ctx[BT_ * D_];
__device__ float g_qkv[(long long)BT_ * 3 * D_];
__device__ float g_ffn[(long long)BT_ * DFF_];
__device__ float g_wqkvt[(long long)LAYERS_ * 3 * D_ * D_];
__device__ float g_bqkv[LAYERS_ * 3 * D_];
__device__ float g_wot[LAYERS_ * D_ * D_];
__device__ float g_w1t[(long long)LAYERS_ * D_ * DFF_];
__device__ float g_w2t[(long long)LAYERS_ * DFF_ * D_];
__device__ float g_embt[D_ * L_];
__device__ float g_projt[PRED_ * D_];

// ---------------- mma / async-copy helpers ----------------
__device__ __forceinline__ uint32_t f2tf(float v) {
    uint32_t t;
    asm("cvt.rna.tf32.f32 %0, %1;" : "=r"(t) : "f"(v));
    return t;
}
__device__ __forceinline__ float rnd_tf(float v) {
    return __uint_as_float(f2tf(v));
}
__device__ __forceinline__ void mma8(float* c, const uint32_t* a, uint32_t b0, uint32_t b1) {
    asm volatile(
        "mma.sync.aligned.m16n8k8.row.col.f32.tf32.tf32.f32 "
        "{%0,%1,%2,%3}, {%4,%5,%6,%7}, {%8,%9}, {%0,%1,%2,%3};"
        : "+f"(c[0]), "+f"(c[1]), "+f"(c[2]), "+f"(c[3])
        : "r"(a[0]), "r"(a[1]), "r"(a[2]), "r"(a[3]), "r"(b0), "r"(b1));
}
__device__ __forceinline__ void ldsm4(uint32_t* r, uint32_t addr) {
    asm volatile("ldmatrix.sync.aligned.m8n8.x4.shared.b16 {%0,%1,%2,%3}, [%4];"
        : "=r"(r[0]), "=r"(r[1]), "=r"(r[2]), "=r"(r[3]) : "r"(addr));
}
__device__ __forceinline__ float geluf(float x) {
    return 0.5f * x * (1.0f + erff(x * 0.70710678118654752f));
}
__device__ __forceinline__ uint32_t smem_u32(const void* p) {
    uint32_t a;
    asm("{ .reg .u64 t; cvta.to.shared.u64 t, %1; cvt.u32.u64 %0, t; }" : "=r"(a) : "l"(p));
    return a;
}
__device__ __forceinline__ void cp16_full(uint32_t dst, const void* src) {
    asm volatile("cp.async.cg.shared.global [%0], [%1], 16;" :: "r"(dst), "l"(src) : "memory");
}
__device__ __forceinline__ void cp16_pred(uint32_t dst, const void* src, int nbytes) {
    asm volatile("cp.async.cg.shared.global [%0], [%1], 16, %2;" :: "r"(dst), "l"(src), "r"(nbytes) : "memory");
}
#define CP_COMMIT() asm volatile("cp.async.commit_group;" ::: "memory")
template <int Nw>
__device__ __forceinline__ void cp_wait() {
    asm volatile("cp.async.wait_group %0;" :: "n"(Nw) : "memory");
}

// ---------------- tf32 tensor-core GEMM: C[M,N] = A[M,K] @ B[N,K]^T (+epi) ----------------
// EPI: 0 none, 1 +bias, 2 +bias+gelu, 3 +bias+residual.  Operands pre-rounded to tf32.
// Fragment loads via ldmatrix (8x4 32-bit subtiles; stride 20 floats is conflict-free).
#define SSTRIDE 20

template <int EPI, int BNt, bool ROUND>
__global__ void __launch_bounds__(256)
mmak(const float* __restrict__ A, const float* __restrict__ Bm,
     const float* __restrict__ bias, const float* __restrict__ Res,
     float* __restrict__ C,
     int M, int Nn, int K, int lda, int ldb, int ldc, int nbH,
     long long sAb, long long sAh, long long sBb, long long sBh,
     long long sCb, long long sCh) {
    constexpr int WN = BNt / 4;
    constexpr int NI = WN / 8;
    constexpr int NP = NI / 2;
    constexpr int BQ = (BNt * 4) / 256;
    constexpr int AE = 128 * SSTRIDE;
    constexpr int BE = BNt * SSTRIDE;
    constexpr int STG = AE + BE;

    extern __shared__ char smem_raw[];
    const uint32_t sbase = smem_u32(smem_raw);

    int tid = threadIdx.x;
    int z = blockIdx.z, zb = z / nbH, zh = z % nbH;
    A  += zb * sAb + zh * sAh;
    Bm += zb * sBb + zh * sBh;
    C  += zb * sCb + zh * sCh;
    int m0 = blockIdx.y * 128, n0 = blockIdx.x * BNt;

    int lane = tid & 31, wid = tid >> 5;
    int wm = (wid & 1) * 64;
    int wn = (wid >> 1) * WN;
    int grp = lane >> 2, tig = lane & 3;

    // ldmatrix per-lane row offsets
    int ls = lane >> 3, r8 = lane & 7;
    uint32_t offA[4];
#pragma unroll
    for (int mi = 0; mi < 4; mi++) {
        int row = wm + mi * 16 + (ls & 1) * 8 + r8;
        int col = (ls >> 1) * 4;
        offA[mi] = (uint32_t)(row * SSTRIDE + col) * 4u;
    }
    uint32_t offB[NP];
#pragma unroll
    for (int pi = 0; pi < NP; pi++) {
        int row = wn + (2 * pi + (ls >> 1)) * 8 + r8;
        int col = (ls & 1) * 4;
        offB[pi] = (uint32_t)(row * SSTRIDE + col) * 4u;
    }

    float acc[4][NI][4];
#pragma unroll
    for (int mi = 0; mi < 4; mi++)
#pragma unroll
        for (int ni = 0; ni < NI; ni++)
#pragma unroll
            for (int r = 0; r < 4; r++) acc[mi][ni][r] = 0.f;

    const int NC = (K + 15) >> 4;
    const bool full = (m0 + 128 <= M) && (n0 + BNt <= Nn) && ((K & 15) == 0);
    const int a_row0 = tid >> 2, a_c4 = (tid & 3) << 2;

    auto issue = [&](int c, int st) {
        int k0 = c * 16;
        uint32_t abase = sbase + (uint32_t)(st * STG) * 4u;
        uint32_t bbase = abase + (uint32_t)AE * 4u;
        if (full) {
#pragma unroll
            for (int u = 0; u < 2; u++) {
                int row = a_row0 + u * 64;
                cp16_full(abase + (uint32_t)(row * SSTRIDE + a_c4) * 4u,
                          A + (long long)(m0 + row) * lda + k0 + a_c4);
            }
#pragma unroll
            for (int u = 0; u < BQ; u++) {
                int row = a_row0 + u * 64;
                cp16_full(bbase + (uint32_t)(row * SSTRIDE + a_c4) * 4u,
                          Bm + (long long)(n0 + row) * ldb + k0 + a_c4);
            }
        } else {
#pragma unroll
            for (int u = 0; u < 2; u++) {
                int row = a_row0 + u * 64;
                int gm = m0 + row, gk = k0 + a_c4;
                int nb = 0;
                if (gm < M) { int rem = K - gk; nb = rem >= 4 ? 16 : (rem > 0 ? rem * 4 : 0); }
                const float* src = (nb > 0) ? (A + (long long)gm * lda + gk) : A;
                cp16_pred(abase + (uint32_t)(row * SSTRIDE + a_c4) * 4u, src, nb);
            }
#pragma unroll
            for (int u = 0; u < BQ; u++) {
                int row = a_row0 + u * 64;
                int gn = n0 + row, gk = k0 + a_c4;
                int nb = 0;
                if (gn < Nn) { int rem = K - gk; nb = rem >= 4 ? 16 : (rem > 0 ? rem * 4 : 0); }
                const float* src = (nb > 0) ? (Bm + (long long)gn * ldb + gk) : Bm;
                cp16_pred(bbase + (uint32_t)(row * SSTRIDE + a_c4) * 4u, src, nb);
            }
        }
    };

    int pre = NC < 2 ? NC : 2;
    for (int s = 0; s < pre; s++) { issue(s, s); CP_COMMIT(); }

    for (int c = 0; c < NC; c++) {
        if (c + 1 < NC) cp_wait<1>(); else cp_wait<0>();
        __syncthreads();
        if (c + 2 < NC) { issue(c + 2, (c + 2) % 3); CP_COMMIT(); }

        uint32_t aB = sbase + (uint32_t)((c % 3) * STG) * 4u;
        uint32_t bB = aB + (uint32_t)AE * 4u;
#pragma unroll
        for (int kk = 0; kk < 2; kk++) {
            uint32_t kof = (uint32_t)kk * 32u;
            uint32_t af[4][4];
#pragma unroll
            for (int mi = 0; mi < 4; mi++) ldsm4(af[mi], aB + offA[mi] + kof);
#pragma unroll
            for (int pi = 0; pi < NP; pi++) {
                uint32_t bb[4];
                ldsm4(bb, bB + offB[pi] + kof);
#pragma unroll
                for (int mi = 0; mi < 4; mi++) {
                    mma8(acc[mi][2 * pi],     af[mi], bb[0], bb[1]);
                    mma8(acc[mi][2 * pi + 1], af[mi], bb[2], bb[3]);
                }
            }
        }
    }

#pragma unroll
    for (int mi = 0; mi < 4; mi++) {
#pragma unroll
        for (int ni = 0; ni < NI; ni++) {
            int col = n0 + wn + ni * 8 + 2 * tig;
            if (col >= Nn) continue;
            float bv0 = 0.f, bv1 = 0.f;
            if (EPI >= 1) { bv0 = bias[col]; bv1 = bias[col + 1]; }
#pragma unroll
            for (int h = 0; h < 2; h++) {
                int gm = m0 + wm + mi * 16 + grp + h * 8;
                if (gm >= M) continue;
                float v0 = acc[mi][ni][h * 2 + 0] + bv0;
                float v1 = acc[mi][ni][h * 2 + 1] + bv1;
                if (EPI == 2) { v0 = geluf(v0); v1 = geluf(v1); }
                if (EPI == 3) {
                    const float* rp = Res + (long long)gm * ldc + col;
                    v0 += rp[0]; v1 += rp[1];
                }
                if (ROUND) { v0 = rnd_tf(v0); v1 = rnd_tf(v1); }
                *(float2*)(C + (long long)gm * ldc + col) = make_float2(v0, v1);
            }
        }
    }
}

// ---------------- fused gated flash attention ----------------
#define QSTR 132
#define KSTR 68
#define FSMEM ((128 * QSTR + 2 * 128 * KSTR) * 4)

__global__ void __launch_bounds__(256)
flash_k(const float* __restrict__ qkv, const float* __restrict__ gate,
        float* __restrict__ ctx) {
    extern __shared__ char sm[];
    float* Sp = (float*)sm;                 // [128][QSTR]  Q staging, then P
    float* Sk = Sp + 128 * QSTR;            // [128][KSTR]
    float* Sv = Sk + 128 * KSTR;            // [128][KSTR]

    int qt = blockIdx.x;
    int bh = blockIdx.y;
    int b = bh >> 3, h = bh & 7;
    int i0 = qt * 128;
    int tid = threadIdx.x, lane = tid & 31, w = tid >> 5;
    int grp = lane >> 2, tig = lane & 3;
    int ls = lane >> 3, r8 = lane & 7;

    const float* qb = qkv + (long long)b * T_ * (3 * D_) + h * E_;
    const float* kb = qb + D_;
    const float* vb = qb + 2 * D_;

    const uint32_t spB = smem_u32(Sp);
    const uint32_t skB = smem_u32(Sk);

    // ldmatrix offsets
    uint32_t offPA;  // A-frags from Sp (Q then P), rows w*16..
    {
        int row = w * 16 + (ls & 1) * 8 + r8;
        int col = (ls >> 1) * 4;
        offPA = (uint32_t)(row * QSTR + col) * 4u;
    }
    uint32_t offKB[8]; // B-frags from Sk, nf pairs
#pragma unroll
    for (int pf = 0; pf < 8; pf++) {
        int row = (2 * pf + (ls >> 1)) * 8 + r8;
        int col = (ls & 1) * 4;
        offKB[pf] = (uint32_t)(row * KSTR + col) * 4u;
    }

    // load Q tile (rows clamped) into Sp, extract fragments via ldmatrix
    for (int e = tid; e < 128 * 16; e += 256) {
        int r = e >> 4, c4 = (e & 15) << 2;
        int gi = i0 + r; if (gi >= T_) gi = T_ - 1;
        *(float4*)(Sp + r * QSTR + c4) = *(const float4*)(qb + (long long)gi * (3 * D_) + c4);
    }
    __syncthreads();
    uint32_t qf[8][4];
#pragma unroll
    for (int ks = 0; ks < 8; ks++) ldsm4(qf[ks], spB + offPA + (uint32_t)ks * 32u);

    float of[8][4];
#pragma unroll
    for (int nf = 0; nf < 8; nf++)
#pragma unroll
        for (int r = 0; r < 4; r++) of[nf][r] = 0.f;
    float m0 = -1e30f, m1 = -1e30f;
    float s1a = 0.f, s1b = 0.f, s2a = 0.f, s2b = 0.f;

    const float* gb = gate + (long long)b * N_ * N_;
    const int row0 = i0 + w * 16 + grp, row1 = row0 + 8;

    for (int j0 = 0; j0 < T_; j0 += 128) {
        __syncthreads();
        for (int e = tid; e < 128 * 16; e += 256) {
            int r = e >> 4, c4 = (e & 15) << 2;
            int gj = j0 + r; if (gj >= T_) gj = T_ - 1;
            *(float4*)(Sk + r * KSTR + c4) = *(const float4*)(kb + (long long)gj * (3 * D_) + c4);
            *(float4*)(Sv + r * KSTR + c4) = *(const float4*)(vb + (long long)gj * (3 * D_) + c4);
        }
        __syncthreads();

        // S = Q @ K^T
        float sf[16][4];
#pragma unroll
        for (int nf = 0; nf < 16; nf++)
#pragma unroll
            for (int r = 0; r < 4; r++) sf[nf][r] = 0.f;
#pragma unroll
        for (int ks = 0; ks < 8; ks++) {
#pragma unroll
            for (int pf = 0; pf < 8; pf++) {
                uint32_t bb[4];
                ldsm4(bb, skB + offKB[pf] + (uint32_t)ks * 32u);
                mma8(sf[2 * pf],     qf[ks], bb[0], bb[1]);
                mma8(sf[2 * pf + 1], qf[ks], bb[2], bb[3]);
            }
        }

        // scale + mask + chunk max
        float cm0 = -1e30f, cm1 = -1e30f;
#pragma unroll
        for (int nf = 0; nf < 16; nf++) {
            int j = j0 + nf * 8 + 2 * tig;
            float x0 = sf[nf][0] * SCALE_, x1 = sf[nf][1] * SCALE_;
            float x2 = sf[nf][2] * SCALE_, x3 = sf[nf][3] * SCALE_;
            if (j >= T_)     { x0 = -1e30f; x2 = -1e30f; }
            if (j + 1 >= T_) { x1 = -1e30f; x3 = -1e30f; }
            sf[nf][0] = x0; sf[nf][1] = x1; sf[nf][2] = x2; sf[nf][3] = x3;
            cm0 = fmaxf(cm0, fmaxf(x0, x1));
            cm1 = fmaxf(cm1, fmaxf(x2, x3));
        }
#pragma unroll
        for (int o = 1; o <= 2; o <<= 1) {
            cm0 = fmaxf(cm0, __shfl_xor_sync(0xffffffffu, cm0, o));
            cm1 = fmaxf(cm1, __shfl_xor_sync(0xffffffffu, cm1, o));
        }
        float nm0 = fmaxf(m0, cm0), nm1 = fmaxf(m1, cm1);
        float f0 = __expf(m0 - nm0), f1 = __expf(m1 - nm1);
        m0 = nm0; m1 = nm1;
        s1a *= f0; s2a *= f0; s1b *= f1; s2b *= f1;
#pragma unroll
        for (int nf = 0; nf < 8; nf++) {
            of[nf][0] *= f0; of[nf][1] *= f0;
            of[nf][2] *= f1; of[nf][3] *= f1;
        }

        // exp, gate, partial sums, write P (warp-private rows of Sp)
        float ls1a = 0.f, ls1b = 0.f, ls2a = 0.f, ls2b = 0.f;
        int r = w * 16 + grp;
#pragma unroll
        for (int nf = 0; nf < 16; nf++) {
            int j = j0 + nf * 8 + 2 * tig;
            float p0 = __expf(sf[nf][0] - m0), p1 = __expf(sf[nf][1] - m0);
            float p2 = __expf(sf[nf][2] - m1), p3 = __expf(sf[nf][3] - m1);
            float g0 = 0.5f, g1 = 0.5f, g2 = 0.5f, g3 = 0.5f;
            if (j < N_) {
                if (row0 < N_) { float2 gg = *(const float2*)(gb + (long long)row0 * N_ + j); g0 = gg.x; g1 = gg.y; }
                if (row1 < N_) { float2 gg = *(const float2*)(gb + (long long)row1 * N_ + j); g2 = gg.x; g3 = gg.y; }
            }
            ls1a += p0 + p1; ls1b += p2 + p3;
            float q0 = p0 * g0, q1 = p1 * g1, q2 = p2 * g2, q3 = p3 * g3;
            ls2a += q0 + q1; ls2b += q2 + q3;
            *(float2*)(Sp + r * QSTR + nf * 8 + 2 * tig) = make_float2(q0, q1);
            *(float2*)(Sp + (r + 8) * QSTR + nf * 8 + 2 * tig) = make_float2(q2, q3);
        }
#pragma unroll
        for (int o = 1; o <= 2; o <<= 1) {
            ls1a += __shfl_xor_sync(0xffffffffu, ls1a, o);
            ls1b += __shfl_xor_sync(0xffffffffu, ls1b, o);
            ls2a += __shfl_xor_sync(0xffffffffu, ls2a, o);
            ls2b += __shfl_xor_sync(0xffffffffu, ls2b, o);
        }
        s1a += ls1a; s1b += ls1b; s2a += ls2a; s2b += ls2b;

        // O += P @ V  (A-frags via ldmatrix; V frags transposed -> scalar LDS)
        __syncwarp();
        const uint32_t* svu = (const uint32_t*)Sv;
#pragma unroll
        for (int ks = 0; ks < 16; ks++) {
            uint32_t a[4];
            ldsm4(a, spB + offPA + (uint32_t)ks * 32u);
#pragma unroll
            for (int nf = 0; nf < 8; nf++) {
                uint32_t b0 = svu[(tig + 8 * ks) * KSTR + nf * 8 + grp];
                uint32_t b1 = svu[(tig + 4 + 8 * ks) * KSTR + nf * 8 + grp];
                mma8(of[nf], a, b0, b1);
            }
        }
    }

    // epilogue
    float d0 = 1.f / (s2a + 1e-6f * s1a);
    float d1 = 1.f / (s2b + 1e-6f * s1b);
    float* cb = ctx + (long long)b * T_ * D_ + h * E_;
#pragma unroll
    for (int nf = 0; nf < 8; nf++) {
        int col = nf * 8 + 2 * tig;
        if (row0 < T_)
            *(float2*)(cb + (long long)row0 * D_ + col) =
                make_float2(rnd_tf(of[nf][0] * d0), rnd_tf(of[nf][1] * d0));
        if (row1 < T_)
            *(float2*)(cb + (long long)row1 * D_ + col) =
                make_float2(rnd_tf(of[nf][2] * d1), rnd_tf(of[nf][3] * d1));
    }
}

// ---------------- batched tiled transpose (rounds output to tf32) ----------------
__global__ void transpose_k(const float* __restrict__ S, float* __restrict__ Dst,
                            int R, int C, int lds, int ldd, int nb2,
                            long long sSb, long long sSh, long long sDb, long long sDh) {
    __shared__ float t[32][33];
    int z = blockIdx.z, zb = z / nb2, zh = z % nb2;
    S += zb * sSb + zh * sSh;
    Dst += zb * sDb + zh * sDh;
    int r0 = blockIdx.y * 32, c0 = blockIdx.x * 32;
    int c = c0 + threadIdx.x;
#pragma unroll
    for (int i = 0; i < 32; i += 8) {
        int r = r0 + threadIdx.y + i;
        if (r < R && c < C) t[threadIdx.y + i][threadIdx.x] = S[(long long)r * lds + c];
    }
    __syncthreads();
    int cc2 = r0 + threadIdx.x;
#pragma unroll
    for (int i = 0; i < 32; i += 8) {
        int rr2 = c0 + threadIdx.y + i;
        if (rr2 < C && cc2 < R) Dst[(long long)rr2 * ldd + cc2] = rnd_tf(t[threadIdx.x][threadIdx.y + i]);
    }
}

// ---------------- reductions ----------------
__device__ __forceinline__ float block_sum(float v, float* sh) {
    int lane = threadIdx.x & 31, w = threadIdx.x >> 5;
#pragma unroll
    for (int o = 16; o; o >>= 1) v += __shfl_xor_sync(0xffffffffu, v, o);
    if (lane == 0) sh[w] = v;
    __syncthreads();
    if (threadIdx.x == 0) {
        float t = 0.f; int nw = blockDim.x >> 5;
        for (int i = 0; i < nw; i++) t += sh[i];
        sh[32] = t;
    }
    __syncthreads();
    float r = sh[32];
    __syncthreads();
    return r;
}

// ---------------- small fused kernels ----------------
__global__ void revin_k(const float* __restrict__ x, const float* __restrict__ gamma,
                        const float* __restrict__ beta, float* __restrict__ tok,
                        float* __restrict__ meanO, float* __restrict__ stdO) {
    int idx = blockIdx.x * blockDim.x + threadIdx.x;
    if (idx >= B_ * N_) return;
    int b = idx / N_, n = idx % N_;
    const float* xp = x + (long long)b * L_ * N_ + n;
    float s = 0.f, s2 = 0.f;
#pragma unroll 4
    for (int l = 0; l < L_; l++) { float v = xp[(long long)l * N_]; s += v; s2 += v * v; }
    float mean = s / L_;
    float var = fmaxf(s2 / L_ - mean * mean, 0.f);
    float sd = sqrtf(var + 1e-5f);
    meanO[idx] = mean; stdO[idx] = sd;
    float g = gamma[n], be = beta[n], inv = 1.f / sd;
    float* tp = tok + ((long long)b * T_ + n) * L_;
#pragma unroll 4
    for (int l = 0; l < L_; l++) tp[l] = rnd_tf((xp[(long long)l * N_] - mean) * inv * g + be);
}

__global__ void marks_k(const float* __restrict__ xm, float* __restrict__ tok) {
    int idx = blockIdx.x * blockDim.x + threadIdx.x;
    if (idx >= B_ * NMARK_ * L_) return;
    int l = idx % L_, m = (idx / L_) % NMARK_, b = idx / (L_ * NMARK_);
    tok[((long long)b * T_ + N_ + m) * L_ + l] = rnd_tf(xm[((long long)b * L_ + l) * NMARK_ + m]);
}

__global__ void trend_k(const float* __restrict__ tok,
                        const float* __restrict__ w1, const float* __restrict__ b1,
                        const float* __restrict__ w2, const float* __restrict__ b2,
                        float* __restrict__ nt) {
    int idx = blockIdx.x * blockDim.x + threadIdx.x;
    if (idx >= B_ * N_) return;
    int b = idx / N_, n = idx % N_;
    const float* xp = tok + ((long long)b * T_ + n) * L_;
    float cum[L_ + 1];
    cum[0] = 0.f;
    float s = 0.f, s2 = 0.f;
    for (int l = 0; l < L_; l++) {
        float v = xp[l];
        cum[l + 1] = cum[l] + v;
        s += v; s2 += v * v;
    }
    float mean = s / L_;
    float var = fmaxf(s2 / L_ - mean * mean, 0.f);
    float sd = sqrtf(var + 1e-6f);
    float logits[4] = {b2[0], b2[1], b2[2], b2[3]};
#pragma unroll
    for (int j = 0; j < 16; j++) {
        float h = fmaxf(mean * w1[j] + sd * w1[16 + j] + b1[j], 0.f);
#pragma unroll
        for (int w = 0; w < 4; w++) logits[w] += h * w2[j * 4 + w];
    }
    float mx = fmaxf(fmaxf(logits[0], logits[1]), fmaxf(logits[2], logits[3]));
    float wt[4], ws = 0.f;
#pragma unroll
    for (int w = 0; w < 4; w++) { wt[w] = expf(logits[w] - mx); ws += wt[w]; }
#pragma unroll
    for (int w = 0; w < 4; w++) wt[w] /= ws;
    const int W[4] = {4, 8, 12, 24};
    float x0 = xp[0];
    float t[L_];
    float nrm2 = 0.f;
    for (int l = 0; l < L_; l++) {
        float tv = 0.f;
#pragma unroll
        for (int wi = 0; wi < 4; wi++) {
            int w = W[wi], lo = l - w + 1;
            float sum = (lo < 0) ? (cum[l + 1] + (float)(-lo) * x0) : (cum[l + 1] - cum[lo]);
            tv += wt[wi] * sum / (float)w;
        }
        t[l] = tv; nrm2 += tv * tv;
    }
    float inv = 1.f / fmaxf(sqrtf(nrm2), 1e-12f);
    float* np = nt + ((long long)b * N_ + n) * L_;
    for (int l = 0; l < L_; l++) np[l] = rnd_tf(t[l] * inv);
}

__global__ void sigmoid_k(float* __restrict__ g, int n) {
    int idx = blockIdx.x * blockDim.x + threadIdx.x;
    if (idx < n) g[idx] = 1.f / (1.f + expf(-g[idx]));
}

__global__ void biascat_k(const float* __restrict__ bq, const float* __restrict__ bk,
                          const float* __restrict__ bv, float* __restrict__ o) {
    int i = blockIdx.x * blockDim.x + threadIdx.x;
    if (i >= LAYERS_ * 3 * D_) return;
    int l = i / (3 * D_), j = i % (3 * D_);
    float v = (j < D_) ? bq[l * D_ + j] : (j < 2 * D_) ? bk[l * D_ + j - D_] : bv[l * D_ + j - 2 * D_];
    o[i] = v;
}

template <bool RES>
__global__ void ln_k(const float* __restrict__ X, const float* __restrict__ Y,
                     const float* __restrict__ g, const float* __restrict__ be,
                     float* __restrict__ out) {
    __shared__ float sh[33];
    long long r = blockIdx.x;
    const float* x = X + r * D_;
    const float* y = RES ? (Y + r * D_) : nullptr;
    float v[4];
    float s = 0.f;
#pragma unroll
    for (int i = 0; i < 4; i++) {
        int c = threadIdx.x + i * 128;
        v[i] = x[c] + (RES ? y[c] : 0.f);
        s += v[i];
    }
    s = block_sum(s, sh);
    float mean = s / D_;
    float s2 = 0.f;
#pragma unroll
    for (int i = 0; i < 4; i++) { float d = v[i] - mean; s2 += d * d; }
    s2 = block_sum(s2, sh);
    float rstd = rsqrtf(s2 / D_ + 1e-5f);
    float* o = out + r * D_;
#pragma unroll
    for (int i = 0; i < 4; i++) {
        int c = threadIdx.x + i * 128;
        o[c] = rnd_tf((v[i] - mean) * rstd * g[c] + be[c]);
    }
}

__global__ void out_k(const float* __restrict__ proj, const float* __restrict__ meanI,
                      const float* __restrict__ stdI, const float* __restrict__ gamma,
                      const float* __restrict__ beta, float* __restrict__ out) {
    int idx = blockIdx.x * blockDim.x + threadIdx.x;
    if (idx >= B_ * PRED_ * N_) return;
    int n = idx % N_, p = (idx / N_) % PRED_, b = idx / (N_ * PRED_);
    float v = proj[((long long)b * T_ + n) * PRED_ + p];
    v = (v - beta[n]) / (gamma[n] + 1e-5f) * stdI[b * N_ + n] + meanI[b * N_ + n];
    out[idx] = v;
}

// ---------------- host orchestration ----------------
static inline dim3 tgrid(int M, int Nn, int BN, int batch) {
    return dim3((Nn + BN - 1) / BN, (M + 127) / 128, batch);
}
#define SMEMB(BNt) (3 * (128 * SSTRIDE + (BNt) * SSTRIDE) * 4)

extern "C" void kernel_launch(void* const* d_in, const int* in_sizes, int n_in,
                              void* d_out, int out_size) {
    const float* x_enc  = (const float*)d_in[0];
    const float* x_mark = (const float*)d_in[1];
    const float* gamma  = (const float*)d_in[4];
    const float* beta   = (const float*)d_in[5];
    const float* tp_w1  = (const float*)d_in[6];
    const float* tp_b1  = (const float*)d_in[7];
    const float* tp_w2  = (const float*)d_in[8];
    const float* tp_b2  = (const float*)d_in[9];
    const float* emb_w  = (const float*)d_in[10];
    const float* emb_b  = (const float*)d_in[11];
    const float* wq = (const float*)d_in[12];
    const float* bq = (const float*)d_in[13];
    const float* wk = (const float*)d_in[14];
    const float* bk = (const float*)d_in[15];
    const float* wv = (const float*)d_in[16];
    const float* bv = (const float*)d_in[17];
    const float* wo = (const float*)d_in[18];
    const float* bo = (const float*)d_in[19];
    const float* w1 = (const float*)d_in[20];
    const float* b1 = (const float*)d_in[21];
    const float* w2 = (const float*)d_in[22];
    const float* b2 = (const float*)d_in[23];
    const float* ln1g = (const float*)d_in[24];
    const float* ln1b = (const float*)d_in[25];
    const float* ln2g = (const float*)d_in[26];
    const float* ln2b = (const float*)d_in[27];
    const float* normg = (const float*)d_in[28];
    const float* normb = (const float*)d_in[29];
    const float* proj_w = (const float*)d_in[30];
    const float* proj_b = (const float*)d_in[31];
    float* out = (float*)d_out;

    float *p_mean, *p_std, *p_tok, *p_nt, *p_guide, *p_x, *p_tmp, *p_ctx, *p_qkv,
          *p_ffn, *p_wqkvt, *p_bqkv, *p_wot, *p_w1t, *p_w2t, *p_embt, *p_projt;
    cudaGetSymbolAddress((void**)&p_mean, g_mean);
    cudaGetSymbolAddress((void**)&p_std, g_std);
    cudaGetSymbolAddress((void**)&p_tok, g_tok);
    cudaGetSymbolAddress((void**)&p_nt, g_nt);
    cudaGetSymbolAddress((void**)&p_guide, g_guide);
    cudaGetSymbolAddress((void**)&p_x, g_x);
    cudaGetSymbolAddress((void**)&p_tmp, g_tmp);
    cudaGetSymbolAddress((void**)&p_ctx, g_ctx);
    cudaGetSymbolAddress((void**)&p_qkv, g_qkv);
    cudaGetSymbolAddress((void**)&p_ffn, g_ffn);
    cudaGetSymbolAddress((void**)&p_wqkvt, g_wqkvt);
    cudaGetSymbolAddress((void**)&p_bqkv, g_bqkv);
    cudaGetSymbolAddress((void**)&p_wot, g_wot);
    cudaGetSymbolAddress((void**)&p_w1t, g_w1t);
    cudaGetSymbolAddress((void**)&p_w2t, g_w2t);
    cudaGetSymbolAddress((void**)&p_embt, g_embt);
    cudaGetSymbolAddress((void**)&p_projt, g_projt);

    cudaFuncSetAttribute(mmak<0, 128, true>,  cudaFuncAttributeMaxDynamicSharedMemorySize, SMEMB(128));
    cudaFuncSetAttribute(mmak<1, 128, true>,  cudaFuncAttributeMaxDynamicSharedMemorySize, SMEMB(128));
    cudaFuncSetAttribute(mmak<1, 128, false>, cudaFuncAttributeMaxDynamicSharedMemorySize, SMEMB(128));
    cudaFuncSetAttribute(mmak<2, 128, true>,  cudaFuncAttributeMaxDynamicSharedMemorySize, SMEMB(128));
    cudaFuncSetAttribute(mmak<3, 128, true>,  cudaFuncAttributeMaxDynamicSharedMemorySize, SMEMB(128));
    cudaFuncSetAttribute(flash_k, cudaFuncAttributeMaxDynamicSharedMemorySize, FSMEM);

    dim3 tb(32, 8);

    revin_k<<<(B_ * N_ + 255) / 256, 256>>>(x_enc, gamma, beta, p_tok, p_mean, p_std);
    marks_k<<<(B_ * NMARK_ * L_ + 255) / 256, 256>>>(x_mark, p_tok);
    trend_k<<<(B_ * N_ + 255) / 256, 256>>>(p_tok, tp_w1, tp_b1, tp_w2, tp_b2, p_nt);
    transpose_k<<<dim3(16, 3, 1), tb>>>(emb_w, p_embt, L_, D_, D_, L_, 1, 0, 0, 0, 0);

    mmak<0, 128, true><<<tgrid(N_, N_, 128, B_), 256, SMEMB(128)>>>(
        p_nt, p_nt, nullptr, nullptr, p_guide, N_, N_, L_, L_, L_, N_, 1,
        (long long)N_ * L_, 0, (long long)N_ * L_, 0, (long long)N_ * N_, 0);
    mmak<1, 128, true><<<tgrid(BT_, D_, 128, 1), 256, SMEMB(128)>>>(
        p_tok, p_embt, emb_b, nullptr, p_x, BT_, D_, L_, L_, L_, D_, 1, 0, 0, 0, 0, 0, 0);
    sigmoid_k<<<(B_ * N_ * N_ + 255) / 256, 256>>>(p_guide, B_ * N_ * N_);

    transpose_k<<<dim3(16, 16, 2), tb>>>(wq, p_wqkvt, 512, 512, 512, 512, 1,
                                         512 * 512, 0, (long long)3 * 512 * 512, 0);
    transpose_k<<<dim3(16, 16, 2), tb>>>(wk, p_wqkvt + 512 * 512, 512, 512, 512, 512, 1,
                                         512 * 512, 0, (long long)3 * 512 * 512, 0);
    transpose_k<<<dim3(16, 16, 2), tb>>>(wv, p_wqkvt + 2 * 512 * 512, 512, 512, 512, 512, 1,
                                         512 * 512, 0, (long long)3 * 512 * 512, 0);
    biascat_k<<<(LAYERS_ * 3 * D_ + 255) / 256, 256>>>(bq, bk, bv, p_bqkv);
    transpose_k<<<dim3(16, 16, 2), tb>>>(wo, p_wot, 512, 512, 512, 512, 1, 512 * 512, 0, 512 * 512, 0);
    transpose_k<<<dim3(64, 16, 2), tb>>>(w1, p_w1t, 512, 2048, 2048, 512, 1,
                                         (long long)512 * 2048, 0, (long long)512 * 2048, 0);
    transpose_k<<<dim3(16, 64, 2), tb>>>(w2, p_w2t, 2048, 512, 512, 2048, 1,
                                         (long long)512 * 2048, 0, (long long)512 * 2048, 0);
    transpose_k<<<dim3(3, 16, 1), tb>>>(proj_w, p_projt, D_, PRED_, PRED_, D_, 1, 0, 0, 0, 0);

    for (int i = 0; i < LAYERS_; i++) {
        const float* wqkvt_i = p_wqkvt + (long long)i * 3 * D_ * D_;
        const float* wot_i = p_wot + (long long)i * D_ * D_;
        const float* w1t_i = p_w1t + (long long)i * D_ * DFF_;
        const float* w2t_i = p_w2t + (long long)i * DFF_ * D_;

        mmak<1, 128, true><<<tgrid(BT_, 3 * D_, 128, 1), 256, SMEMB(128)>>>(
            p_x, wqkvt_i, p_bqkv + i * 3 * D_, nullptr, p_qkv,
            BT_, 3 * D_, D_, D_, D_, 3 * D_, 1, 0, 0, 0, 0, 0, 0);

        flash_k<<<dim3(5, B_ * H_), 256, FSMEM>>>(p_qkv, p_guide, p_ctx);

        mmak<3, 128, true><<<tgrid(BT_, D_, 128, 1), 256, SMEMB(128)>>>(
            p_ctx, wot_i, bo + i * D_, p_x, p_tmp, BT_, D_, D_, D_, D_, D_, 1, 0, 0, 0, 0, 0, 0);

        ln_k<false><<<BT_, 128>>>(p_tmp, nullptr, ln1g + i * D_, ln1b + i * D_, p_tmp);

        mmak<2, 128, true><<<tgrid(BT_, DFF_, 128, 1), 256, SMEMB(128)>>>(
            p_tmp, w1t_i, b1 + i * DFF_, nullptr, p_ffn, BT_, DFF_, D_, D_, D_, DFF_, 1, 0, 0, 0, 0, 0, 0);
        mmak<1, 128, true><<<tgrid(BT_, D_, 128, 1), 256, SMEMB(128)>>>(
            p_ffn, w2t_i, b2 + i * D_, nullptr, p_ctx, BT_, D_, DFF_, DFF_, DFF_, D_, 1, 0, 0, 0, 0, 0, 0);

        ln_k<true><<<BT_, 128>>>(p_tmp, p_ctx, ln2g + i * D_, ln2b + i * D_, p_x);
    }

    ln_k<false><<<BT_, 128>>>(p_x, nullptr, normg, normb, p_tmp);

    mmak<1, 128, false><<<tgrid(BT_, PRED_, 128, 1), 256, SMEMB(128)>>>(
        p_tmp, p_projt, proj_b, nullptr, p_qkv, BT_, PRED_, D_, D_, D_, PRED_, 1, 0, 0, 0, 0, 0, 0);

    out_k<<<(B_ * PRED_ * N_ + 255) / 256, 256>>>(p_qkv, p_mean, p_std, gamma, beta, out);
}

// round 13
// speedup vs baseline: 5.7892x; 1.6342x over previous
#include <cuda_runtime.h>
#include <cuda_fp16.h>
#include <cstdint>
#include <math.h>

// ---------------- problem constants ----------------
#define B_ 16
#define L_ 96
#define N_ 512
#define D_ 512
#define H_ 8
#define E_ 64
#define DFF_ 2048
#define T_ 516
#define PRED_ 96
#define NMARK_ 4
#define LAYERS_ 2
#define BT_ (B_ * T_)     // 8256
#define SCALE_ 0.125f

// ---------------- scratch ----------------
__device__ float g_mean[B_ * N_];
__device__ float g_std[B_ * N_];
__device__ float g_guide[B_ * N_ * N_];
__device__ float g_bqkv[LAYERS_ * 3 * D_];
__device__ float g_proj[BT_ * PRED_];
__device__ __half g_tok[B_ * T_ * L_];
__device__ __half g_nt[B_ * N_ * L_];
__device__ __half g_x[BT_ * D_];
__device__ __half g_tmp[BT_ * D_];
__device__ __half g_ctx[BT_ * D_];
__device__ __half g_qkv[(long long)BT_ * 3 * D_];
__device__ __half g_ffn[(long long)BT_ * DFF_];
__device__ __half g_wqkvt[(long long)LAYERS_ * 3 * D_ * D_];
__device__ __half g_wot[LAYERS_ * D_ * D_];
__device__ __half g_w1t[(long long)LAYERS_ * D_ * DFF_];
__device__ __half g_w2t[(long long)LAYERS_ * DFF_ * D_];
__device__ __half g_embt[D_ * L_];
__device__ __half g_projt[PRED_ * D_];

// ---------------- helpers ----------------
__device__ __forceinline__ void mma16(float* c, const uint32_t* a, uint32_t b0, uint32_t b1) {
    asm volatile(
        "mma.sync.aligned.m16n8k16.row.col.f32.f16.f16.f32 "
        "{%0,%1,%2,%3}, {%4,%5,%6,%7}, {%8,%9}, {%0,%1,%2,%3};"
        : "+f"(c[0]), "+f"(c[1]), "+f"(c[2]), "+f"(c[3])
        : "r"(a[0]), "r"(a[1]), "r"(a[2]), "r"(a[3]), "r"(b0), "r"(b1));
}
__device__ __forceinline__ void ldsm4(uint32_t* r, uint32_t addr) {
    asm volatile("ldmatrix.sync.aligned.m8n8.x4.shared.b16 {%0,%1,%2,%3}, [%4];"
        : "=r"(r[0]), "=r"(r[1]), "=r"(r[2]), "=r"(r[3]) : "r"(addr));
}
__device__ __forceinline__ void ldsm4t(uint32_t* r, uint32_t addr) {
    asm volatile("ldmatrix.sync.aligned.m8n8.x4.trans.shared.b16 {%0,%1,%2,%3}, [%4];"
        : "=r"(r[0]), "=r"(r[1]), "=r"(r[2]), "=r"(r[3]) : "r"(addr));
}
__device__ __forceinline__ uint32_t h2pack(float a, float b) {
    __half2 h = __floats2half2_rn(a, b);
    return *reinterpret_cast<uint32_t*>(&h);
}
__device__ __forceinline__ float geluf(float x) {
    return 0.5f * x * (1.0f + erff(x * 0.70710678118654752f));
}
__device__ __forceinline__ uint32_t smem_u32(const void* p) {
    uint32_t a;
    asm("{ .reg .u64 t; cvta.to.shared.u64 t, %1; cvt.u32.u64 %0, t; }" : "=r"(a) : "l"(p));
    return a;
}
__device__ __forceinline__ void cp16_full(uint32_t dst, const void* src) {
    asm volatile("cp.async.cg.shared.global [%0], [%1], 16;" :: "r"(dst), "l"(src) : "memory");
}
__device__ __forceinline__ void cp16_pred(uint32_t dst, const void* src, int nbytes) {
    asm volatile("cp.async.cg.shared.global [%0], [%1], 16, %2;" :: "r"(dst), "l"(src), "r"(nbytes) : "memory");
}
#define CP_COMMIT() asm volatile("cp.async.commit_group;" ::: "memory")
template <int Nw>
__device__ __forceinline__ void cp_wait() {
    asm volatile("cp.async.wait_group %0;" :: "n"(Nw) : "memory");
}

// ---------------- fp16 tensor-core GEMM: C[M,N] = A[M,K] @ B[N,K]^T (+epi) ----------------
// EPI: 0 none, 1 +bias, 2 +bias+gelu, 3 +bias+residual.  K must be a multiple of 32.
// OT: output element type (float or __half).
#define SSH 40   // smem row stride in halfs (80B): ldmatrix conflict-free

template <int EPI, int BNt, typename OT>
__global__ void __launch_bounds__(256)
mmak(const __half* __restrict__ A, const __half* __restrict__ Bm,
     const float* __restrict__ bias, const __half* __restrict__ Res,
     OT* __restrict__ C,
     int M, int Nn, int K, int lda, int ldb, int ldc, int nbH,
     long long sAb, long long sAh, long long sBb, long long sBh,
     long long sCb, long long sCh) {
    constexpr int WN = BNt / 4;
    constexpr int NI = WN / 8;
    constexpr int NP = NI / 2;
    constexpr int BQ = (BNt * 4) / 256;
    constexpr int AE = 128 * SSH;          // halfs
    constexpr int BE = BNt * SSH;
    constexpr int STG = AE + BE;

    extern __shared__ char smem_raw[];
    const uint32_t sbase = smem_u32(smem_raw);

    int tid = threadIdx.x;
    int z = blockIdx.z, zb = z / nbH, zh = z % nbH;
    A  += zb * sAb + zh * sAh;
    Bm += zb * sBb + zh * sBh;
    C  += zb * sCb + zh * sCh;
    int m0 = blockIdx.y * 128, n0 = blockIdx.x * BNt;

    int lane = tid & 31, wid = tid >> 5;
    int wm = (wid & 1) * 64;
    int wn = (wid >> 1) * WN;
    int grp = lane >> 2, tig = lane & 3;
    int ls = lane >> 3, r8 = lane & 7;

    uint32_t offA[4];
#pragma unroll
    for (int mi = 0; mi < 4; mi++) {
        int row = wm + mi * 16 + (ls & 1) * 8 + r8;
        int col = (ls >> 1) * 8;
        offA[mi] = (uint32_t)(row * SSH + col) * 2u;
    }
    uint32_t offB[NP];
#pragma unroll
    for (int pi = 0; pi < NP; pi++) {
        int row = wn + (2 * pi + (ls >> 1)) * 8 + r8;
        int col = (ls & 1) * 8;
        offB[pi] = (uint32_t)(row * SSH + col) * 2u;
    }

    float acc[4][NI][4];
#pragma unroll
    for (int mi = 0; mi < 4; mi++)
#pragma unroll
        for (int ni = 0; ni < NI; ni++)
#pragma unroll
            for (int r = 0; r < 4; r++) acc[mi][ni][r] = 0.f;

    const int NC = K >> 5;                 // chunks of 32 halfs
    const bool full = (m0 + 128 <= M) && (n0 + BNt <= Nn);
    const int a_row0 = tid >> 2, a_c8 = (tid & 3) << 3;   // 8-half (16B) segs

    auto issue = [&](int c, int st) {
        int k0 = c * 32;
        uint32_t abase = sbase + (uint32_t)(st * STG) * 2u;
        uint32_t bbase = abase + (uint32_t)AE * 2u;
        if (full) {
#pragma unroll
            for (int u = 0; u < 2; u++) {
                int row = a_row0 + u * 64;
                cp16_full(abase + (uint32_t)(row * SSH + a_c8) * 2u,
                          A + (long long)(m0 + row) * lda + k0 + a_c8);
            }
#pragma unroll
            for (int u = 0; u < BQ; u++) {
                int row = a_row0 + u * 64;
                cp16_full(bbase + (uint32_t)(row * SSH + a_c8) * 2u,
                          Bm + (long long)(n0 + row) * ldb + k0 + a_c8);
            }
        } else {
#pragma unroll
            for (int u = 0; u < 2; u++) {
                int row = a_row0 + u * 64;
                int gm = m0 + row;
                int nb = (gm < M) ? 16 : 0;
                const __half* src = (nb > 0) ? (A + (long long)gm * lda + k0 + a_c8) : A;
                cp16_pred(abase + (uint32_t)(row * SSH + a_c8) * 2u, src, nb);
            }
#pragma unroll
            for (int u = 0; u < BQ; u++) {
                int row = a_row0 + u * 64;
                int gn = n0 + row;
                int nb = (gn < Nn) ? 16 : 0;
                const __half* src = (nb > 0) ? (Bm + (long long)gn * ldb + k0 + a_c8) : Bm;
                cp16_pred(bbase + (uint32_t)(row * SSH + a_c8) * 2u, src, nb);
            }
        }
    };

    int pre = NC < 2 ? NC : 2;
    for (int s = 0; s < pre; s++) { issue(s, s); CP_COMMIT(); }

    for (int c = 0; c < NC; c++) {
        if (c + 1 < NC) cp_wait<1>(); else cp_wait<0>();
        __syncthreads();
        if (c + 2 < NC) { issue(c + 2, (c + 2) % 3); CP_COMMIT(); }

        uint32_t aB = sbase + (uint32_t)((c % 3) * STG) * 2u;
        uint32_t bB = aB + (uint32_t)AE * 2u;
#pragma unroll
        for (int kk = 0; kk < 2; kk++) {           // two k16 steps per 32-half chunk
            uint32_t kof = (uint32_t)kk * 32u;     // 16 halfs = 32 bytes
            uint32_t af[4][4];
#pragma unroll
            for (int mi = 0; mi < 4; mi++) ldsm4(af[mi], aB + offA[mi] + kof);
#pragma unroll
            for (int pi = 0; pi < NP; pi++) {
                uint32_t bb[4];
                ldsm4(bb, bB + offB[pi] + kof);
#pragma unroll
                for (int mi = 0; mi < 4; mi++) {
                    mma16(acc[mi][2 * pi],     af[mi], bb[0], bb[1]);
                    mma16(acc[mi][2 * pi + 1], af[mi], bb[2], bb[3]);
                }
            }
        }
    }

#pragma unroll
    for (int mi = 0; mi < 4; mi++) {
#pragma unroll
        for (int ni = 0; ni < NI; ni++) {
            int col = n0 + wn + ni * 8 + 2 * tig;
            if (col >= Nn) continue;
            float bv0 = 0.f, bv1 = 0.f;
            if (EPI >= 1) { bv0 = bias[col]; bv1 = bias[col + 1]; }
#pragma unroll
            for (int h = 0; h < 2; h++) {
                int gm = m0 + wm + mi * 16 + grp + h * 8;
                if (gm >= M) continue;
                float v0 = acc[mi][ni][h * 2 + 0] + bv0;
                float v1 = acc[mi][ni][h * 2 + 1] + bv1;
                if (EPI == 2) { v0 = geluf(v0); v1 = geluf(v1); }
                if (EPI == 3) {
                    const __half* rp = Res + (long long)gm * ldc + col;
                    v0 += __half2float(rp[0]); v1 += __half2float(rp[1]);
                }
                if (sizeof(OT) == 2) {
                    *(uint32_t*)((__half*)C + (long long)gm * ldc + col) = h2pack(v0, v1);
                } else {
                    *(float2*)((float*)C + (long long)gm * ldc + col) = make_float2(v0, v1);
                }
            }
        }
    }
}

// ---------------- fused gated flash attention (fp16 operands) ----------------
#define QSH 136   // P/Q row stride halfs (272B)
#define KSH 72    // K/V row stride halfs (144B)
#define FSMEM ((128 * QSH + 2 * 128 * KSH) * 2)

__global__ void __launch_bounds__(256)
flash_k(const __half* __restrict__ qkv, const float* __restrict__ gate,
        __half* __restrict__ ctx) {
    extern __shared__ char sm[];
    __half* Sp = (__half*)sm;               // [128][QSH]  Q staging, then P
    __half* Sk = Sp + 128 * QSH;            // [128][KSH]
    __half* Sv = Sk + 128 * KSH;            // [128][KSH]

    int qt = blockIdx.x;
    int bh = blockIdx.y;
    int b = bh >> 3, h = bh & 7;
    int i0 = qt * 128;
    int tid = threadIdx.x, lane = tid & 31, w = tid >> 5;
    int grp = lane >> 2, tig = lane & 3;
    int ls = lane >> 3, r8 = lane & 7;

    const __half* qb = qkv + (long long)b * T_ * (3 * D_) + h * E_;
    const __half* kb = qb + D_;
    const __half* vb = qb + 2 * D_;

    const uint32_t spB = smem_u32(Sp);
    const uint32_t skB = smem_u32(Sk);
    const uint32_t svB = smem_u32(Sv);

    // A-frag offsets from Sp (Q then P), warp-private rows w*16..
    uint32_t offPA;
    {
        int row = w * 16 + (ls & 1) * 8 + r8;
        int col = (ls >> 1) * 8;
        offPA = (uint32_t)(row * QSH + col) * 2u;
    }
    // B-frag offsets (QK) from Sk: pf -> n-tile pair
    uint32_t offKB[8];
#pragma unroll
    for (int pf = 0; pf < 8; pf++) {
        int row = (2 * pf + (ls >> 1)) * 8 + r8;
        int col = (ls & 1) * 8;
        offKB[pf] = (uint32_t)(row * KSH + col) * 2u;
    }
    // B-frag offsets (PV, trans) from Sv: pe -> e-tile pair; add ks*16*KSH*2 per k-step
    uint32_t offVB[4];
#pragma unroll
    for (int pe = 0; pe < 4; pe++) {
        int row = (ls & 1) * 8 + r8;
        int col = pe * 16 + (ls >> 1) * 8;
        offVB[pe] = (uint32_t)(row * KSH + col) * 2u;
    }

    // load Q tile (rows clamped) into Sp
    for (int e = tid; e < 128 * 8; e += 256) {
        int r = e >> 3, c8 = (e & 7) << 3;
        int gi = i0 + r; if (gi >= T_) gi = T_ - 1;
        *(uint4*)(Sp + r * QSH + c8) = *(const uint4*)(qb + (long long)gi * (3 * D_) + c8);
    }
    __syncthreads();
    uint32_t qf[4][4];
#pragma unroll
    for (int ks = 0; ks < 4; ks++) ldsm4(qf[ks], spB + offPA + (uint32_t)ks * 32u);

    float of[8][4];
#pragma unroll
    for (int nf = 0; nf < 8; nf++)
#pragma unroll
        for (int r = 0; r < 4; r++) of[nf][r] = 0.f;
    float m0 = -1e30f, m1 = -1e30f;
    float s1a = 0.f, s1b = 0.f, s2a = 0.f, s2b = 0.f;

    const float* gb = gate + (long long)b * N_ * N_;
    const int row0 = i0 + w * 16 + grp, row1 = row0 + 8;

    for (int j0 = 0; j0 < T_; j0 += 128) {
        __syncthreads();
        for (int e = tid; e < 128 * 8; e += 256) {
            int r = e >> 3, c8 = (e & 7) << 3;
            int gj = j0 + r; if (gj >= T_) gj = T_ - 1;
            *(uint4*)(Sk + r * KSH + c8) = *(const uint4*)(kb + (long long)gj * (3 * D_) + c8);
            *(uint4*)(Sv + r * KSH + c8) = *(const uint4*)(vb + (long long)gj * (3 * D_) + c8);
        }
        __syncthreads();

        // S = Q @ K^T
        float sf[16][4];
#pragma unroll
        for (int nf = 0; nf < 16; nf++)
#pragma unroll
            for (int r = 0; r < 4; r++) sf[nf][r] = 0.f;
#pragma unroll
        for (int ks = 0; ks < 4; ks++) {
#pragma unroll
            for (int pf = 0; pf < 8; pf++) {
                uint32_t bb[4];
                ldsm4(bb, skB + offKB[pf] + (uint32_t)ks * 32u);
                mma16(sf[2 * pf],     qf[ks], bb[0], bb[1]);
                mma16(sf[2 * pf + 1], qf[ks], bb[2], bb[3]);
            }
        }

        // scale + mask + chunk max
        float cm0 = -1e30f, cm1 = -1e30f;
#pragma unroll
        for (int nf = 0; nf < 16; nf++) {
            int j = j0 + nf * 8 + 2 * tig;
            float x0 = sf[nf][0] * SCALE_, x1 = sf[nf][1] * SCALE_;
            float x2 = sf[nf][2] * SCALE_, x3 = sf[nf][3] * SCALE_;
            if (j >= T_)     { x0 = -1e30f; x2 = -1e30f; }
            if (j + 1 >= T_) { x1 = -1e30f; x3 = -1e30f; }
            sf[nf][0] = x0; sf[nf][1] = x1; sf[nf][2] = x2; sf[nf][3] = x3;
            cm0 = fmaxf(cm0, fmaxf(x0, x1));
            cm1 = fmaxf(cm1, fmaxf(x2, x3));
        }
#pragma unroll
        for (int o = 1; o <= 2; o <<= 1) {
            cm0 = fmaxf(cm0, __shfl_xor_sync(0xffffffffu, cm0, o));
            cm1 = fmaxf(cm1, __shfl_xor_sync(0xffffffffu, cm1, o));
        }
        float nm0 = fmaxf(m0, cm0), nm1 = fmaxf(m1, cm1);
        float f0 = __expf(m0 - nm0), f1 = __expf(m1 - nm1);
        m0 = nm0; m1 = nm1;
        s1a *= f0; s2a *= f0; s1b *= f1; s2b *= f1;
#pragma unroll
        for (int nf = 0; nf < 8; nf++) {
            of[nf][0] *= f0; of[nf][1] *= f0;
            of[nf][2] *= f1; of[nf][3] *= f1;
        }

        // exp, gate, partial sums, write P (half, warp-private rows of Sp)
        float ls1a = 0.f, ls1b = 0.f, ls2a = 0.f, ls2b = 0.f;
        int r = w * 16 + grp;
#pragma unroll
        for (int nf = 0; nf < 16; nf++) {
            int j = j0 + nf * 8 + 2 * tig;
            float p0 = __expf(sf[nf][0] - m0), p1 = __expf(sf[nf][1] - m0);
            float p2 = __expf(sf[nf][2] - m1), p3 = __expf(sf[nf][3] - m1);
            float g0 = 0.5f, g1 = 0.5f, g2 = 0.5f, g3 = 0.5f;
            if (j < N_) {
                if (row0 < N_) { float2 gg = *(const float2*)(gb + (long long)row0 * N_ + j); g0 = gg.x; g1 = gg.y; }
                if (row1 < N_) { float2 gg = *(const float2*)(gb + (long long)row1 * N_ + j); g2 = gg.x; g3 = gg.y; }
            }
            ls1a += p0 + p1; ls1b += p2 + p3;
            float q0 = p0 * g0, q1 = p1 * g1, q2 = p2 * g2, q3 = p3 * g3;
            ls2a += q0 + q1; ls2b += q2 + q3;
            *(uint32_t*)(Sp + r * QSH + nf * 8 + 2 * tig) = h2pack(q0, q1);
            *(uint32_t*)(Sp + (r + 8) * QSH + nf * 8 + 2 * tig) = h2pack(q2, q3);
        }
#pragma unroll
        for (int o = 1; o <= 2; o <<= 1) {
            ls1a += __shfl_xor_sync(0xffffffffu, ls1a, o);
            ls1b += __shfl_xor_sync(0xffffffffu, ls1b, o);
            ls2a += __shfl_xor_sync(0xffffffffu, ls2a, o);
            ls2b += __shfl_xor_sync(0xffffffffu, ls2b, o);
        }
        s1a += ls1a; s1b += ls1b; s2a += ls2a; s2b += ls2b;

        // O += P @ V   (A via ldmatrix; V via ldmatrix.trans)
        __syncwarp();
#pragma unroll
        for (int ks = 0; ks < 8; ks++) {
            uint32_t a[4];
            ldsm4(a, spB + offPA + (uint32_t)ks * 32u);
            uint32_t vof = (uint32_t)(ks * 16 * KSH) * 2u;
#pragma unroll
            for (int pe = 0; pe < 4; pe++) {
                uint32_t bb[4];
                ldsm4t(bb, svB + offVB[pe] + vof);
                mma16(of[2 * pe],     a, bb[0], bb[1]);
                mma16(of[2 * pe + 1], a, bb[2], bb[3]);
            }
        }
    }

    // epilogue
    float d0 = 1.f / (s2a + 1e-6f * s1a);
    float d1 = 1.f / (s2b + 1e-6f * s1b);
    __half* cb = ctx + (long long)b * T_ * D_ + h * E_;
#pragma unroll
    for (int nf = 0; nf < 8; nf++) {
        int col = nf * 8 + 2 * tig;
        if (row0 < T_)
            *(uint32_t*)(cb + (long long)row0 * D_ + col) = h2pack(of[nf][0] * d0, of[nf][1] * d0);
        if (row1 < T_)
            *(uint32_t*)(cb + (long long)row1 * D_ + col) = h2pack(of[nf][2] * d1, of[nf][3] * d1);
    }
}

// ---------------- batched tiled transpose: float src -> half dst ----------------
__global__ void transpose_k(const float* __restrict__ S, __half* __restrict__ Dst,
                            int R, int C, int lds, int ldd, int nb2,
                            long long sSb, long long sSh, long long sDb, long long sDh) {
    __shared__ float t[32][33];
    int z = blockIdx.z, zb = z / nb2, zh = z % nb2;
    S += zb * sSb + zh * sSh;
    Dst += zb * sDb + zh * sDh;
    int r0 = blockIdx.y * 32, c0 = blockIdx.x * 32;
    int c = c0 + threadIdx.x;
#pragma unroll
    for (int i = 0; i < 32; i += 8) {
        int r = r0 + threadIdx.y + i;
        if (r < R && c < C) t[threadIdx.y + i][threadIdx.x] = S[(long long)r * lds + c];
    }
    __syncthreads();
    int cc2 = r0 + threadIdx.x;
#pragma unroll
    for (int i = 0; i < 32; i += 8) {
        int rr2 = c0 + threadIdx.y + i;
        if (rr2 < C && cc2 < R) Dst[(long long)rr2 * ldd + cc2] = __float2half(t[threadIdx.x][threadIdx.y + i]);
    }
}

// ---------------- reductions ----------------
__device__ __forceinline__ float block_sum(float v, float* sh) {
    int lane = threadIdx.x & 31, w = threadIdx.x >> 5;
#pragma unroll
    for (int o = 16; o; o >>= 1) v += __shfl_xor_sync(0xffffffffu, v, o);
    if (lane == 0) sh[w] = v;
    __syncthreads();
    if (threadIdx.x == 0) {
        float t = 0.f; int nw = blockDim.x >> 5;
        for (int i = 0; i < nw; i++) t += sh[i];
        sh[32] = t;
    }
    __syncthreads();
    float r = sh[32];
    __syncthreads();
    return r;
}

// ---------------- small fused kernels ----------------
__global__ void revin_k(const float* __restrict__ x, const float* __restrict__ gamma,
                        const float* __restrict__ beta, __half* __restrict__ tok,
                        float* __restrict__ meanO, float* __restrict__ stdO) {
    int idx = blockIdx.x * blockDim.x + threadIdx.x;
    if (idx >= B_ * N_) return;
    int b = idx / N_, n = idx % N_;
    const float* xp = x + (long long)b * L_ * N_ + n;
    float s = 0.f, s2 = 0.f;
#pragma unroll 4
    for (int l = 0; l < L_; l++) { float v = xp[(long long)l * N_]; s += v; s2 += v * v; }
    float mean = s / L_;
    float var = fmaxf(s2 / L_ - mean * mean, 0.f);
    float sd = sqrtf(var + 1e-5f);
    meanO[idx] = mean; stdO[idx] = sd;
    float g = gamma[n], be = beta[n], inv = 1.f / sd;
    __half* tp = tok + ((long long)b * T_ + n) * L_;
#pragma unroll 4
    for (int l = 0; l < L_; l++) tp[l] = __float2half((xp[(long long)l * N_] - mean) * inv * g + be);
}

__global__ void marks_k(const float* __restrict__ xm, __half* __restrict__ tok) {
    int idx = blockIdx.x * blockDim.x + threadIdx.x;
    if (idx >= B_ * NMARK_ * L_) return;
    int l = idx % L_, m = (idx / L_) % NMARK_, b = idx / (L_ * NMARK_);
    tok[((long long)b * T_ + N_ + m) * L_ + l] = __float2half(xm[((long long)b * L_ + l) * NMARK_ + m]);
}

__global__ void trend_k(const __half* __restrict__ tok,
                        const float* __restrict__ w1, const float* __restrict__ b1,
                        const float* __restrict__ w2, const float* __restrict__ b2,
                        __half* __restrict__ nt) {
    int idx = blockIdx.x * blockDim.x + threadIdx.x;
    if (idx >= B_ * N_) return;
    int b = idx / N_, n = idx % N_;
    const __half* xp = tok + ((long long)b * T_ + n) * L_;
    float cum[L_ + 1];
    cum[0] = 0.f;
    float s = 0.f, s2 = 0.f;
    for (int l = 0; l < L_; l++) {
        float v = __half2float(xp[l]);
        cum[l + 1] = cum[l] + v;
        s += v; s2 += v * v;
    }
    float mean = s / L_;
    float var = fmaxf(s2 / L_ - mean * mean, 0.f);
    float sd = sqrtf(var + 1e-6f);
    float logits[4] = {b2[0], b2[1], b2[2], b2[3]};
#pragma unroll
    for (int j = 0; j < 16; j++) {
        float h = fmaxf(mean * w1[j] + sd * w1[16 + j] + b1[j], 0.f);
#pragma unroll
        for (int w = 0; w < 4; w++) logits[w] += h * w2[j * 4 + w];
    }
    float mx = fmaxf(fmaxf(logits[0], logits[1]), fmaxf(logits[2], logits[3]));
    float wt[4], ws = 0.f;
#pragma unroll
    for (int w = 0; w < 4; w++) { wt[w] = expf(logits[w] - mx); ws += wt[w]; }
#pragma unroll
    for (int w = 0; w < 4; w++) wt[w] /= ws;
    const int W[4] = {4, 8, 12, 24};
    float x0 = __half2float(xp[0]);
    float t[L_];
    float nrm2 = 0.f;
    for (int l = 0; l < L_; l++) {
        float tv = 0.f;
#pragma unroll
        for (int wi = 0; wi < 4; wi++) {
            int w = W[wi], lo = l - w + 1;
            float sum = (lo < 0) ? (cum[l + 1] + (float)(-lo) * x0) : (cum[l + 1] - cum[lo]);
            tv += wt[wi] * sum / (float)w;
        }
        t[l] = tv; nrm2 += tv * tv;
    }
    float inv = 1.f / fmaxf(sqrtf(nrm2), 1e-12f);
    __half* np = nt + ((long long)b * N_ + n) * L_;
    for (int l = 0; l < L_; l++) np[l] = __float2half(t[l] * inv);
}

__global__ void sigmoid_k(float* __restrict__ g, int n) {
    int idx = blockIdx.x * blockDim.x + threadIdx.x;
    if (idx < n) g[idx] = 1.f / (1.f + expf(-g[idx]));
}

__global__ void biascat_k(const float* __restrict__ bq, const float* __restrict__ bk,
                          const float* __restrict__ bv, float* __restrict__ o) {
    int i = blockIdx.x * blockDim.x + threadIdx.x;
    if (i >= LAYERS_ * 3 * D_) return;
    int l = i / (3 * D_), j = i % (3 * D_);
    float v = (j < D_) ? bq[l * D_ + j] : (j < 2 * D_) ? bk[l * D_ + j - D_] : bv[l * D_ + j - 2 * D_];
    o[i] = v;
}

template <bool RES>
__global__ void ln_k(const __half* __restrict__ X, const __half* __restrict__ Y,
                     const float* __restrict__ g, const float* __restrict__ be,
                     __half* __restrict__ out) {
    __shared__ float sh[33];
    long long r = blockIdx.x;
    const __half* x = X + r * D_;
    const __half* y = RES ? (Y + r * D_) : nullptr;
    float v[4];
    float s = 0.f;
#pragma unroll
    for (int i = 0; i < 4; i++) {
        int c = threadIdx.x + i * 128;
        v[i] = __half2float(x[c]) + (RES ? __half2float(y[c]) : 0.f);
        s += v[i];
    }
    s = block_sum(s, sh);
    float mean = s / D_;
    float s2 = 0.f;
#pragma unroll
    for (int i = 0; i < 4; i++) { float d = v[i] - mean; s2 += d * d; }
    s2 = block_sum(s2, sh);
    float rstd = rsqrtf(s2 / D_ + 1e-5f);
    __half* o = out + r * D_;
#pragma unroll
    for (int i = 0; i < 4; i++) {
        int c = threadIdx.x + i * 128;
        o[c] = __float2half((v[i] - mean) * rstd * g[c] + be[c]);
    }
}

__global__ void out_k(const float* __restrict__ proj, const float* __restrict__ meanI,
                      const float* __restrict__ stdI, const float* __restrict__ gamma,
                      const float* __restrict__ beta, float* __restrict__ out) {
    int idx = blockIdx.x * blockDim.x + threadIdx.x;
    if (idx >= B_ * PRED_ * N_) return;
    int n = idx % N_, p = (idx / N_) % PRED_, b = idx / (N_ * PRED_);
    float v = proj[((long long)b * T_ + n) * PRED_ + p];
    v = (v - beta[n]) / (gamma[n] + 1e-5f) * stdI[b * N_ + n] + meanI[b * N_ + n];
    out[idx] = v;
}

// ---------------- host orchestration ----------------
static inline dim3 tgrid(int M, int Nn, int BN, int batch) {
    return dim3((Nn + BN - 1) / BN, (M + 127) / 128, batch);
}
#define SMEMB(BNt) (3 * (128 * SSH + (BNt) * SSH) * 2)

extern "C" void kernel_launch(void* const* d_in, const int* in_sizes, int n_in,
                              void* d_out, int out_size) {
    const float* x_enc  = (const float*)d_in[0];
    const float* x_mark = (const float*)d_in[1];
    const float* gamma  = (const float*)d_in[4];
    const float* beta   = (const float*)d_in[5];
    const float* tp_w1  = (const float*)d_in[6];
    const float* tp_b1  = (const float*)d_in[7];
    const float* tp_w2  = (const float*)d_in[8];
    const float* tp_b2  = (const float*)d_in[9];
    const float* emb_w  = (const float*)d_in[10];
    const float* emb_b  = (const float*)d_in[11];
    const float* wq = (const float*)d_in[12];
    const float* bq = (const float*)d_in[13];
    const float* wk = (const float*)d_in[14];
    const float* bk = (const float*)d_in[15];
    const float* wv = (const float*)d_in[16];
    const float* bv = (const float*)d_in[17];
    const float* wo = (const float*)d_in[18];
    const float* bo = (const float*)d_in[19];
    const float* w1 = (const float*)d_in[20];
    const float* b1 = (const float*)d_in[21];
    const float* w2 = (const float*)d_in[22];
    const float* b2 = (const float*)d_in[23];
    const float* ln1g = (const float*)d_in[24];
    const float* ln1b = (const float*)d_in[25];
    const float* ln2g = (const float*)d_in[26];
    const float* ln2b = (const float*)d_in[27];
    const float* normg = (const float*)d_in[28];
    const float* normb = (const float*)d_in[29];
    const float* proj_w = (const float*)d_in[30];
    const float* proj_b = (const float*)d_in[31];
    float* out = (float*)d_out;

    float *p_mean, *p_std, *p_guide, *p_bqkv, *p_proj;
    __half *p_tok, *p_nt, *p_x, *p_tmp, *p_ctx, *p_qkv, *p_ffn,
           *p_wqkvt, *p_wot, *p_w1t, *p_w2t, *p_embt, *p_projt;
    cudaGetSymbolAddress((void**)&p_mean, g_mean);
    cudaGetSymbolAddress((void**)&p_std, g_std);
    cudaGetSymbolAddress((void**)&p_guide, g_guide);
    cudaGetSymbolAddress((void**)&p_bqkv, g_bqkv);
    cudaGetSymbolAddress((void**)&p_proj, g_proj);
    cudaGetSymbolAddress((void**)&p_tok, g_tok);
    cudaGetSymbolAddress((void**)&p_nt, g_nt);
    cudaGetSymbolAddress((void**)&p_x, g_x);
    cudaGetSymbolAddress((void**)&p_tmp, g_tmp);
    cudaGetSymbolAddress((void**)&p_ctx, g_ctx);
    cudaGetSymbolAddress((void**)&p_qkv, g_qkv);
    cudaGetSymbolAddress((void**)&p_ffn, g_ffn);
    cudaGetSymbolAddress((void**)&p_wqkvt, g_wqkvt);
    cudaGetSymbolAddress((void**)&p_wot, g_wot);
    cudaGetSymbolAddress((void**)&p_w1t, g_w1t);
    cudaGetSymbolAddress((void**)&p_w2t, g_w2t);
    cudaGetSymbolAddress((void**)&p_embt, g_embt);
    cudaGetSymbolAddress((void**)&p_projt, g_projt);

    cudaFuncSetAttribute(mmak<0, 128, float>,  cudaFuncAttributeMaxDynamicSharedMemorySize, SMEMB(128));
    cudaFuncSetAttribute(mmak<1, 128, __half>, cudaFuncAttributeMaxDynamicSharedMemorySize, SMEMB(128));
    cudaFuncSetAttribute(mmak<1, 128, float>,  cudaFuncAttributeMaxDynamicSharedMemorySize, SMEMB(128));
    cudaFuncSetAttribute(mmak<2, 128, __half>, cudaFuncAttributeMaxDynamicSharedMemorySize, SMEMB(128));
    cudaFuncSetAttribute(mmak<3, 128, __half>, cudaFuncAttributeMaxDynamicSharedMemorySize, SMEMB(128));
    cudaFuncSetAttribute(flash_k, cudaFuncAttributeMaxDynamicSharedMemorySize, FSMEM);

    dim3 tb(32, 8);

    revin_k<<<(B_ * N_ + 255) / 256, 256>>>(x_enc, gamma, beta, p_tok, p_mean, p_std);
    marks_k<<<(B_ * NMARK_ * L_ + 255) / 256, 256>>>(x_mark, p_tok);
    trend_k<<<(B_ * N_ + 255) / 256, 256>>>(p_tok, tp_w1, tp_b1, tp_w2, tp_b2, p_nt);
    transpose_k<<<dim3(16, 3, 1), tb>>>(emb_w, p_embt, L_, D_, D_, L_, 1, 0, 0, 0, 0);

    // Gram (raw logits, float out) then sigmoid in place
    mmak<0, 128, float><<<tgrid(N_, N_, 128, B_), 256, SMEMB(128)>>>(
        p_nt, p_nt, nullptr, nullptr, p_guide, N_, N_, L_, L_, L_, N_, 1,
        (long long)N_ * L_, 0, (long long)N_ * L_, 0, (long long)N_ * N_, 0);
    // embedding: x = tok @ emb_w + emb_b (half out)
    mmak<1, 128, __half><<<tgrid(BT_, D_, 128, 1), 256, SMEMB(128)>>>(
        p_tok, p_embt, emb_b, nullptr, p_x, BT_, D_, L_, L_, L_, D_, 1, 0, 0, 0, 0, 0, 0);
    sigmoid_k<<<(B_ * N_ * N_ + 255) / 256, 256>>>(p_guide, B_ * N_ * N_);

    transpose_k<<<dim3(16, 16, 2), tb>>>(wq, p_wqkvt, 512, 512, 512, 512, 1,
                                         512 * 512, 0, (long long)3 * 512 * 512, 0);
    transpose_k<<<dim3(16, 16, 2), tb>>>(wk, p_wqkvt + 512 * 512, 512, 512, 512, 512, 1,
                                         512 * 512, 0, (long long)3 * 512 * 512, 0);
    transpose_k<<<dim3(16, 16, 2), tb>>>(wv, p_wqkvt + 2 * 512 * 512, 512, 512, 512, 512, 1,
                                         512 * 512, 0, (long long)3 * 512 * 512, 0);
    biascat_k<<<(LAYERS_ * 3 * D_ + 255) / 256, 256>>>(bq, bk, bv, p_bqkv);
    transpose_k<<<dim3(16, 16, 2), tb>>>(wo, p_wot, 512, 512, 512, 512, 1, 512 * 512, 0, 512 * 512, 0);
    transpose_k<<<dim3(64, 16, 2), tb>>>(w1, p_w1t, 512, 2048, 2048, 512, 1,
                                         (long long)512 * 2048, 0, (long long)512 * 2048, 0);
    transpose_k<<<dim3(16, 64, 2), tb>>>(w2, p_w2t, 2048, 512, 512, 2048, 1,
                                         (long long)512 * 2048, 0, (long long)512 * 2048, 0);
    transpose_k<<<dim3(3, 16, 1), tb>>>(proj_w, p_projt, D_, PRED_, PRED_, D_, 1, 0, 0, 0, 0);

    for (int i = 0; i < LAYERS_; i++) {
        const __half* wqkvt_i = p_wqkvt + (long long)i * 3 * D_ * D_;
        const __half* wot_i = p_wot + (long long)i * D_ * D_;
        const __half* w1t_i = p_w1t + (long long)i * D_ * DFF_;
        const __half* w2t_i = p_w2t + (long long)i * DFF_ * D_;

        mmak<1, 128, __half><<<tgrid(BT_, 3 * D_, 128, 1), 256, SMEMB(128)>>>(
            p_x, wqkvt_i, p_bqkv + i * 3 * D_, nullptr, p_qkv,
            BT_, 3 * D_, D_, D_, D_, 3 * D_, 1, 0, 0, 0, 0, 0, 0);

        flash_k<<<dim3(5, B_ * H_), 256, FSMEM>>>(p_qkv, p_guide, p_ctx);

        mmak<3, 128, __half><<<tgrid(BT_, D_, 128, 1), 256, SMEMB(128)>>>(
            p_ctx, wot_i, bo + i * D_, p_x, p_tmp, BT_, D_, D_, D_, D_, D_, 1, 0, 0, 0, 0, 0, 0);

        ln_k<false><<<BT_, 128>>>(p_tmp, nullptr, ln1g + i * D_, ln1b + i * D_, p_tmp);

        mmak<2, 128, __half><<<tgrid(BT_, DFF_, 128, 1), 256, SMEMB(128)>>>(
            p_tmp, w1t_i, b1 + i * DFF_, nullptr, p_ffn, BT_, DFF_, D_, D_, D_, DFF_, 1, 0, 0, 0, 0, 0, 0);
        mmak<1, 128, __half><<<tgrid(BT_, D_, 128, 1), 256, SMEMB(128)>>>(
            p_ffn, w2t_i, b2 + i * D_, nullptr, p_ctx, BT_, D_, DFF_, DFF_, DFF_, D_, 1, 0, 0, 0, 0, 0, 0);

        ln_k<true><<<BT_, 128>>>(p_tmp, p_ctx, ln2g + i * D_, ln2b + i * D_, p_x);
    }

    ln_k<false><<<BT_, 128>>>(p_x, nullptr, normg, normb, p_tmp);

    // projection -> float (feeds out_k directly; no extra rounding)
    mmak<1, 128, float><<<tgrid(BT_, PRED_, 128, 1), 256, SMEMB(128)>>>(
        p_tmp, p_projt, proj_b, nullptr, p_proj, BT_, PRED_, D_, D_, D_, PRED_, 1, 0, 0, 0, 0, 0, 0);

    out_k<<<(B_ * PRED_ * N_ + 255) / 256, 256>>>(p_proj, p_mean, p_std, gamma, beta, out);
}

// round 14
// speedup vs baseline: 5.8813x; 1.0159x over previous
#include <cuda_runtime.h>
#include <cuda_fp16.h>
#include <cstdint>
#include <math.h>

// ---------------- problem constants ----------------
#define B_ 16
#define L_ 96
#define N_ 512
#define D_ 512
#define H_ 8
#define E_ 64
#define DFF_ 2048
#define T_ 516
#define PRED_ 96
#define NMARK_ 4
#define LAYERS_ 2
#define BT_ (B_ * T_)     // 8256
#define SCALE_ 0.125f

// ---------------- scratch ----------------
__device__ float g_mean[B_ * N_];
__device__ float g_std[B_ * N_];
__device__ float g_guide[B_ * N_ * N_];
__device__ float g_bqkv[LAYERS_ * 3 * D_];
__device__ float g_proj[BT_ * PRED_];
__device__ __half g_tok[B_ * T_ * L_];
__device__ __half g_nt[B_ * N_ * L_];
__device__ __half g_x[BT_ * D_];
__device__ __half g_tmp[BT_ * D_];
__device__ __half g_ctx[BT_ * D_];
__device__ __half g_qkv[(long long)BT_ * 3 * D_];
__device__ __half g_ffn[(long long)BT_ * DFF_];
__device__ __half g_wqkvt[(long long)LAYERS_ * 3 * D_ * D_];
__device__ __half g_wot[LAYERS_ * D_ * D_];
__device__ __half g_w1t[(long long)LAYERS_ * D_ * DFF_];
__device__ __half g_w2t[(long long)LAYERS_ * DFF_ * D_];
__device__ __half g_embt[D_ * L_];
__device__ __half g_projt[PRED_ * D_];

// ---------------- helpers ----------------
__device__ __forceinline__ void mma16(float* c, const uint32_t* a, uint32_t b0, uint32_t b1) {
    asm volatile(
        "mma.sync.aligned.m16n8k16.row.col.f32.f16.f16.f32 "
        "{%0,%1,%2,%3}, {%4,%5,%6,%7}, {%8,%9}, {%0,%1,%2,%3};"
        : "+f"(c[0]), "+f"(c[1]), "+f"(c[2]), "+f"(c[3])
        : "r"(a[0]), "r"(a[1]), "r"(a[2]), "r"(a[3]), "r"(b0), "r"(b1));
}
__device__ __forceinline__ void ldsm4(uint32_t* r, uint32_t addr) {
    asm volatile("ldmatrix.sync.aligned.m8n8.x4.shared.b16 {%0,%1,%2,%3}, [%4];"
        : "=r"(r[0]), "=r"(r[1]), "=r"(r[2]), "=r"(r[3]) : "r"(addr));
}
__device__ __forceinline__ void ldsm4t(uint32_t* r, uint32_t addr) {
    asm volatile("ldmatrix.sync.aligned.m8n8.x4.trans.shared.b16 {%0,%1,%2,%3}, [%4];"
        : "=r"(r[0]), "=r"(r[1]), "=r"(r[2]), "=r"(r[3]) : "r"(addr));
}
__device__ __forceinline__ uint32_t h2pack(float a, float b) {
    __half2 h = __floats2half2_rn(a, b);
    return *reinterpret_cast<uint32_t*>(&h);
}
__device__ __forceinline__ float geluf(float x) {
    return 0.5f * x * (1.0f + erff(x * 0.70710678118654752f));
}
__device__ __forceinline__ uint32_t smem_u32(const void* p) {
    uint32_t a;
    asm("{ .reg .u64 t; cvta.to.shared.u64 t, %1; cvt.u32.u64 %0, t; }" : "=r"(a) : "l"(p));
    return a;
}
__device__ __forceinline__ void cp16_full(uint32_t dst, const void* src) {
    asm volatile("cp.async.cg.shared.global [%0], [%1], 16;" :: "r"(dst), "l"(src) : "memory");
}
__device__ __forceinline__ void cp16_pred(uint32_t dst, const void* src, int nbytes) {
    asm volatile("cp.async.cg.shared.global [%0], [%1], 16, %2;" :: "r"(dst), "l"(src), "r"(nbytes) : "memory");
}
#define CP_COMMIT() asm volatile("cp.async.commit_group;" ::: "memory")
template <int Nw>
__device__ __forceinline__ void cp_wait() {
    asm volatile("cp.async.wait_group %0;" :: "n"(Nw) : "memory");
}

// ---------------- fp16 tensor-core GEMM: C[M,N] = A[M,K] @ B[N,K]^T (+epi) ----------------
// EPI: 0 none, 1 +bias, 2 +bias+gelu, 3 +bias+residual, 4 sigmoid (no bias).
// K must be a multiple of 32.  OT: output element type (float or __half).
#define SSH 40   // smem row stride in halfs (80B): ldmatrix conflict-free

template <int EPI, int BNt, typename OT>
__global__ void __launch_bounds__(256, 2)
mmak(const __half* __restrict__ A, const __half* __restrict__ Bm,
     const float* __restrict__ bias, const __half* __restrict__ Res,
     OT* __restrict__ C,
     int M, int Nn, int K, int lda, int ldb, int ldc, int nbH,
     long long sAb, long long sAh, long long sBb, long long sBh,
     long long sCb, long long sCh) {
    constexpr int WN = BNt / 4;
    constexpr int NI = WN / 8;
    constexpr int NP = NI / 2;
    constexpr int BQ = (BNt * 4) / 256;
    constexpr int AE = 128 * SSH;          // halfs
    constexpr int BE = BNt * SSH;
    constexpr int STG = AE + BE;

    extern __shared__ char smem_raw[];
    const uint32_t sbase = smem_u32(smem_raw);

    int tid = threadIdx.x;
    int z = blockIdx.z, zb = z / nbH, zh = z % nbH;
    A  += zb * sAb + zh * sAh;
    Bm += zb * sBb + zh * sBh;
    C  += zb * sCb + zh * sCh;
    int m0 = blockIdx.y * 128, n0 = blockIdx.x * BNt;

    int lane = tid & 31, wid = tid >> 5;
    int wm = (wid & 1) * 64;
    int wn = (wid >> 1) * WN;
    int grp = lane >> 2, tig = lane & 3;
    int ls = lane >> 3, r8 = lane & 7;

    uint32_t offA[4];
#pragma unroll
    for (int mi = 0; mi < 4; mi++) {
        int row = wm + mi * 16 + (ls & 1) * 8 + r8;
        int col = (ls >> 1) * 8;
        offA[mi] = (uint32_t)(row * SSH + col) * 2u;
    }
    uint32_t offB[NP];
#pragma unroll
    for (int pi = 0; pi < NP; pi++) {
        int row = wn + (2 * pi + (ls >> 1)) * 8 + r8;
        int col = (ls & 1) * 8;
        offB[pi] = (uint32_t)(row * SSH + col) * 2u;
    }

    float acc[4][NI][4];
#pragma unroll
    for (int mi = 0; mi < 4; mi++)
#pragma unroll
        for (int ni = 0; ni < NI; ni++)
#pragma unroll
            for (int r = 0; r < 4; r++) acc[mi][ni][r] = 0.f;

    const int NC = K >> 5;                 // chunks of 32 halfs
    const bool full = (m0 + 128 <= M) && (n0 + BNt <= Nn);
    const int a_row0 = tid >> 2, a_c8 = (tid & 3) << 3;   // 8-half (16B) segs

    auto issue = [&](int c, int st) {
        int k0 = c * 32;
        uint32_t abase = sbase + (uint32_t)(st * STG) * 2u;
        uint32_t bbase = abase + (uint32_t)AE * 2u;
        if (full) {
#pragma unroll
            for (int u = 0; u < 2; u++) {
                int row = a_row0 + u * 64;
                cp16_full(abase + (uint32_t)(row * SSH + a_c8) * 2u,
                          A + (long long)(m0 + row) * lda + k0 + a_c8);
            }
#pragma unroll
            for (int u = 0; u < BQ; u++) {
                int row = a_row0 + u * 64;
                cp16_full(bbase + (uint32_t)(row * SSH + a_c8) * 2u,
                          Bm + (long long)(n0 + row) * ldb + k0 + a_c8);
            }
        } else {
#pragma unroll
            for (int u = 0; u < 2; u++) {
                int row = a_row0 + u * 64;
                int gm = m0 + row;
                int nb = (gm < M) ? 16 : 0;
                const __half* src = (nb > 0) ? (A + (long long)gm * lda + k0 + a_c8) : A;
                cp16_pred(abase + (uint32_t)(row * SSH + a_c8) * 2u, src, nb);
            }
#pragma unroll
            for (int u = 0; u < BQ; u++) {
                int row = a_row0 + u * 64;
                int gn = n0 + row;
                int nb = (gn < Nn) ? 16 : 0;
                const __half* src = (nb > 0) ? (Bm + (long long)gn * ldb + k0 + a_c8) : Bm;
                cp16_pred(bbase + (uint32_t)(row * SSH + a_c8) * 2u, src, nb);
            }
        }
    };

    int pre = NC < 2 ? NC : 2;
    for (int s = 0; s < pre; s++) { issue(s, s); CP_COMMIT(); }

    for (int c = 0; c < NC; c++) {
        if (c + 1 < NC) cp_wait<1>(); else cp_wait<0>();
        __syncthreads();
        if (c + 2 < NC) { issue(c + 2, (c + 2) % 3); CP_COMMIT(); }

        uint32_t aB = sbase + (uint32_t)((c % 3) * STG) * 2u;
        uint32_t bB = aB + (uint32_t)AE * 2u;
#pragma unroll
        for (int kk = 0; kk < 2; kk++) {           // two k16 steps per 32-half chunk
            uint32_t kof = (uint32_t)kk * 32u;     // 16 halfs = 32 bytes
            uint32_t af[4][4];
#pragma unroll
            for (int mi = 0; mi < 4; mi++) ldsm4(af[mi], aB + offA[mi] + kof);
#pragma unroll
            for (int pi = 0; pi < NP; pi++) {
                uint32_t bb[4];
                ldsm4(bb, bB + offB[pi] + kof);
#pragma unroll
                for (int mi = 0; mi < 4; mi++) {
                    mma16(acc[mi][2 * pi],     af[mi], bb[0], bb[1]);
                    mma16(acc[mi][2 * pi + 1], af[mi], bb[2], bb[3]);
                }
            }
        }
    }

#pragma unroll
    for (int mi = 0; mi < 4; mi++) {
#pragma unroll
        for (int ni = 0; ni < NI; ni++) {
            int col = n0 + wn + ni * 8 + 2 * tig;
            if (col >= Nn) continue;
            float bv0 = 0.f, bv1 = 0.f;
            if (EPI >= 1 && EPI <= 3) { bv0 = bias[col]; bv1 = bias[col + 1]; }
#pragma unroll
            for (int h = 0; h < 2; h++) {
                int gm = m0 + wm + mi * 16 + grp + h * 8;
                if (gm >= M) continue;
                float v0 = acc[mi][ni][h * 2 + 0] + bv0;
                float v1 = acc[mi][ni][h * 2 + 1] + bv1;
                if (EPI == 2) { v0 = geluf(v0); v1 = geluf(v1); }
                if (EPI == 3) {
                    const __half* rp = Res + (long long)gm * ldc + col;
                    v0 += __half2float(rp[0]); v1 += __half2float(rp[1]);
                }
                if (EPI == 4) {
                    v0 = 1.f / (1.f + __expf(-v0));
                    v1 = 1.f / (1.f + __expf(-v1));
                }
                if (sizeof(OT) == 2) {
                    *(uint32_t*)((__half*)C + (long long)gm * ldc + col) = h2pack(v0, v1);
                } else {
                    *(float2*)((float*)C + (long long)gm * ldc + col) = make_float2(v0, v1);
                }
            }
        }
    }
}

// ---------------- fused gated flash attention (fp16 operands) ----------------
#define QSH 136   // P/Q row stride halfs (272B)
#define KSH 72    // K/V row stride halfs (144B)
#define FSMEM ((128 * QSH + 2 * 128 * KSH) * 2)

__global__ void __launch_bounds__(256)
flash_k(const __half* __restrict__ qkv, const float* __restrict__ gate,
        __half* __restrict__ ctx) {
    extern __shared__ char sm[];
    __half* Sp = (__half*)sm;               // [128][QSH]  Q staging, then P
    __half* Sk = Sp + 128 * QSH;            // [128][KSH]
    __half* Sv = Sk + 128 * KSH;            // [128][KSH]

    int qt = blockIdx.x;
    int bh = blockIdx.y;
    int b = bh >> 3, h = bh & 7;
    int i0 = qt * 128;
    int tid = threadIdx.x, lane = tid & 31, w = tid >> 5;
    int grp = lane >> 2, tig = lane & 3;
    int ls = lane >> 3, r8 = lane & 7;

    const __half* qb = qkv + (long long)b * T_ * (3 * D_) + h * E_;
    const __half* kb = qb + D_;
    const __half* vb = qb + 2 * D_;

    const uint32_t spB = smem_u32(Sp);
    const uint32_t skB = smem_u32(Sk);
    const uint32_t svB = smem_u32(Sv);

    uint32_t offPA;
    {
        int row = w * 16 + (ls & 1) * 8 + r8;
        int col = (ls >> 1) * 8;
        offPA = (uint32_t)(row * QSH + col) * 2u;
    }
    uint32_t offKB[8];
#pragma unroll
    for (int pf = 0; pf < 8; pf++) {
        int row = (2 * pf + (ls >> 1)) * 8 + r8;
        int col = (ls & 1) * 8;
        offKB[pf] = (uint32_t)(row * KSH + col) * 2u;
    }
    uint32_t offVB[4];
#pragma unroll
    for (int pe = 0; pe < 4; pe++) {
        int row = (ls & 1) * 8 + r8;
        int col = pe * 16 + (ls >> 1) * 8;
        offVB[pe] = (uint32_t)(row * KSH + col) * 2u;
    }

    for (int e = tid; e < 128 * 8; e += 256) {
        int r = e >> 3, c8 = (e & 7) << 3;
        int gi = i0 + r; if (gi >= T_) gi = T_ - 1;
        *(uint4*)(Sp + r * QSH + c8) = *(const uint4*)(qb + (long long)gi * (3 * D_) + c8);
    }
    __syncthreads();
    uint32_t qf[4][4];
#pragma unroll
    for (int ks = 0; ks < 4; ks++) ldsm4(qf[ks], spB + offPA + (uint32_t)ks * 32u);

    float of[8][4];
#pragma unroll
    for (int nf = 0; nf < 8; nf++)
#pragma unroll
        for (int r = 0; r < 4; r++) of[nf][r] = 0.f;
    float m0 = -1e30f, m1 = -1e30f;
    float s1a = 0.f, s1b = 0.f, s2a = 0.f, s2b = 0.f;

    const float* gb = gate + (long long)b * N_ * N_;
    const int row0 = i0 + w * 16 + grp, row1 = row0 + 8;

    for (int j0 = 0; j0 < T_; j0 += 128) {
        __syncthreads();
        for (int e = tid; e < 128 * 8; e += 256) {
            int r = e >> 3, c8 = (e & 7) << 3;
            int gj = j0 + r; if (gj >= T_) gj = T_ - 1;
            *(uint4*)(Sk + r * KSH + c8) = *(const uint4*)(kb + (long long)gj * (3 * D_) + c8);
            *(uint4*)(Sv + r * KSH + c8) = *(const uint4*)(vb + (long long)gj * (3 * D_) + c8);
        }
        __syncthreads();

        float sf[16][4];
#pragma unroll
        for (int nf = 0; nf < 16; nf++)
#pragma unroll
            for (int r = 0; r < 4; r++) sf[nf][r] = 0.f;
#pragma unroll
        for (int ks = 0; ks < 4; ks++) {
#pragma unroll
            for (int pf = 0; pf < 8; pf++) {
                uint32_t bb[4];
                ldsm4(bb, skB + offKB[pf] + (uint32_t)ks * 32u);
                mma16(sf[2 * pf],     qf[ks], bb[0], bb[1]);
                mma16(sf[2 * pf + 1], qf[ks], bb[2], bb[3]);
            }
        }

        float cm0 = -1e30f, cm1 = -1e30f;
#pragma unroll
        for (int nf = 0; nf < 16; nf++) {
            int j = j0 + nf * 8 + 2 * tig;
            float x0 = sf[nf][0] * SCALE_, x1 = sf[nf][1] * SCALE_;
            float x2 = sf[nf][2] * SCALE_, x3 = sf[nf][3] * SCALE_;
            if (j >= T_)     { x0 = -1e30f; x2 = -1e30f; }
            if (j + 1 >= T_) { x1 = -1e30f; x3 = -1e30f; }
            sf[nf][0] = x0; sf[nf][1] = x1; sf[nf][2] = x2; sf[nf][3] = x3;
            cm0 = fmaxf(cm0, fmaxf(x0, x1));
            cm1 = fmaxf(cm1, fmaxf(x2, x3));
        }
#pragma unroll
        for (int o = 1; o <= 2; o <<= 1) {
            cm0 = fmaxf(cm0, __shfl_xor_sync(0xffffffffu, cm0, o));
            cm1 = fmaxf(cm1, __shfl_xor_sync(0xffffffffu, cm1, o));
        }
        float nm0 = fmaxf(m0, cm0), nm1 = fmaxf(m1, cm1);
        float f0 = __expf(m0 - nm0), f1 = __expf(m1 - nm1);
        m0 = nm0; m1 = nm1;
        s1a *= f0; s2a *= f0; s1b *= f1; s2b *= f1;
#pragma unroll
        for (int nf = 0; nf < 8; nf++) {
            of[nf][0] *= f0; of[nf][1] *= f0;
            of[nf][2] *= f1; of[nf][3] *= f1;
        }

        float ls1a = 0.f, ls1b = 0.f, ls2a = 0.f, ls2b = 0.f;
        int r = w * 16 + grp;
#pragma unroll
        for (int nf = 0; nf < 16; nf++) {
            int j = j0 + nf * 8 + 2 * tig;
            float p0 = __expf(sf[nf][0] - m0), p1 = __expf(sf[nf][1] - m0);
            float p2 = __expf(sf[nf][2] - m1), p3 = __expf(sf[nf][3] - m1);
            float g0 = 0.5f, g1 = 0.5f, g2 = 0.5f, g3 = 0.5f;
            if (j < N_) {
                if (row0 < N_) { float2 gg = *(const float2*)(gb + (long long)row0 * N_ + j); g0 = gg.x; g1 = gg.y; }
                if (row1 < N_) { float2 gg = *(const float2*)(gb + (long long)row1 * N_ + j); g2 = gg.x; g3 = gg.y; }
            }
            ls1a += p0 + p1; ls1b += p2 + p3;
            float q0 = p0 * g0, q1 = p1 * g1, q2 = p2 * g2, q3 = p3 * g3;
            ls2a += q0 + q1; ls2b += q2 + q3;
            *(uint32_t*)(Sp + r * QSH + nf * 8 + 2 * tig) = h2pack(q0, q1);
            *(uint32_t*)(Sp + (r + 8) * QSH + nf * 8 + 2 * tig) = h2pack(q2, q3);
        }
#pragma unroll
        for (int o = 1; o <= 2; o <<= 1) {
            ls1a += __shfl_xor_sync(0xffffffffu, ls1a, o);
            ls1b += __shfl_xor_sync(0xffffffffu, ls1b, o);
            ls2a += __shfl_xor_sync(0xffffffffu, ls2a, o);
            ls2b += __shfl_xor_sync(0xffffffffu, ls2b, o);
        }
        s1a += ls1a; s1b += ls1b; s2a += ls2a; s2b += ls2b;

        __syncwarp();
#pragma unroll
        for (int ks = 0; ks < 8; ks++) {
            uint32_t a[4];
            ldsm4(a, spB + offPA + (uint32_t)ks * 32u);
            uint32_t vof = (uint32_t)(ks * 16 * KSH) * 2u;
#pragma unroll
            for (int pe = 0; pe < 4; pe++) {
                uint32_t bb[4];
                ldsm4t(bb, svB + offVB[pe] + vof);
                mma16(of[2 * pe],     a, bb[0], bb[1]);
                mma16(of[2 * pe + 1], a, bb[2], bb[3]);
            }
        }
    }

    float d0 = 1.f / (s2a + 1e-6f * s1a);
    float d1 = 1.f / (s2b + 1e-6f * s1b);
    __half* cb = ctx + (long long)b * T_ * D_ + h * E_;
#pragma unroll
    for (int nf = 0; nf < 8; nf++) {
        int col = nf * 8 + 2 * tig;
        if (row0 < T_)
            *(uint32_t*)(cb + (long long)row0 * D_ + col) = h2pack(of[nf][0] * d0, of[nf][1] * d0);
        if (row1 < T_)
            *(uint32_t*)(cb + (long long)row1 * D_ + col) = h2pack(of[nf][2] * d1, of[nf][3] * d1);
    }
}

// ---------------- batched tiled transpose: float src -> half dst ----------------
__global__ void transpose_k(const float* __restrict__ S, __half* __restrict__ Dst,
                            int R, int C, int lds, int ldd, int nb2,
                            long long sSb, long long sSh, long long sDb, long long sDh) {
    __shared__ float t[32][33];
    int z = blockIdx.z, zb = z / nb2, zh = z % nb2;
    S += zb * sSb + zh * sSh;
    Dst += zb * sDb + zh * sDh;
    int r0 = blockIdx.y * 32, c0 = blockIdx.x * 32;
    int c = c0 + threadIdx.x;
#pragma unroll
    for (int i = 0; i < 32; i += 8) {
        int r = r0 + threadIdx.y + i;
        if (r < R && c < C) t[threadIdx.y + i][threadIdx.x] = S[(long long)r * lds + c];
    }
    __syncthreads();
    int cc2 = r0 + threadIdx.x;
#pragma unroll
    for (int i = 0; i < 32; i += 8) {
        int rr2 = c0 + threadIdx.y + i;
        if (rr2 < C && cc2 < R) Dst[(long long)rr2 * ldd + cc2] = __float2half(t[threadIdx.x][threadIdx.y + i]);
    }
}

// ---------------- reductions ----------------
__device__ __forceinline__ float block_sum(float v, float* sh) {
    int lane = threadIdx.x & 31, w = threadIdx.x >> 5;
#pragma unroll
    for (int o = 16; o; o >>= 1) v += __shfl_xor_sync(0xffffffffu, v, o);
    if (lane == 0) sh[w] = v;
    __syncthreads();
    if (threadIdx.x == 0) {
        float t = 0.f; int nw = blockDim.x >> 5;
        for (int i = 0; i < nw; i++) t += sh[i];
        sh[32] = t;
    }
    __syncthreads();
    float r = sh[32];
    __syncthreads();
    return r;
}

// ---------------- small fused kernels ----------------
__global__ void revin_k(const float* __restrict__ x, const float* __restrict__ gamma,
                        const float* __restrict__ beta, __half* __restrict__ tok,
                        float* __restrict__ meanO, float* __restrict__ stdO) {
    int idx = blockIdx.x * blockDim.x + threadIdx.x;
    if (idx >= B_ * N_) return;
    int b = idx / N_, n = idx % N_;
    const float* xp = x + (long long)b * L_ * N_ + n;
    float s = 0.f, s2 = 0.f;
#pragma unroll 4
    for (int l = 0; l < L_; l++) { float v = xp[(long long)l * N_]; s += v; s2 += v * v; }
    float mean = s / L_;
    float var = fmaxf(s2 / L_ - mean * mean, 0.f);
    float sd = sqrtf(var + 1e-5f);
    meanO[idx] = mean; stdO[idx] = sd;
    float g = gamma[n], be = beta[n], inv = 1.f / sd;
    __half* tp = tok + ((long long)b * T_ + n) * L_;
#pragma unroll 4
    for (int l = 0; l < L_; l++) tp[l] = __float2half((xp[(long long)l * N_] - mean) * inv * g + be);
}

__global__ void marks_k(const float* __restrict__ xm, __half* __restrict__ tok) {
    int idx = blockIdx.x * blockDim.x + threadIdx.x;
    if (idx >= B_ * NMARK_ * L_) return;
    int l = idx % L_, m = (idx / L_) % NMARK_, b = idx / (L_ * NMARK_);
    tok[((long long)b * T_ + N_ + m) * L_ + l] = __float2half(xm[((long long)b * L_ + l) * NMARK_ + m]);
}

__global__ void trend_k(const __half* __restrict__ tok,
                        const float* __restrict__ w1, const float* __restrict__ b1,
                        const float* __restrict__ w2, const float* __restrict__ b2,
                        __half* __restrict__ nt) {
    int idx = blockIdx.x * blockDim.x + threadIdx.x;
    if (idx >= B_ * N_) return;
    int b = idx / N_, n = idx % N_;
    const __half* xp = tok + ((long long)b * T_ + n) * L_;
    float cum[L_ + 1];
    cum[0] = 0.f;
    float s = 0.f, s2 = 0.f;
    for (int l = 0; l < L_; l++) {
        float v = __half2float(xp[l]);
        cum[l + 1] = cum[l] + v;
        s += v; s2 += v * v;
    }
    float mean = s / L_;
    float var = fmaxf(s2 / L_ - mean * mean, 0.f);
    float sd = sqrtf(var + 1e-6f);
    float logits[4] = {b2[0], b2[1], b2[2], b2[3]};
#pragma unroll
    for (int j = 0; j < 16; j++) {
        float h = fmaxf(mean * w1[j] + sd * w1[16 + j] + b1[j], 0.f);
#pragma unroll
        for (int w = 0; w < 4; w++) logits[w] += h * w2[j * 4 + w];
    }
    float mx = fmaxf(fmaxf(logits[0], logits[1]), fmaxf(logits[2], logits[3]));
    float wt[4], ws = 0.f;
#pragma unroll
    for (int w = 0; w < 4; w++) { wt[w] = expf(logits[w] - mx); ws += wt[w]; }
#pragma unroll
    for (int w = 0; w < 4; w++) wt[w] /= ws;
    const int W[4] = {4, 8, 12, 24};
    float x0 = __half2float(xp[0]);
    float t[L_];
    float nrm2 = 0.f;
    for (int l = 0; l < L_; l++) {
        float tv = 0.f;
#pragma unroll
        for (int wi = 0; wi < 4; wi++) {
            int w = W[wi], lo = l - w + 1;
            float sum = (lo < 0) ? (cum[l + 1] + (float)(-lo) * x0) : (cum[l + 1] - cum[lo]);
            tv += wt[wi] * sum / (float)w;
        }
        t[l] = tv; nrm2 += tv * tv;
    }
    float inv = 1.f / fmaxf(sqrtf(nrm2), 1e-12f);
    __half* np = nt + ((long long)b * N_ + n) * L_;
    for (int l = 0; l < L_; l++) np[l] = __float2half(t[l] * inv);
}

__global__ void biascat_k(const float* __restrict__ bq, const float* __restrict__ bk,
                          const float* __restrict__ bv, float* __restrict__ o) {
    int i = blockIdx.x * blockDim.x + threadIdx.x;
    if (i >= LAYERS_ * 3 * D_) return;
    int l = i / (3 * D_), j = i % (3 * D_);
    float v = (j < D_) ? bq[l * D_ + j] : (j < 2 * D_) ? bk[l * D_ + j - D_] : bv[l * D_ + j - 2 * D_];
    o[i] = v;
}

template <bool RES>
__global__ void ln_k(const __half* __restrict__ X, const __half* __restrict__ Y,
                     const float* __restrict__ g, const float* __restrict__ be,
                     __half* __restrict__ out) {
    __shared__ float sh[33];
    long long r = blockIdx.x;
    const __half* x = X + r * D_;
    const __half* y = RES ? (Y + r * D_) : nullptr;
    float v[4];
    float s = 0.f;
#pragma unroll
    for (int i = 0; i < 4; i++) {
        int c = threadIdx.x + i * 128;
        v[i] = __half2float(x[c]) + (RES ? __half2float(y[c]) : 0.f);
        s += v[i];
    }
    s = block_sum(s, sh);
    float mean = s / D_;
    float s2 = 0.f;
#pragma unroll
    for (int i = 0; i < 4; i++) { float d = v[i] - mean; s2 += d * d; }
    s2 = block_sum(s2, sh);
    float rstd = rsqrtf(s2 / D_ + 1e-5f);
    __half* o = out + r * D_;
#pragma unroll
    for (int i = 0; i < 4; i++) {
        int c = threadIdx.x + i * 128;
        o[c] = __float2half((v[i] - mean) * rstd * g[c] + be[c]);
    }
}

__global__ void out_k(const float* __restrict__ proj, const float* __restrict__ meanI,
                      const float* __restrict__ stdI, const float* __restrict__ gamma,
                      const float* __restrict__ beta, float* __restrict__ out) {
    int idx = blockIdx.x * blockDim.x + threadIdx.x;
    if (idx >= B_ * PRED_ * N_) return;
    int n = idx % N_, p = (idx / N_) % PRED_, b = idx / (N_ * PRED_);
    float v = proj[((long long)b * T_ + n) * PRED_ + p];
    v = (v - beta[n]) / (gamma[n] + 1e-5f) * stdI[b * N_ + n] + meanI[b * N_ + n];
    out[idx] = v;
}

// ---------------- host orchestration ----------------
static inline dim3 tgrid(int M, int Nn, int BN, int batch) {
    return dim3((Nn + BN - 1) / BN, (M + 127) / 128, batch);
}
#define SMEMB(BNt) (3 * (128 * SSH + (BNt) * SSH) * 2)

extern "C" void kernel_launch(void* const* d_in, const int* in_sizes, int n_in,
                              void* d_out, int out_size) {
    const float* x_enc  = (const float*)d_in[0];
    const float* x_mark = (const float*)d_in[1];
    const float* gamma  = (const float*)d_in[4];
    const float* beta   = (const float*)d_in[5];
    const float* tp_w1  = (const float*)d_in[6];
    const float* tp_b1  = (const float*)d_in[7];
    const float* tp_w2  = (const float*)d_in[8];
    const float* tp_b2  = (const float*)d_in[9];
    const float* emb_w  = (const float*)d_in[10];
    const float* emb_b  = (const float*)d_in[11];
    const float* wq = (const float*)d_in[12];
    const float* bq = (const float*)d_in[13];
    const float* wk = (const float*)d_in[14];
    const float* bk = (const float*)d_in[15];
    const float* wv = (const float*)d_in[16];
    const float* bv = (const float*)d_in[17];
    const float* wo = (const float*)d_in[18];
    const float* bo = (const float*)d_in[19];
    const float* w1 = (const float*)d_in[20];
    const float* b1 = (const float*)d_in[21];
    const float* w2 = (const float*)d_in[22];
    const float* b2 = (const float*)d_in[23];
    const float* ln1g = (const float*)d_in[24];
    const float* ln1b = (const float*)d_in[25];
    const float* ln2g = (const float*)d_in[26];
    const float* ln2b = (const float*)d_in[27];
    const float* normg = (const float*)d_in[28];
    const float* normb = (const float*)d_in[29];
    const float* proj_w = (const float*)d_in[30];
    const float* proj_b = (const float*)d_in[31];
    float* out = (float*)d_out;

    float *p_mean, *p_std, *p_guide, *p_bqkv, *p_proj;
    __half *p_tok, *p_nt, *p_x, *p_tmp, *p_ctx, *p_qkv, *p_ffn,
           *p_wqkvt, *p_wot, *p_w1t, *p_w2t, *p_embt, *p_projt;
    cudaGetSymbolAddress((void**)&p_mean, g_mean);
    cudaGetSymbolAddress((void**)&p_std, g_std);
    cudaGetSymbolAddress((void**)&p_guide, g_guide);
    cudaGetSymbolAddress((void**)&p_bqkv, g_bqkv);
    cudaGetSymbolAddress((void**)&p_proj, g_proj);
    cudaGetSymbolAddress((void**)&p_tok, g_tok);
    cudaGetSymbolAddress((void**)&p_nt, g_nt);
    cudaGetSymbolAddress((void**)&p_x, g_x);
    cudaGetSymbolAddress((void**)&p_tmp, g_tmp);
    cudaGetSymbolAddress((void**)&p_ctx, g_ctx);
    cudaGetSymbolAddress((void**)&p_qkv, g_qkv);
    cudaGetSymbolAddress((void**)&p_ffn, g_ffn);
    cudaGetSymbolAddress((void**)&p_wqkvt, g_wqkvt);
    cudaGetSymbolAddress((void**)&p_wot, g_wot);
    cudaGetSymbolAddress((void**)&p_w1t, g_w1t);
    cudaGetSymbolAddress((void**)&p_w2t, g_w2t);
    cudaGetSymbolAddress((void**)&p_embt, g_embt);
    cudaGetSymbolAddress((void**)&p_projt, g_projt);

    cudaFuncSetAttribute(mmak<4, 128, float>,  cudaFuncAttributeMaxDynamicSharedMemorySize, SMEMB(128));
    cudaFuncSetAttribute(mmak<1, 128, __half>, cudaFuncAttributeMaxDynamicSharedMemorySize, SMEMB(128));
    cudaFuncSetAttribute(mmak<1, 128, float>,  cudaFuncAttributeMaxDynamicSharedMemorySize, SMEMB(128));
    cudaFuncSetAttribute(mmak<2, 128, __half>, cudaFuncAttributeMaxDynamicSharedMemorySize, SMEMB(128));
    cudaFuncSetAttribute(mmak<3, 128, __half>, cudaFuncAttributeMaxDynamicSharedMemorySize, SMEMB(128));
    cudaFuncSetAttribute(flash_k, cudaFuncAttributeMaxDynamicSharedMemorySize, FSMEM);

    dim3 tb(32, 8);

    revin_k<<<(B_ * N_ + 255) / 256, 256>>>(x_enc, gamma, beta, p_tok, p_mean, p_std);
    marks_k<<<(B_ * NMARK_ * L_ + 255) / 256, 256>>>(x_mark, p_tok);
    trend_k<<<(B_ * N_ + 255) / 256, 256>>>(p_tok, tp_w1, tp_b1, tp_w2, tp_b2, p_nt);
    transpose_k<<<dim3(16, 3, 1), tb>>>(emb_w, p_embt, L_, D_, D_, L_, 1, 0, 0, 0, 0);

    // Gram with fused sigmoid -> gate
    mmak<4, 128, float><<<tgrid(N_, N_, 128, B_), 256, SMEMB(128)>>>(
        p_nt, p_nt, nullptr, nullptr, p_guide, N_, N_, L_, L_, L_, N_, 1,
        (long long)N_ * L_, 0, (long long)N_ * L_, 0, (long long)N_ * N_, 0);
    // embedding: x = tok @ emb_w + emb_b (half out)
    mmak<1, 128, __half><<<tgrid(BT_, D_, 128, 1), 256, SMEMB(128)>>>(
        p_tok, p_embt, emb_b, nullptr, p_x, BT_, D_, L_, L_, L_, D_, 1, 0, 0, 0, 0, 0, 0);

    transpose_k<<<dim3(16, 16, 2), tb>>>(wq, p_wqkvt, 512, 512, 512, 512, 1,
                                         512 * 512, 0, (long long)3 * 512 * 512, 0);
    transpose_k<<<dim3(16, 16, 2), tb>>>(wk, p_wqkvt + 512 * 512, 512, 512, 512, 512, 1,
                                         512 * 512, 0, (long long)3 * 512 * 512, 0);
    transpose_k<<<dim3(16, 16, 2), tb>>>(wv, p_wqkvt + 2 * 512 * 512, 512, 512, 512, 512, 1,
                                         512 * 512, 0, (long long)3 * 512 * 512, 0);
    biascat_k<<<(LAYERS_ * 3 * D_ + 255) / 256, 256>>>(bq, bk, bv, p_bqkv);
    transpose_k<<<dim3(16, 16, 2), tb>>>(wo, p_wot, 512, 512, 512, 512, 1, 512 * 512, 0, 512 * 512, 0);
    transpose_k<<<dim3(64, 16, 2), tb>>>(w1, p_w1t, 512, 2048, 2048, 512, 1,
                                         (long long)512 * 2048, 0, (long long)512 * 2048, 0);
    transpose_k<<<dim3(16, 64, 2), tb>>>(w2, p_w2t, 2048, 512, 512, 2048, 1,
                                         (long long)512 * 2048, 0, (long long)512 * 2048, 0);
    transpose_k<<<dim3(3, 16, 1), tb>>>(proj_w, p_projt, D_, PRED_, PRED_, D_, 1, 0, 0, 0, 0);

    for (int i = 0; i < LAYERS_; i++) {
        const __half* wqkvt_i = p_wqkvt + (long long)i * 3 * D_ * D_;
        const __half* wot_i = p_wot + (long long)i * D_ * D_;
        const __half* w1t_i = p_w1t + (long long)i * D_ * DFF_;
        const __half* w2t_i = p_w2t + (long long)i * DFF_ * D_;

        mmak<1, 128, __half><<<tgrid(BT_, 3 * D_, 128, 1), 256, SMEMB(128)>>>(
            p_x, wqkvt_i, p_bqkv + i * 3 * D_, nullptr, p_qkv,
            BT_, 3 * D_, D_, D_, D_, 3 * D_, 1, 0, 0, 0, 0, 0, 0);

        flash_k<<<dim3(5, B_ * H_), 256, FSMEM>>>(p_qkv, p_guide, p_ctx);

        mmak<3, 128, __half><<<tgrid(BT_, D_, 128, 1), 256, SMEMB(128)>>>(
            p_ctx, wot_i, bo + i * D_, p_x, p_tmp, BT_, D_, D_, D_, D_, D_, 1, 0, 0, 0, 0, 0, 0);

        ln_k<false><<<BT_, 128>>>(p_tmp, nullptr, ln1g + i * D_, ln1b + i * D_, p_tmp);

        mmak<2, 128, __half><<<tgrid(BT_, DFF_, 128, 1), 256, SMEMB(128)>>>(
            p_tmp, w1t_i, b1 + i * DFF_, nullptr, p_ffn, BT_, DFF_, D_, D_, D_, DFF_, 1, 0, 0, 0, 0, 0, 0);
        mmak<1, 128, __half><<<tgrid(BT_, D_, 128, 1), 256, SMEMB(128)>>>(
            p_ffn, w2t_i, b2 + i * D_, nullptr, p_ctx, BT_, D_, DFF_, DFF_, DFF_, D_, 1, 0, 0, 0, 0, 0, 0);

        ln_k<true><<<BT_, 128>>>(p_tmp, p_ctx, ln2g + i * D_, ln2b + i * D_, p_x);
    }

    ln_k<false><<<BT_, 128>>>(p_x, nullptr, normg, normb, p_tmp);

    mmak<1, 128, float><<<tgrid(BT_, PRED_, 128, 1), 256, SMEMB(128)>>>(
        p_tmp, p_projt, proj_b, nullptr, p_proj, BT_, PRED_, D_, D_, D_, PRED_, 1, 0, 0, 0, 0, 0, 0);

    out_k<<<(B_ * PRED_ * N_ + 255) / 256, 256>>>(p_proj, p_mean, p_std, gamma, beta, out);
}

// round 16
// speedup vs baseline: 6.1911x; 1.0527x over previous
#include <cuda_runtime.h>
#include <cuda_fp16.h>
#include <cstdint>
#include <math.h>

// ---------------- problem constants ----------------
#define B_ 16
#define L_ 96
#define N_ 512
#define D_ 512
#define H_ 8
#define E_ 64
#define DFF_ 2048
#define T_ 516
#define PRED_ 96
#define NMARK_ 4
#define LAYERS_ 2
#define BT_ (B_ * T_)     // 8256
#define SCALE_ 0.125f

// ---------------- scratch ----------------
__device__ float g_mean[B_ * N_];
__device__ float g_std[B_ * N_];
__device__ float g_guide[B_ * N_ * N_];
__device__ float g_bqkv[LAYERS_ * 3 * D_];
__device__ float g_proj[BT_ * PRED_];
__device__ __half g_tok[B_ * T_ * L_];
__device__ __half g_nt[B_ * N_ * L_];
__device__ __half g_x[BT_ * D_];
__device__ __half g_tmp[BT_ * D_];
__device__ __half g_ctx[BT_ * D_];
__device__ __half g_qkv[(long long)BT_ * 3 * D_];
__device__ __half g_ffn[(long long)BT_ * DFF_];
__device__ __half g_wqkvt[(long long)LAYERS_ * 3 * D_ * D_];
__device__ __half g_wot[LAYERS_ * D_ * D_];
__device__ __half g_w1t[(long long)LAYERS_ * D_ * DFF_];
__device__ __half g_w2t[(long long)LAYERS_ * DFF_ * D_];
__device__ __half g_embt[D_ * L_];
__device__ __half g_projt[PRED_ * D_];

// ---------------- helpers ----------------
__device__ __forceinline__ void mma16(float* c, const uint32_t* a, uint32_t b0, uint32_t b1) {
    asm volatile(
        "mma.sync.aligned.m16n8k16.row.col.f32.f16.f16.f32 "
        "{%0,%1,%2,%3}, {%4,%5,%6,%7}, {%8,%9}, {%0,%1,%2,%3};"
        : "+f"(c[0]), "+f"(c[1]), "+f"(c[2]), "+f"(c[3])
        : "r"(a[0]), "r"(a[1]), "r"(a[2]), "r"(a[3]), "r"(b0), "r"(b1));
}
__device__ __forceinline__ void ldsm4(uint32_t* r, uint32_t addr) {
    asm volatile("ldmatrix.sync.aligned.m8n8.x4.shared.b16 {%0,%1,%2,%3}, [%4];"
        : "=r"(r[0]), "=r"(r[1]), "=r"(r[2]), "=r"(r[3]) : "r"(addr));
}
__device__ __forceinline__ void ldsm4t(uint32_t* r, uint32_t addr) {
    asm volatile("ldmatrix.sync.aligned.m8n8.x4.trans.shared.b16 {%0,%1,%2,%3}, [%4];"
        : "=r"(r[0]), "=r"(r[1]), "=r"(r[2]), "=r"(r[3]) : "r"(addr));
}
__device__ __forceinline__ uint32_t h2pack(float a, float b) {
    __half2 h = __floats2half2_rn(a, b);
    return *reinterpret_cast<uint32_t*>(&h);
}
__device__ __forceinline__ float geluf(float x) {
    return 0.5f * x * (1.0f + erff(x * 0.70710678118654752f));
}
__device__ __forceinline__ uint32_t smem_u32(const void* p) {
    uint32_t a;
    asm("{ .reg .u64 t; cvta.to.shared.u64 t, %1; cvt.u32.u64 %0, t; }" : "=r"(a) : "l"(p));
    return a;
}
__device__ __forceinline__ void cp16_full(uint32_t dst, const void* src) {
    asm volatile("cp.async.cg.shared.global [%0], [%1], 16;" :: "r"(dst), "l"(src) : "memory");
}
__device__ __forceinline__ void cp16_pred(uint32_t dst, const void* src, int nbytes) {
    asm volatile("cp.async.cg.shared.global [%0], [%1], 16, %2;" :: "r"(dst), "l"(src), "r"(nbytes) : "memory");
}
#define CP_COMMIT() asm volatile("cp.async.commit_group;" ::: "memory")
template <int Nw>
__device__ __forceinline__ void cp_wait() {
    asm volatile("cp.async.wait_group %0;" :: "n"(Nw) : "memory");
}

// ---------------- fp16 tensor-core GEMM: C[M,N] = A[M,K] @ B[N,K]^T (+epi) ----------------
// EPI: 0 none, 1 +bias, 2 +bias+gelu, 3 +bias+residual, 4 sigmoid (no bias).
// BK=64 halfs per chunk, 2-stage cp.async pipeline. OT: float or __half output.
#define SSH 72   // smem row stride in halfs (144B): ldmatrix conflict-free (16B step mod 128)

template <int EPI, typename OT>
__global__ void __launch_bounds__(256, 2)
mmak(const __half* __restrict__ A, const __half* __restrict__ Bm,
     const float* __restrict__ bias, const __half* __restrict__ Res,
     OT* __restrict__ C,
     int M, int Nn, int K, int lda, int ldb, int ldc, int nbH,
     long long sAb, long long sAh, long long sBb, long long sBh,
     long long sCb, long long sCh) {
    constexpr int BNt = 128;
    constexpr int NI = 4;                  // n-fragments per warp (WN=32)
    constexpr int NP = 2;
    constexpr int AE = 128 * SSH;          // halfs per A stage
    constexpr int STG = 2 * AE;            // A + B stage

    extern __shared__ char smem_raw[];
    const uint32_t sbase = smem_u32(smem_raw);

    int tid = threadIdx.x;
    int z = blockIdx.z, zb = z / nbH, zh = z % nbH;
    A  += zb * sAb + zh * sAh;
    Bm += zb * sBb + zh * sBh;
    C  += zb * sCb + zh * sCh;
    int m0 = blockIdx.y * 128, n0 = blockIdx.x * BNt;

    int lane = tid & 31, wid = tid >> 5;
    int wm = (wid & 1) * 64;
    int wn = (wid >> 1) * 32;
    int grp = lane >> 2, tig = lane & 3;
    int ls = lane >> 3, r8 = lane & 7;

    uint32_t offA[4];
#pragma unroll
    for (int mi = 0; mi < 4; mi++) {
        int row = wm + mi * 16 + (ls & 1) * 8 + r8;
        int col = (ls >> 1) * 8;
        offA[mi] = (uint32_t)(row * SSH + col) * 2u;
    }
    uint32_t offB[NP];
#pragma unroll
    for (int pi = 0; pi < NP; pi++) {
        int row = wn + (2 * pi + (ls >> 1)) * 8 + r8;
        int col = (ls & 1) * 8;
        offB[pi] = (uint32_t)(row * SSH + col) * 2u;
    }

    float acc[4][NI][4];
#pragma unroll
    for (int mi = 0; mi < 4; mi++)
#pragma unroll
        for (int ni = 0; ni < NI; ni++)
#pragma unroll
            for (int r = 0; r < 4; r++) acc[mi][ni][r] = 0.f;

    const int NC = (K + 63) >> 6;          // chunks of 64 halfs
    const bool full = (m0 + 128 <= M) && (n0 + BNt <= Nn) && ((K & 63) == 0);
    const int l_row = tid >> 3, l_c8 = (tid & 7) << 3;   // 8 segs/row, 16B each

    auto issue = [&](int c, int st) {
        int k0 = c * 64;
        uint32_t abase = sbase + (uint32_t)(st * STG) * 2u;
        uint32_t bbase = abase + (uint32_t)AE * 2u;
        if (full) {
#pragma unroll
            for (int u = 0; u < 4; u++) {
                int row = l_row + u * 32;
                cp16_full(abase + (uint32_t)(row * SSH + l_c8) * 2u,
                          A + (long long)(m0 + row) * lda + k0 + l_c8);
                cp16_full(bbase + (uint32_t)(row * SSH + l_c8) * 2u,
                          Bm + (long long)(n0 + row) * ldb + k0 + l_c8);
            }
        } else {
            int gk = k0 + l_c8;
            int rem = K - gk;
            int nbk = rem >= 8 ? 16 : (rem > 0 ? rem * 2 : 0);
#pragma unroll
            for (int u = 0; u < 4; u++) {
                int row = l_row + u * 32;
                int gm = m0 + row;
                int nb = (gm < M) ? nbk : 0;
                const __half* srcA = (nb > 0) ? (A + (long long)gm * lda + gk) : A;
                cp16_pred(abase + (uint32_t)(row * SSH + l_c8) * 2u, srcA, nb);
                int gn = n0 + row;
                int nb2 = (gn < Nn) ? nbk : 0;
                const __half* srcB = (nb2 > 0) ? (Bm + (long long)gn * ldb + gk) : Bm;
                cp16_pred(bbase + (uint32_t)(row * SSH + l_c8) * 2u, srcB, nb2);
            }
        }
    };

    issue(0, 0);
    CP_COMMIT();

    for (int c = 0; c < NC; c++) {
        cp_wait<0>();
        __syncthreads();
        if (c + 1 < NC) { issue(c + 1, (c + 1) & 1); CP_COMMIT(); }

        uint32_t aB = sbase + (uint32_t)((c & 1) * STG) * 2u;
        uint32_t bB = aB + (uint32_t)AE * 2u;
#pragma unroll
        for (int kk = 0; kk < 4; kk++) {           // four k16 steps per 64-half chunk
            uint32_t kof = (uint32_t)kk * 32u;     // 16 halfs = 32 bytes
            uint32_t af[4][4];
#pragma unroll
            for (int mi = 0; mi < 4; mi++) ldsm4(af[mi], aB + offA[mi] + kof);
#pragma unroll
            for (int pi = 0; pi < NP; pi++) {
                uint32_t bb[4];
                ldsm4(bb, bB + offB[pi] + kof);
#pragma unroll
                for (int mi = 0; mi < 4; mi++) {
                    mma16(acc[mi][2 * pi],     af[mi], bb[0], bb[1]);
                    mma16(acc[mi][2 * pi + 1], af[mi], bb[2], bb[3]);
                }
            }
        }
    }

#pragma unroll
    for (int mi = 0; mi < 4; mi++) {
#pragma unroll
        for (int ni = 0; ni < NI; ni++) {
            int col = n0 + wn + ni * 8 + 2 * tig;
            if (col >= Nn) continue;
            float bv0 = 0.f, bv1 = 0.f;
            if (EPI >= 1 && EPI <= 3) { bv0 = bias[col]; bv1 = bias[col + 1]; }
#pragma unroll
            for (int h = 0; h < 2; h++) {
                int gm = m0 + wm + mi * 16 + grp + h * 8;
                if (gm >= M) continue;
                float v0 = acc[mi][ni][h * 2 + 0] + bv0;
                float v1 = acc[mi][ni][h * 2 + 1] + bv1;
                if (EPI == 2) { v0 = geluf(v0); v1 = geluf(v1); }
                if (EPI == 3) {
                    const __half* rp = Res + (long long)gm * ldc + col;
                    v0 += __half2float(rp[0]); v1 += __half2float(rp[1]);
                }
                if (EPI == 4) {
                    v0 = 1.f / (1.f + __expf(-v0));
                    v1 = 1.f / (1.f + __expf(-v1));
                }
                if (sizeof(OT) == 2) {
                    *(uint32_t*)((__half*)C + (long long)gm * ldc + col) = h2pack(v0, v1);
                } else {
                    *(float2*)((float*)C + (long long)gm * ldc + col) = make_float2(v0, v1);
                }
            }
        }
    }
}

// ---------------- fused gated flash attention (fp16 operands) ----------------
#define QSH 136   // P/Q row stride halfs (272B)
#define KSH 72    // K/V row stride halfs (144B)
#define FSMEM ((128 * QSH + 2 * 128 * KSH) * 2)

__global__ void __launch_bounds__(256)
flash_k(const __half* __restrict__ qkv, const float* __restrict__ gate,
        __half* __restrict__ ctx) {
    extern __shared__ char sm[];
    __half* Sp = (__half*)sm;
    __half* Sk = Sp + 128 * QSH;
    __half* Sv = Sk + 128 * KSH;

    int qt = blockIdx.x;
    int bh = blockIdx.y;
    int b = bh >> 3, h = bh & 7;
    int i0 = qt * 128;
    int tid = threadIdx.x, lane = tid & 31, w = tid >> 5;
    int grp = lane >> 2, tig = lane & 3;
    int ls = lane >> 3, r8 = lane & 7;

    const __half* qb = qkv + (long long)b * T_ * (3 * D_) + h * E_;
    const __half* kb = qb + D_;
    const __half* vb = qb + 2 * D_;

    const uint32_t spB = smem_u32(Sp);
    const uint32_t skB = smem_u32(Sk);
    const uint32_t svB = smem_u32(Sv);

    uint32_t offPA;
    {
        int row = w * 16 + (ls & 1) * 8 + r8;
        int col = (ls >> 1) * 8;
        offPA = (uint32_t)(row * QSH + col) * 2u;
    }
    uint32_t offKB[8];
#pragma unroll
    for (int pf = 0; pf < 8; pf++) {
        int row = (2 * pf + (ls >> 1)) * 8 + r8;
        int col = (ls & 1) * 8;
        offKB[pf] = (uint32_t)(row * KSH + col) * 2u;
    }
    uint32_t offVB[4];
#pragma unroll
    for (int pe = 0; pe < 4; pe++) {
        int row = (ls & 1) * 8 + r8;
        int col = pe * 16 + (ls >> 1) * 8;
        offVB[pe] = (uint32_t)(row * KSH + col) * 2u;
    }

    for (int e = tid; e < 128 * 8; e += 256) {
        int r = e >> 3, c8 = (e & 7) << 3;
        int gi = i0 + r; if (gi >= T_) gi = T_ - 1;
        *(uint4*)(Sp + r * QSH + c8) = *(const uint4*)(qb + (long long)gi * (3 * D_) + c8);
    }
    __syncthreads();
    uint32_t qf[4][4];
#pragma unroll
    for (int ks = 0; ks < 4; ks++) ldsm4(qf[ks], spB + offPA + (uint32_t)ks * 32u);

    float of[8][4];
#pragma unroll
    for (int nf = 0; nf < 8; nf++)
#pragma unroll
        for (int r = 0; r < 4; r++) of[nf][r] = 0.f;
    float m0 = -1e30f, m1 = -1e30f;
    float s1a = 0.f, s1b = 0.f, s2a = 0.f, s2b = 0.f;

    const float* gb = gate + (long long)b * N_ * N_;
    const int row0 = i0 + w * 16 + grp, row1 = row0 + 8;

    for (int j0 = 0; j0 < T_; j0 += 128) {
        __syncthreads();
        for (int e = tid; e < 128 * 8; e += 256) {
            int r = e >> 3, c8 = (e & 7) << 3;
            int gj = j0 + r; if (gj >= T_) gj = T_ - 1;
            *(uint4*)(Sk + r * KSH + c8) = *(const uint4*)(kb + (long long)gj * (3 * D_) + c8);
            *(uint4*)(Sv + r * KSH + c8) = *(const uint4*)(vb + (long long)gj * (3 * D_) + c8);
        }
        __syncthreads();

        float sf[16][4];
#pragma unroll
        for (int nf = 0; nf < 16; nf++)
#pragma unroll
            for (int r = 0; r < 4; r++) sf[nf][r] = 0.f;
#pragma unroll
        for (int ks = 0; ks < 4; ks++) {
#pragma unroll
            for (int pf = 0; pf < 8; pf++) {
                uint32_t bb[4];
                ldsm4(bb, skB + offKB[pf] + (uint32_t)ks * 32u);
                mma16(sf[2 * pf],     qf[ks], bb[0], bb[1]);
                mma16(sf[2 * pf + 1], qf[ks], bb[2], bb[3]);
            }
        }

        float cm0 = -1e30f, cm1 = -1e30f;
#pragma unroll
        for (int nf = 0; nf < 16; nf++) {
            int j = j0 + nf * 8 + 2 * tig;
            float x0 = sf[nf][0] * SCALE_, x1 = sf[nf][1] * SCALE_;
            float x2 = sf[nf][2] * SCALE_, x3 = sf[nf][3] * SCALE_;
            if (j >= T_)     { x0 = -1e30f; x2 = -1e30f; }
            if (j + 1 >= T_) { x1 = -1e30f; x3 = -1e30f; }
            sf[nf][0] = x0; sf[nf][1] = x1; sf[nf][2] = x2; sf[nf][3] = x3;
            cm0 = fmaxf(cm0, fmaxf(x0, x1));
            cm1 = fmaxf(cm1, fmaxf(x2, x3));
        }
#pragma unroll
        for (int o = 1; o <= 2; o <<= 1) {
            cm0 = fmaxf(cm0, __shfl_xor_sync(0xffffffffu, cm0, o));
            cm1 = fmaxf(cm1, __shfl_xor_sync(0xffffffffu, cm1, o));
        }
        float nm0 = fmaxf(m0, cm0), nm1 = fmaxf(m1, cm1);
        float f0 = __expf(m0 - nm0), f1 = __expf(m1 - nm1);
        m0 = nm0; m1 = nm1;
        s1a *= f0; s2a *= f0; s1b *= f1; s2b *= f1;
#pragma unroll
        for (int nf = 0; nf < 8; nf++) {
            of[nf][0] *= f0; of[nf][1] *= f0;
            of[nf][2] *= f1; of[nf][3] *= f1;
        }

        float ls1a = 0.f, ls1b = 0.f, ls2a = 0.f, ls2b = 0.f;
        int r = w * 16 + grp;
#pragma unroll
        for (int nf = 0; nf < 16; nf++) {
            int j = j0 + nf * 8 + 2 * tig;
            float p0 = __expf(sf[nf][0] - m0), p1 = __expf(sf[nf][1] - m0);
            float p2 = __expf(sf[nf][2] - m1), p3 = __expf(sf[nf][3] - m1);
            float g0 = 0.5f, g1 = 0.5f, g2 = 0.5f, g3 = 0.5f;
            if (j < N_) {
                if (row0 < N_) { float2 gg = *(const float2*)(gb + (long long)row0 * N_ + j); g0 = gg.x; g1 = gg.y; }
                if (row1 < N_) { float2 gg = *(const float2*)(gb + (long long)row1 * N_ + j); g2 = gg.x; g3 = gg.y; }
            }
            ls1a += p0 + p1; ls1b += p2 + p3;
            float q0 = p0 * g0, q1 = p1 * g1, q2 = p2 * g2, q3 = p3 * g3;
            ls2a += q0 + q1; ls2b += q2 + q3;
            *(uint32_t*)(Sp + r * QSH + nf * 8 + 2 * tig) = h2pack(q0, q1);
            *(uint32_t*)(Sp + (r + 8) * QSH + nf * 8 + 2 * tig) = h2pack(q2, q3);
        }
#pragma unroll
        for (int o = 1; o <= 2; o <<= 1) {
            ls1a += __shfl_xor_sync(0xffffffffu, ls1a, o);
            ls1b += __shfl_xor_sync(0xffffffffu, ls1b, o);
            ls2a += __shfl_xor_sync(0xffffffffu, ls2a, o);
            ls2b += __shfl_xor_sync(0xffffffffu, ls2b, o);
        }
        s1a += ls1a; s1b += ls1b; s2a += ls2a; s2b += ls2b;

        __syncwarp();
#pragma unroll
        for (int ks = 0; ks < 8; ks++) {
            uint32_t a[4];
            ldsm4(a, spB + offPA + (uint32_t)ks * 32u);
            uint32_t vof = (uint32_t)(ks * 16 * KSH) * 2u;
#pragma unroll
            for (int pe = 0; pe < 4; pe++) {
                uint32_t bb[4];
                ldsm4t(bb, svB + offVB[pe] + vof);
                mma16(of[2 * pe],     a, bb[0], bb[1]);
                mma16(of[2 * pe + 1], a, bb[2], bb[3]);
            }
        }
    }

    float d0 = 1.f / (s2a + 1e-6f * s1a);
    float d1 = 1.f / (s2b + 1e-6f * s1b);
    __half* cb = ctx + (long long)b * T_ * D_ + h * E_;
#pragma unroll
    for (int nf = 0; nf < 8; nf++) {
        int col = nf * 8 + 2 * tig;
        if (row0 < T_)
            *(uint32_t*)(cb + (long long)row0 * D_ + col) = h2pack(of[nf][0] * d0, of[nf][1] * d0);
        if (row1 < T_)
            *(uint32_t*)(cb + (long long)row1 * D_ + col) = h2pack(of[nf][2] * d1, of[nf][3] * d1);
    }
}

// ---------------- batched tiled transpose: float src -> half dst ----------------
__global__ void transpose_k(const float* __restrict__ S, __half* __restrict__ Dst,
                            int R, int C, int lds, int ldd, int nb2,
                            long long sSb, long long sSh, long long sDb, long long sDh) {
    __shared__ float t[32][33];
    int z = blockIdx.z, zb = z / nb2, zh = z % nb2;
    S += zb * sSb + zh * sSh;
    Dst += zb * sDb + zh * sDh;
    int r0 = blockIdx.y * 32, c0 = blockIdx.x * 32;
    int c = c0 + threadIdx.x;
#pragma unroll
    for (int i = 0; i < 32; i += 8) {
        int r = r0 + threadIdx.y + i;
        if (r < R && c < C) t[threadIdx.y + i][threadIdx.x] = S[(long long)r * lds + c];
    }
    __syncthreads();
    int cc2 = r0 + threadIdx.x;
#pragma unroll
    for (int i = 0; i < 32; i += 8) {
        int rr2 = c0 + threadIdx.y + i;
        if (rr2 < C && cc2 < R) Dst[(long long)rr2 * ldd + cc2] = __float2half(t[threadIdx.x][threadIdx.y + i]);
    }
}

// ---------------- reductions ----------------
__device__ __forceinline__ float block_sum(float v, float* sh) {
    int lane = threadIdx.x & 31, w = threadIdx.x >> 5;
#pragma unroll
    for (int o = 16; o; o >>= 1) v += __shfl_xor_sync(0xffffffffu, v, o);
    if (lane == 0) sh[w] = v;
    __syncthreads();
    if (threadIdx.x == 0) {
        float t = 0.f; int nw = blockDim.x >> 5;
        for (int i = 0; i < nw; i++) t += sh[i];
        sh[32] = t;
    }
    __syncthreads();
    float r = sh[32];
    __syncthreads();
    return r;
}

// ---------------- small fused kernels ----------------
__global__ void revin_k(const float* __restrict__ x, const float* __restrict__ gamma,
                        const float* __restrict__ beta, __half* __restrict__ tok,
                        float* __restrict__ meanO, float* __restrict__ stdO) {
    int idx = blockIdx.x * blockDim.x + threadIdx.x;
    if (idx >= B_ * N_) return;
    int b = idx / N_, n = idx % N_;
    const float* xp = x + (long long)b * L_ * N_ + n;
    float s = 0.f, s2 = 0.f;
#pragma unroll 4
    for (int l = 0; l < L_; l++) { float v = xp[(long long)l * N_]; s += v; s2 += v * v; }
    float mean = s / L_;
    float var = fmaxf(s2 / L_ - mean * mean, 0.f);
    float sd = sqrtf(var + 1e-5f);
    meanO[idx] = mean; stdO[idx] = sd;
    float g = gamma[n], be = beta[n], inv = 1.f / sd;
    __half* tp = tok + ((long long)b * T_ + n) * L_;
#pragma unroll 4
    for (int l = 0; l < L_; l++) tp[l] = __float2half((xp[(long long)l * N_] - mean) * inv * g + be);
}

__global__ void marks_k(const float* __restrict__ xm, __half* __restrict__ tok) {
    int idx = blockIdx.x * blockDim.x + threadIdx.x;
    if (idx >= B_ * NMARK_ * L_) return;
    int l = idx % L_, m = (idx / L_) % NMARK_, b = idx / (L_ * NMARK_);
    tok[((long long)b * T_ + N_ + m) * L_ + l] = __float2half(xm[((long long)b * L_ + l) * NMARK_ + m]);
}

__global__ void trend_k(const __half* __restrict__ tok,
                        const float* __restrict__ w1, const float* __restrict__ b1,
                        const float* __restrict__ w2, const float* __restrict__ b2,
                        __half* __restrict__ nt) {
    int idx = blockIdx.x * blockDim.x + threadIdx.x;
    if (idx >= B_ * N_) return;
    int b = idx / N_, n = idx % N_;
    const __half* xp = tok + ((long long)b * T_ + n) * L_;
    float cum[L_ + 1];
    cum[0] = 0.f;
    float s = 0.f, s2 = 0.f;
    for (int l = 0; l < L_; l++) {
        float v = __half2float(xp[l]);
        cum[l + 1] = cum[l] + v;
        s += v; s2 += v * v;
    }
    float mean = s / L_;
    float var = fmaxf(s2 / L_ - mean * mean, 0.f);
    float sd = sqrtf(var + 1e-6f);
    float logits[4] = {b2[0], b2[1], b2[2], b2[3]};
#pragma unroll
    for (int j = 0; j < 16; j++) {
        float h = fmaxf(mean * w1[j] + sd * w1[16 + j] + b1[j], 0.f);
#pragma unroll
        for (int w = 0; w < 4; w++) logits[w] += h * w2[j * 4 + w];
    }
    float mx = fmaxf(fmaxf(logits[0], logits[1]), fmaxf(logits[2], logits[3]));
    float wt[4], ws = 0.f;
#pragma unroll
    for (int w = 0; w < 4; w++) { wt[w] = expf(logits[w] - mx); ws += wt[w]; }
#pragma unroll
    for (int w = 0; w < 4; w++) wt[w] /= ws;
    const int W[4] = {4, 8, 12, 24};
    float x0 = __half2float(xp[0]);
    float t[L_];
    float nrm2 = 0.f;
    for (int l = 0; l < L_; l++) {
        float tv = 0.f;
#pragma unroll
        for (int wi = 0; wi < 4; wi++) {
            int w = W[wi], lo = l - w + 1;
            float sum = (lo < 0) ? (cum[l + 1] + (float)(-lo) * x0) : (cum[l + 1] - cum[lo]);
            tv += wt[wi] * sum / (float)w;
        }
        t[l] = tv; nrm2 += tv * tv;
    }
    float inv = 1.f / fmaxf(sqrtf(nrm2), 1e-12f);
    __half* np = nt + ((long long)b * N_ + n) * L_;
    for (int l = 0; l < L_; l++) np[l] = __float2half(t[l] * inv);
}

__global__ void biascat_k(const float* __restrict__ bq, const float* __restrict__ bk,
                          const float* __restrict__ bv, float* __restrict__ o) {
    int i = blockIdx.x * blockDim.x + threadIdx.x;
    if (i >= LAYERS_ * 3 * D_) return;
    int l = i / (3 * D_), j = i % (3 * D_);
    float v = (j < D_) ? bq[l * D_ + j] : (j < 2 * D_) ? bk[l * D_ + j - D_] : bv[l * D_ + j - 2 * D_];
    o[i] = v;
}

template <bool RES>
__global__ void ln_k(const __half* __restrict__ X, const __half* __restrict__ Y,
                     const float* __restrict__ g, const float* __restrict__ be,
                     __half* __restrict__ out) {
    __shared__ float sh[33];
    long long r = blockIdx.x;
    const __half* x = X + r * D_;
    const __half* y = RES ? (Y + r * D_) : nullptr;
    float v[4];
    float s = 0.f;
#pragma unroll
    for (int i = 0; i < 4; i++) {
        int c = threadIdx.x + i * 128;
        v[i] = __half2float(x[c]) + (RES ? __half2float(y[c]) : 0.f);
        s += v[i];
    }
    s = block_sum(s, sh);
    float mean = s / D_;
    float s2 = 0.f;
#pragma unroll
    for (int i = 0; i < 4; i++) { float d = v[i] - mean; s2 += d * d; }
    s2 = block_sum(s2, sh);
    float rstd = rsqrtf(s2 / D_ + 1e-5f);
    __half* o = out + r * D_;
#pragma unroll
    for (int i = 0; i < 4; i++) {
        int c = threadIdx.x + i * 128;
        o[c] = __float2half((v[i] - mean) * rstd * g[c] + be[c]);
    }
}

__global__ void out_k(const float* __restrict__ proj, const float* __restrict__ meanI,
                      const float* __restrict__ stdI, const float* __restrict__ gamma,
                      const float* __restrict__ beta, float* __restrict__ out) {
    int idx = blockIdx.x * blockDim.x + threadIdx.x;
    if (idx >= B_ * PRED_ * N_) return;
    int n = idx % N_, p = (idx / N_) % PRED_, b = idx / (N_ * PRED_);
    float v = proj[((long long)b * T_ + n) * PRED_ + p];
    v = (v - beta[n]) / (gamma[n] + 1e-5f) * stdI[b * N_ + n] + meanI[b * N_ + n];
    out[idx] = v;
}

// ---------------- host orchestration ----------------
static inline dim3 tgrid(int M, int Nn, int batch) {
    return dim3((Nn + 127) / 128, (M + 127) / 128, batch);
}
#define SMEMB (2 * 2 * 128 * SSH * 2)   // 2 stages * (A+B) * 128 rows * SSH halfs * 2B = 73728

extern "C" void kernel_launch(void* const* d_in, const int* in_sizes, int n_in,
                              void* d_out, int out_size) {
    const float* x_enc  = (const float*)d_in[0];
    const float* x_mark = (const float*)d_in[1];
    const float* gamma  = (const float*)d_in[4];
    const float* beta   = (const float*)d_in[5];
    const float* tp_w1  = (const float*)d_in[6];
    const float* tp_b1  = (const float*)d_in[7];
    const float* tp_w2  = (const float*)d_in[8];
    const float* tp_b2  = (const float*)d_in[9];
    const float* emb_w  = (const float*)d_in[10];
    const float* emb_b  = (const float*)d_in[11];
    const float* wq = (const float*)d_in[12];
    const float* bq = (const float*)d_in[13];
    const float* wk = (const float*)d_in[14];
    const float* bk = (const float*)d_in[15];
    const float* wv = (const float*)d_in[16];
    const float* bv = (const float*)d_in[17];
    const float* wo = (const float*)d_in[18];
    const float* bo = (const float*)d_in[19];
    const float* w1 = (const float*)d_in[20];
    const float* b1 = (const float*)d_in[21];
    const float* w2 = (const float*)d_in[22];
    const float* b2 = (const float*)d_in[23];
    const float* ln1g = (const float*)d_in[24];
    const float* ln1b = (const float*)d_in[25];
    const float* ln2g = (const float*)d_in[26];
    const float* ln2b = (const float*)d_in[27];
    const float* normg = (const float*)d_in[28];
    const float* normb = (const float*)d_in[29];
    const float* proj_w = (const float*)d_in[30];
    const float* proj_b = (const float*)d_in[31];
    float* out = (float*)d_out;

    float *p_mean, *p_std, *p_guide, *p_bqkv, *p_proj;
    __half *p_tok, *p_nt, *p_x, *p_tmp, *p_ctx, *p_qkv, *p_ffn,
           *p_wqkvt, *p_wot, *p_w1t, *p_w2t, *p_embt, *p_projt;
    cudaGetSymbolAddress((void**)&p_mean, g_mean);
    cudaGetSymbolAddress((void**)&p_std, g_std);
    cudaGetSymbolAddress((void**)&p_guide, g_guide);
    cudaGetSymbolAddress((void**)&p_bqkv, g_bqkv);
    cudaGetSymbolAddress((void**)&p_proj, g_proj);
    cudaGetSymbolAddress((void**)&p_tok, g_tok);
    cudaGetSymbolAddress((void**)&p_nt, g_nt);
    cudaGetSymbolAddress((void**)&p_x, g_x);
    cudaGetSymbolAddress((void**)&p_tmp, g_tmp);
    cudaGetSymbolAddress((void**)&p_ctx, g_ctx);
    cudaGetSymbolAddress((void**)&p_qkv, g_qkv);
    cudaGetSymbolAddress((void**)&p_ffn, g_ffn);
    cudaGetSymbolAddress((void**)&p_wqkvt, g_wqkvt);
    cudaGetSymbolAddress((void**)&p_wot, g_wot);
    cudaGetSymbolAddress((void**)&p_w1t, g_w1t);
    cudaGetSymbolAddress((void**)&p_w2t, g_w2t);
    cudaGetSymbolAddress((void**)&p_embt, g_embt);
    cudaGetSymbolAddress((void**)&p_projt, g_projt);

    cudaFuncSetAttribute(mmak<4, float>,  cudaFuncAttributeMaxDynamicSharedMemorySize, SMEMB);
    cudaFuncSetAttribute(mmak<1, __half>, cudaFuncAttributeMaxDynamicSharedMemorySize, SMEMB);
    cudaFuncSetAttribute(mmak<1, float>,  cudaFuncAttributeMaxDynamicSharedMemorySize, SMEMB);
    cudaFuncSetAttribute(mmak<2, __half>, cudaFuncAttributeMaxDynamicSharedMemorySize, SMEMB);
    cudaFuncSetAttribute(mmak<3, __half>, cudaFuncAttributeMaxDynamicSharedMemorySize, SMEMB);
    cudaFuncSetAttribute(flash_k, cudaFuncAttributeMaxDynamicSharedMemorySize, FSMEM);

    dim3 tb(32, 8);

    revin_k<<<(B_ * N_ + 255) / 256, 256>>>(x_enc, gamma, beta, p_tok, p_mean, p_std);
    marks_k<<<(B_ * NMARK_ * L_ + 255) / 256, 256>>>(x_mark, p_tok);
    trend_k<<<(B_ * N_ + 255) / 256, 256>>>(p_tok, tp_w1, tp_b1, tp_w2, tp_b2, p_nt);
    transpose_k<<<dim3(16, 3, 1), tb>>>(emb_w, p_embt, L_, D_, D_, L_, 1, 0, 0, 0, 0);

    // Gram with fused sigmoid -> gate
    mmak<4, float><<<tgrid(N_, N_, B_), 256, SMEMB>>>(
        p_nt, p_nt, nullptr, nullptr, p_guide, N_, N_, L_, L_, L_, N_, 1,
        (long long)N_ * L_, 0, (long long)N_ * L_, 0, (long long)N_ * N_, 0);
    // embedding: x = tok @ emb_w + emb_b (half out)
    mmak<1, __half><<<tgrid(BT_, D_, 1), 256, SMEMB>>>(
        p_tok, p_embt, emb_b, nullptr, p_x, BT_, D_, L_, L_, L_, D_, 1, 0, 0, 0, 0, 0, 0);

    transpose_k<<<dim3(16, 16, 2), tb>>>(wq, p_wqkvt, 512, 512, 512, 512, 1,
                                         512 * 512, 0, (long long)3 * 512 * 512, 0);
    transpose_k<<<dim3(16, 16, 2), tb>>>(wk, p_wqkvt + 512 * 512, 512, 512, 512, 512, 1,
                                         512 * 512, 0, (long long)3 * 512 * 512, 0);
    transpose_k<<<dim3(16, 16, 2), tb>>>(wv, p_wqkvt + 2 * 512 * 512, 512, 512, 512, 512, 1,
                                         512 * 512, 0, (long long)3 * 512 * 512, 0);
    biascat_k<<<(LAYERS_ * 3 * D_ + 255) / 256, 256>>>(bq, bk, bv, p_bqkv);
    transpose_k<<<dim3(16, 16, 2), tb>>>(wo, p_wot, 512, 512, 512, 512, 1, 512 * 512, 0, 512 * 512, 0);
    transpose_k<<<dim3(64, 16, 2), tb>>>(w1, p_w1t, 512, 2048, 2048, 512, 1,
                                         (long long)512 * 2048, 0, (long long)512 * 2048, 0);
    transpose_k<<<dim3(16, 64, 2), tb>>>(w2, p_w2t, 2048, 512, 512, 2048, 1,
                                         (long long)512 * 2048, 0, (long long)512 * 2048, 0);
    transpose_k<<<dim3(3, 16, 1), tb>>>(proj_w, p_projt, D_, PRED_, PRED_, D_, 1, 0, 0, 0, 0);

    for (int i = 0; i < LAYERS_; i++) {
        const __half* wqkvt_i = p_wqkvt + (long long)i * 3 * D_ * D_;
        const __half* wot_i = p_wot + (long long)i * D_ * D_;
        const __half* w1t_i = p_w1t + (long long)i * D_ * DFF_;
        const __half* w2t_i = p_w2t + (long long)i * DFF_ * D_;

        mmak<1, __half><<<tgrid(BT_, 3 * D_, 1), 256, SMEMB>>>(
            p_x, wqkvt_i, p_bqkv + i * 3 * D_, nullptr, p_qkv,
            BT_, 3 * D_, D_, D_, D_, 3 * D_, 1, 0, 0, 0, 0, 0, 0);

        flash_k<<<dim3(5, B_ * H_), 256, FSMEM>>>(p_qkv, p_guide, p_ctx);

        mmak<3, __half><<<tgrid(BT_, D_, 1), 256, SMEMB>>>(
            p_ctx, wot_i, bo + i * D_, p_x, p_tmp, BT_, D_, D_, D_, D_, D_, 1, 0, 0, 0, 0, 0, 0);

        ln_k<false><<<BT_, 128>>>(p_tmp, nullptr, ln1g + i * D_, ln1b + i * D_, p_tmp);

        mmak<2, __half><<<tgrid(BT_, DFF_, 1), 256, SMEMB>>>(
            p_tmp, w1t_i, b1 + i * DFF_, nullptr, p_ffn, BT_, DFF_, D_, D_, D_, DFF_, 1, 0, 0, 0, 0, 0, 0);
        mmak<1, __half><<<tgrid(BT_, D_, 1), 256, SMEMB>>>(
            p_ffn, w2t_i, b2 + i * D_, nullptr, p_ctx, BT_, D_, DFF_, DFF_, DFF_, D_, 1, 0, 0, 0, 0, 0, 0);

        ln_k<true><<<BT_, 128>>>(p_tmp, p_ctx, ln2g + i * D_, ln2b + i * D_, p_x);
    }

    ln_k<false><<<BT_, 128>>>(p_x, nullptr, normg, normb, p_tmp);

    mmak<1, float><<<tgrid(BT_, PRED_, 1), 256, SMEMB>>>(
        p_tmp, p_projt, proj_b, nullptr, p_proj, BT_, PRED_, D_, D_, D_, PRED_, 1, 0, 0, 0, 0, 0, 0);

    out_k<<<(B_ * PRED_ * N_ + 255) / 256, 256>>>(p_proj, p_mean, p_std, gamma, beta, out);
}